// round 6
// baseline (speedup 1.0000x reference)
#include <cuda_runtime.h>
#include <math.h>
#include <stdint.h>

// Problem constants
#define BB 4
#define SEQ 2048
#define DIM 2048
#define NH 16
#define HD 128
#define NTOK (BB * SEQ)        // 8192
#define QKVC (3 * DIM)         // 6144

// Scratch (device globals: allocation-free)
__device__ float g_qkv[(size_t)NTOK * QKVC];   // 192 MB
__device__ float g_ctx[(size_t)NTOK * DIM];    // 64 MB
__device__ float g_xr[(size_t)NTOK * DIM];     // tf32-rounded x
__device__ float g_w1[(size_t)DIM * QKVC];     // tf32-rounded Wqkv (row-major)
__device__ float g_w2[(size_t)DIM * DIM];      // tf32-rounded Wout (row-major)
__device__ float g_cos[SEQ * (HD / 2)];
__device__ float g_sin[SEQ * (HD / 2)];

// ---------------------------------------------------------------------------
// PTX helpers
// ---------------------------------------------------------------------------
__device__ __forceinline__ void cp_async16(float* smem, const float* gmem) {
    uint32_t s = (uint32_t)__cvta_generic_to_shared(smem);
    asm volatile("cp.async.cg.shared.global [%0], [%1], 16;\n" :: "r"(s), "l"(gmem));
}
__device__ __forceinline__ void cp_commit() {
    asm volatile("cp.async.commit_group;\n");
}
__device__ __forceinline__ void cp_wait0() {
    asm volatile("cp.async.wait_group 0;\n");
}
__device__ __forceinline__ void cp_wait1() {
    asm volatile("cp.async.wait_group 1;\n");
}
__device__ __forceinline__ uint32_t f2tf32(float f) {
    uint32_t u;
    asm("cvt.rna.tf32.f32 %0, %1;\n" : "=r"(u) : "f"(f));
    return u;
}
__device__ __forceinline__ float tf32r(float f) {
    return __uint_as_float(f2tf32(f));
}
__device__ __forceinline__ uint32_t fu(float f) { return __float_as_uint(f); }

__device__ __forceinline__ void mma_tf32(float* c, const uint32_t* a, const uint32_t* b) {
    asm volatile(
        "mma.sync.aligned.m16n8k8.row.col.f32.tf32.tf32.f32 "
        "{%0,%1,%2,%3}, {%4,%5,%6,%7}, {%8,%9}, {%0,%1,%2,%3};\n"
        : "+f"(c[0]), "+f"(c[1]), "+f"(c[2]), "+f"(c[3])
        : "r"(a[0]), "r"(a[1]), "r"(a[2]), "r"(a[3]), "r"(b[0]), "r"(b[1]));
}

// ---------------------------------------------------------------------------
// Prep kernels
// ---------------------------------------------------------------------------
__global__ void round_tf32(const float* __restrict__ src, float* __restrict__ dst,
                           int n4) {
    int i = blockIdx.x * blockDim.x + threadIdx.x;
    if (i >= n4) return;
    float4 v = ((const float4*)src)[i];
    v.x = tf32r(v.x); v.y = tf32r(v.y); v.z = tf32r(v.z); v.w = tf32r(v.w);
    ((float4*)dst)[i] = v;
}

__global__ void build_rope_tables() {
    int idx = blockIdx.x * blockDim.x + threadIdx.x;
    if (idx >= SEQ * (HD / 2)) return;
    int pos = idx / (HD / 2);
    int i = idx % (HD / 2);
    double inv = exp(-((double)(2 * i) / (double)HD) * log(10000.0));
    double ang = (double)pos * inv;
    g_cos[idx] = (float)cos(ang);
    g_sin[idx] = (float)sin(ang);
}

__global__ void rope_kernel() {
    int idx = blockIdx.x * blockDim.x + threadIdx.x;
    const int total = NTOK * 2 * NH * (HD / 2);
    if (idx >= total) return;
    int i  = idx & 63;
    int h  = (idx >> 6) & 15;
    int qk = (idx >> 10) & 1;
    int t  = idx >> 11;
    int pos = t & (SEQ - 1);
    float c = g_cos[pos * (HD / 2) + i];
    float s = g_sin[pos * (HD / 2) + i];
    float* p = g_qkv + (size_t)t * QKVC + qk * DIM + h * HD + 2 * i;
    float x0 = p[0], x1 = p[1];
    p[0] = tf32r(x0 * c - x1 * s);
    p[1] = tf32r(x1 * c + x0 * s);
}

// ---------------------------------------------------------------------------
// TF32 mma.sync GEMM: C[M,N] = A[M,K] @ B[K,N] + bias
// BM=128, BN=256, BK=32; 3-stage cp.async pipeline; 8 warps (2x4),
// warp tile 64x64 (mt=4, nt=8). Inputs pre-rounded tf32.
// ---------------------------------------------------------------------------
#define BM 128
#define BN 256
#define BK 32
#define ASTRIDE 36             // BK+4: a-frag bank = 4g+t (conflict-free)
#define BSTRIDE 264            // BN+8: b-frag bank = 8t+g (conflict-free)
#define A_STAGE (BM * ASTRIDE) // 4608 floats
#define B_STAGE (BK * BSTRIDE) // 8448 floats
#define STAGE_FLOATS (A_STAGE + B_STAGE)       // 13056
#define NSTAGE 3
#define GEMM_SMEM_BYTES (NSTAGE * STAGE_FLOATS * 4)  // 156672

__device__ __forceinline__ void load_a_stage(float* As, const float* A, int K,
                                             int brow, int ktile, int tid) {
    // 128 rows x 8 chunks(16B) = 1024 chunks; 4 per thread
#pragma unroll
    for (int v = 0; v < 4; v++) {
        int idx = v * 256 + tid;
        int row = idx >> 3;
        int ch = idx & 7;
        cp_async16(As + row * ASTRIDE + ch * 4,
                   A + (size_t)(brow + row) * K + ktile * BK + ch * 4);
    }
}
__device__ __forceinline__ void load_b_stage(float* Bs, const float* B, int N,
                                             int bcol, int ktile, int tid) {
    // 32 rows x 64 chunks = 2048 chunks; 8 per thread
#pragma unroll
    for (int v = 0; v < 8; v++) {
        int idx = v * 256 + tid;
        int row = idx >> 6;
        int ch = idx & 63;
        cp_async16(Bs + row * BSTRIDE + ch * 4,
                   B + (size_t)(ktile * BK + row) * N + bcol + ch * 4);
    }
}

__global__ __launch_bounds__(256, 1)
void gemm_tf32(const float* __restrict__ A, const float* __restrict__ B,
               const float* __restrict__ bias, float* __restrict__ C,
               int M, int N, int K, int rnd_out) {
    extern __shared__ float sm[];
    int tid = threadIdx.x;
    int brow = blockIdx.y * BM;
    int bcol = blockIdx.x * BN;
    int warp = tid >> 5, lane = tid & 31;
    int wm = warp >> 2;          // 0..1  (64 rows each)
    int wn = warp & 3;           // 0..3  (64 cols each)
    int g = lane >> 2, t = lane & 3;

    float c[4][8][4];
#pragma unroll
    for (int i = 0; i < 4; i++)
#pragma unroll
        for (int j = 0; j < 8; j++)
#pragma unroll
            for (int r = 0; r < 4; r++) c[i][j][r] = 0.f;

    const int NK = K / BK;

    // Prologue: stages 0..NSTAGE-2
#pragma unroll
    for (int s = 0; s < NSTAGE - 1; s++) {
        float* st = sm + s * STAGE_FLOATS;
        load_a_stage(st, A, K, brow, s, tid);
        load_b_stage(st + A_STAGE, B, N, bcol, s, tid);
        cp_commit();
    }

    for (int kt = 0; kt < NK; kt++) {
        cp_wait1();          // stage kt complete (one group may stay in flight)
        __syncthreads();     // everyone done reading buf (kt-1)%NSTAGE

        if (kt + NSTAGE - 1 < NK) {
            float* st = sm + ((kt + NSTAGE - 1) % NSTAGE) * STAGE_FLOATS;
            load_a_stage(st, A, K, brow, kt + NSTAGE - 1, tid);
            load_b_stage(st + A_STAGE, B, N, bcol, kt + NSTAGE - 1, tid);
        }
        cp_commit();         // commit every iteration to keep group count in step

        const float* As = sm + (kt % NSTAGE) * STAGE_FLOATS;
        const float* Bs = As + A_STAGE;

#pragma unroll
        for (int ks = 0; ks < 4; ks++) {
            int k0 = ks * 8;
            uint32_t a[4][4], b[8][2];
#pragma unroll
            for (int mt = 0; mt < 4; mt++) {
                const float* ap = As + (wm * 64 + mt * 16 + g) * ASTRIDE + k0 + t;
                a[mt][0] = fu(ap[0]);
                a[mt][1] = fu(ap[8 * ASTRIDE]);
                a[mt][2] = fu(ap[4]);
                a[mt][3] = fu(ap[8 * ASTRIDE + 4]);
            }
#pragma unroll
            for (int nt = 0; nt < 8; nt++) {
                const float* bp = Bs + (k0 + t) * BSTRIDE + wn * 64 + nt * 8 + g;
                b[nt][0] = fu(bp[0]);
                b[nt][1] = fu(bp[4 * BSTRIDE]);
            }
#pragma unroll
            for (int mt = 0; mt < 4; mt++)
#pragma unroll
                for (int nt = 0; nt < 8; nt++)
                    mma_tf32(c[mt][nt], a[mt], b[nt]);
        }
    }

    // Epilogue
#pragma unroll
    for (int mt = 0; mt < 4; mt++) {
        int r0 = brow + wm * 64 + mt * 16 + g;
#pragma unroll
        for (int nt = 0; nt < 8; nt++) {
            int col = bcol + wn * 64 + nt * 8 + 2 * t;
            float b0 = bias[col], b1 = bias[col + 1];
            float v00 = c[mt][nt][0] + b0, v01 = c[mt][nt][1] + b1;
            float v10 = c[mt][nt][2] + b0, v11 = c[mt][nt][3] + b1;
            if (rnd_out) {
                v00 = tf32r(v00); v01 = tf32r(v01);
                v10 = tf32r(v10); v11 = tf32r(v11);
            }
            *(float2*)(C + (size_t)r0 * N + col) = make_float2(v00, v01);
            *(float2*)(C + (size_t)(r0 + 8) * N + col) = make_float2(v10, v11);
        }
    }
}

// ---------------------------------------------------------------------------
// Tensor-core flash attention (unchanged from R4)
// ---------------------------------------------------------------------------
#define FQT 128
#define FKT 64
#define QPAD 132
#define KPAD 132
#define VPAD 132
#define SPAD 76
#define KSTG (FKT * KPAD)
#define FA_SMEM_FLOATS (FQT * QPAD + 2 * KSTG + FKT * VPAD + FQT * SPAD + 256)
#define FA_SMEM_BYTES (FA_SMEM_FLOATS * 4)

__device__ __forceinline__ void fa_load_tile_async(float* dst, const float* gsrc,
                                                   int tid) {
#pragma unroll
    for (int v = 0; v < 8; v++) {
        int idx = v * 256 + tid;
        int row = idx >> 5, ch = (idx & 31) << 2;
        cp_async16(dst + row * KPAD + ch, gsrc + (size_t)row * QKVC + ch);
    }
}

__global__ __launch_bounds__(256, 1)
void flash_attn_mma(const float* __restrict__ qkv, float* __restrict__ ctx) {
    int qtile = blockIdx.x, head = blockIdx.y, batch = blockIdx.z;
    int q0 = qtile * FQT;
    int tid = threadIdx.x, warp = tid >> 5, lane = tid & 31;
    int g = lane >> 2, t = lane & 3;

    extern __shared__ float sm[];
    float* Qs = sm;
    float* Ks0 = Qs + FQT * QPAD;
    float* Vs = Ks0 + 2 * KSTG;
    float* Ss = Vs + FKT * VPAD;
    float* cr = Ss + FQT * SPAD;
    float* ls = cr + 128;

    const float scale = 0.08838834764831845f;
    const float* qbase = qkv + (size_t)(batch * SEQ + q0) * QKVC + head * HD;
    const float* kvbase = qkv + (size_t)(batch * SEQ) * QKVC + DIM + head * HD;

    int ntiles = 2 * (qtile + 1);

    fa_load_tile_async(Ks0, kvbase, tid);
    cp_commit();
    fa_load_tile_async(Vs, kvbase + DIM, tid);
    cp_commit();

#pragma unroll
    for (int v = 0; v < 16; v++) {
        int idx = v * 256 + tid;
        int row = idx >> 5, ch = (idx & 31) << 2;
        *(float4*)(Qs + row * QPAD + ch) =
            *(const float4*)(qbase + (size_t)row * QKVC + ch);
    }

    float o[8][2][4];
#pragma unroll
    for (int mt = 0; mt < 8; mt++)
#pragma unroll
        for (int nt = 0; nt < 2; nt++)
#pragma unroll
            for (int r = 0; r < 4; r++) o[mt][nt][r] = 0.f;

    float m_a = -INFINITY, m_b = -INFINITY, l_a = 0.f, l_b = 0.f;
    int rowa = q0 + warp * 16 + g;
    int rowb = rowa + 8;

    int buf = 0;
    for (int kt = 0; kt < ntiles; kt++) {
        int k0g = kt * FKT;
        const float* kvtile = kvbase + (size_t)k0g * QKVC;

        cp_wait1();
        __syncthreads();
        if (kt + 1 < ntiles) {
            fa_load_tile_async(Ks0 + (buf ^ 1) * KSTG,
                               kvtile + (size_t)FKT * QKVC, tid);
            cp_commit();
        }
        const float* Ks = Ks0 + buf * KSTG;

        float sc[8][4];
#pragma unroll
        for (int nt = 0; nt < 8; nt++)
#pragma unroll
            for (int r = 0; r < 4; r++) sc[nt][r] = 0.f;

#pragma unroll
        for (int k8 = 0; k8 < HD; k8 += 8) {
            uint32_t a[4];
            const float* qp = Qs + (warp * 16 + g) * QPAD + k8 + t;
            a[0] = fu(qp[0]);
            a[1] = fu(qp[8 * QPAD]);
            a[2] = fu(qp[4]);
            a[3] = fu(qp[8 * QPAD + 4]);
#pragma unroll
            for (int nt = 0; nt < 8; nt++) {
                uint32_t b[2];
                const float* kp = Ks + (nt * 8 + g) * KPAD + k8 + t;
                b[0] = fu(kp[0]);
                b[1] = fu(kp[4]);
                mma_tf32(sc[nt], a, b);
            }
        }

#pragma unroll
        for (int nt = 0; nt < 8; nt++)
#pragma unroll
            for (int r = 0; r < 4; r++) sc[nt][r] *= scale;

        if (kt >= 2 * qtile) {
#pragma unroll
            for (int nt = 0; nt < 8; nt++) {
                int col = k0g + nt * 8 + 2 * t;
                if (col > rowa) sc[nt][0] = -INFINITY;
                if (col + 1 > rowa) sc[nt][1] = -INFINITY;
                if (col > rowb) sc[nt][2] = -INFINITY;
                if (col + 1 > rowb) sc[nt][3] = -INFINITY;
            }
        }

        float tma = -INFINITY, tmb = -INFINITY;
#pragma unroll
        for (int nt = 0; nt < 8; nt++) {
            tma = fmaxf(tma, fmaxf(sc[nt][0], sc[nt][1]));
            tmb = fmaxf(tmb, fmaxf(sc[nt][2], sc[nt][3]));
        }
        tma = fmaxf(tma, __shfl_xor_sync(0xffffffff, tma, 1));
        tma = fmaxf(tma, __shfl_xor_sync(0xffffffff, tma, 2));
        tmb = fmaxf(tmb, __shfl_xor_sync(0xffffffff, tmb, 1));
        tmb = fmaxf(tmb, __shfl_xor_sync(0xffffffff, tmb, 2));

        float nma = fmaxf(m_a, tma), nmb = fmaxf(m_b, tmb);
        float ca = __expf(m_a - nma), cb = __expf(m_b - nmb);
        m_a = nma; m_b = nmb;

        float sa = 0.f, sb = 0.f;
#pragma unroll
        for (int nt = 0; nt < 8; nt++) {
            float p0 = __expf(sc[nt][0] - nma);
            float p1 = __expf(sc[nt][1] - nma);
            float p2 = __expf(sc[nt][2] - nmb);
            float p3 = __expf(sc[nt][3] - nmb);
            sc[nt][0] = p0; sc[nt][1] = p1; sc[nt][2] = p2; sc[nt][3] = p3;
            sa += p0 + p1;
            sb += p2 + p3;
        }
        sa += __shfl_xor_sync(0xffffffff, sa, 1);
        sa += __shfl_xor_sync(0xffffffff, sa, 2);
        sb += __shfl_xor_sync(0xffffffff, sb, 1);
        sb += __shfl_xor_sync(0xffffffff, sb, 2);
        l_a = l_a * ca + sa;
        l_b = l_b * cb + sb;

        if (t == 0) {
            cr[warp * 16 + g] = ca;
            cr[warp * 16 + g + 8] = cb;
        }

#pragma unroll
        for (int nt = 0; nt < 8; nt++) {
            *(float2*)(Ss + (warp * 16 + g) * SPAD + nt * 8 + 2 * t) =
                make_float2(sc[nt][0], sc[nt][1]);
            *(float2*)(Ss + (warp * 16 + g + 8) * SPAD + nt * 8 + 2 * t) =
                make_float2(sc[nt][2], sc[nt][3]);
        }

        if (kt + 1 < ntiles) cp_wait1(); else cp_wait0();
        __syncthreads();

#pragma unroll
        for (int nt = 0; nt < 2; nt++) {
            float c0 = cr[warp * 16 + nt * 8 + 2 * t];
            float c1 = cr[warp * 16 + nt * 8 + 2 * t + 1];
#pragma unroll
            for (int mt = 0; mt < 8; mt++) {
                o[mt][nt][0] *= c0;
                o[mt][nt][1] *= c1;
                o[mt][nt][2] *= c0;
                o[mt][nt][3] *= c1;
            }
        }

#pragma unroll
        for (int k8 = 0; k8 < FKT; k8 += 8) {
            uint32_t b[2][2];
#pragma unroll
            for (int nt = 0; nt < 2; nt++) {
                const float* pp = Ss + (warp * 16 + nt * 8 + g) * SPAD + k8 + t;
                b[nt][0] = f2tf32(pp[0]);
                b[nt][1] = f2tf32(pp[4]);
            }
#pragma unroll
            for (int mt = 0; mt < 8; mt++) {
                uint32_t a[4];
                const float* vp = Vs + (k8 + t) * VPAD + mt * 16 + g;
                a[0] = fu(vp[0]);
                a[1] = fu(vp[8]);
                a[2] = fu(vp[4 * VPAD]);
                a[3] = fu(vp[4 * VPAD + 8]);
                mma_tf32(o[mt][0], a, b[0]);
                mma_tf32(o[mt][1], a, b[1]);
            }
        }

        __syncthreads();
        if (kt + 1 < ntiles) {
            fa_load_tile_async(Vs, kvtile + (size_t)FKT * QKVC + DIM, tid);
            cp_commit();
        }
        buf ^= 1;
    }

    if (t == 0) {
        ls[warp * 16 + g] = l_a;
        ls[warp * 16 + g + 8] = l_b;
    }
    __syncwarp();

#pragma unroll
    for (int nt = 0; nt < 2; nt++) {
        int q_loc = warp * 16 + nt * 8 + 2 * t;
        float il0 = 1.0f / ls[q_loc];
        float il1 = 1.0f / ls[q_loc + 1];
        size_t r0 = (size_t)(batch * SEQ + q0 + q_loc) * DIM + head * HD;
        size_t r1 = r0 + DIM;
#pragma unroll
        for (int mt = 0; mt < 8; mt++) {
            int d = mt * 16 + g;
            ctx[r0 + d] = tf32r(o[mt][nt][0] * il0);
            ctx[r1 + d] = tf32r(o[mt][nt][1] * il1);
            ctx[r0 + d + 8] = tf32r(o[mt][nt][2] * il0);
            ctx[r1 + d + 8] = tf32r(o[mt][nt][3] * il1);
        }
    }
}

// ---------------------------------------------------------------------------
// Launch
// ---------------------------------------------------------------------------
extern "C" void kernel_launch(void* const* d_in, const int* in_sizes, int n_in,
                              void* d_out, int out_size) {
    const float* x      = (const float*)d_in[0];
    const float* Wqkv_w = (const float*)d_in[2];
    const float* Wqkv_b = (const float*)d_in[3];
    const float* Wout_w = (const float*)d_in[4];
    const float* Wout_b = (const float*)d_in[5];
    float* out = (float*)d_out;

    void *qkv_p, *ctx_p, *xr_p, *w1_p, *w2_p;
    cudaGetSymbolAddress(&qkv_p, g_qkv);
    cudaGetSymbolAddress(&ctx_p, g_ctx);
    cudaGetSymbolAddress(&xr_p, g_xr);
    cudaGetSymbolAddress(&w1_p, g_w1);
    cudaGetSymbolAddress(&w2_p, g_w2);
    float* qkv = (float*)qkv_p;
    float* ctx = (float*)ctx_p;
    float* xr  = (float*)xr_p;
    float* w1  = (float*)w1_p;
    float* w2  = (float*)w2_p;

    cudaFuncSetAttribute(gemm_tf32, cudaFuncAttributeMaxDynamicSharedMemorySize,
                         GEMM_SMEM_BYTES);
    cudaFuncSetAttribute(flash_attn_mma,
                         cudaFuncAttributeMaxDynamicSharedMemorySize, FA_SMEM_BYTES);

    // 0) Pre-round operands to tf32
    round_tf32<<<(NTOK * DIM / 4 + 255) / 256, 256>>>(x, xr, NTOK * DIM / 4);
    round_tf32<<<(DIM * QKVC / 4 + 255) / 256, 256>>>(Wqkv_w, w1, DIM * QKVC / 4);
    round_tf32<<<(DIM * DIM / 4 + 255) / 256, 256>>>(Wout_w, w2, DIM * DIM / 4);

    // 1) RoPE tables
    build_rope_tables<<<(SEQ * (HD / 2) + 255) / 256, 256>>>();

    // 2) QKV projection (rounded output feeds attention MMAs)
    gemm_tf32<<<dim3(QKVC / BN, NTOK / BM), 256, GEMM_SMEM_BYTES>>>(
        xr, w1, Wqkv_b, qkv, NTOK, QKVC, DIM, 1);

    // 3) RoPE on q,k in place (rounded output)
    rope_kernel<<<(NTOK * 2 * NH * (HD / 2)) / 256, 256>>>();

    // 4) Flash attention
    flash_attn_mma<<<dim3(SEQ / FQT, NH, BB), 256, FA_SMEM_BYTES>>>(qkv, ctx);

    // 5) Output projection (fp32 output)
    gemm_tf32<<<dim3(DIM / BN, NTOK / BM), 256, GEMM_SMEM_BYTES>>>(
        ctx, w2, Wout_b, out, NTOK, DIM, DIM, 0);
}

// round 7
// speedup vs baseline: 1.0478x; 1.0478x over previous
#include <cuda_runtime.h>
#include <math.h>
#include <stdint.h>

// Problem constants
#define BB 4
#define SEQ 2048
#define DIM 2048
#define NH 16
#define HD 128
#define NTOK (BB * SEQ)        // 8192
#define QKVC (3 * DIM)         // 6144

// Scratch (device globals: allocation-free)
__device__ float g_qkv[(size_t)NTOK * QKVC];   // 192 MB
__device__ float g_ctx[(size_t)NTOK * DIM];    // 64 MB
__device__ float g_xr[(size_t)NTOK * DIM];     // tf32-rounded x
__device__ float g_w1[(size_t)DIM * QKVC];     // tf32-rounded Wqkv
__device__ float g_w2[(size_t)DIM * DIM];      // tf32-rounded Wout
__device__ float g_cos[SEQ * (HD / 2)];
__device__ float g_sin[SEQ * (HD / 2)];

// ---------------------------------------------------------------------------
// PTX helpers
// ---------------------------------------------------------------------------
__device__ __forceinline__ void cp_async16(float* smem, const float* gmem) {
    uint32_t s = (uint32_t)__cvta_generic_to_shared(smem);
    asm volatile("cp.async.cg.shared.global [%0], [%1], 16;\n" :: "r"(s), "l"(gmem));
}
__device__ __forceinline__ void cp_commit() {
    asm volatile("cp.async.commit_group;\n");
}
__device__ __forceinline__ void cp_wait0() {
    asm volatile("cp.async.wait_group 0;\n");
}
__device__ __forceinline__ void cp_wait1() {
    asm volatile("cp.async.wait_group 1;\n");
}
__device__ __forceinline__ uint32_t f2tf32(float f) {
    uint32_t u;
    asm("cvt.rna.tf32.f32 %0, %1;\n" : "=r"(u) : "f"(f));
    return u;
}
__device__ __forceinline__ float tf32r(float f) {
    return __uint_as_float(f2tf32(f));
}
__device__ __forceinline__ uint32_t fu(float f) { return __float_as_uint(f); }

__device__ __forceinline__ void mma_tf32(float* c, const uint32_t* a, const uint32_t* b) {
    asm volatile(
        "mma.sync.aligned.m16n8k8.row.col.f32.tf32.tf32.f32 "
        "{%0,%1,%2,%3}, {%4,%5,%6,%7}, {%8,%9}, {%0,%1,%2,%3};\n"
        : "+f"(c[0]), "+f"(c[1]), "+f"(c[2]), "+f"(c[3])
        : "r"(a[0]), "r"(a[1]), "r"(a[2]), "r"(a[3]), "r"(b[0]), "r"(b[1]));
}

// ---------------------------------------------------------------------------
// Prep kernels
// ---------------------------------------------------------------------------
__global__ void round_tf32(const float* __restrict__ src, float* __restrict__ dst,
                           int n4) {
    int i = blockIdx.x * blockDim.x + threadIdx.x;
    if (i >= n4) return;
    float4 v = ((const float4*)src)[i];
    v.x = tf32r(v.x); v.y = tf32r(v.y); v.z = tf32r(v.z); v.w = tf32r(v.w);
    ((float4*)dst)[i] = v;
}

__global__ void build_rope_tables() {
    int idx = blockIdx.x * blockDim.x + threadIdx.x;
    if (idx >= SEQ * (HD / 2)) return;
    int pos = idx / (HD / 2);
    int i = idx % (HD / 2);
    double inv = exp(-((double)(2 * i) / (double)HD) * log(10000.0));
    double ang = (double)pos * inv;
    g_cos[idx] = (float)cos(ang);
    g_sin[idx] = (float)sin(ang);
}

// ---------------------------------------------------------------------------
// TF32 mma.sync GEMM: C = A @ B + bias.  BM=BN=128, BK=32, occ 2, 3 stages.
// rnd_out: tf32-round outputs.  do_rope: apply RoPE to cols < 2*DIM
// (q,k regions of the fused QKV output; pairs are (even,odd) columns).
// ---------------------------------------------------------------------------
#define BM 128
#define BN 128
#define BK 32
#define ASTRIDE 36
#define BSTRIDE 136
#define A_STAGE (BM * ASTRIDE)
#define B_STAGE (BK * BSTRIDE)
#define STAGE_FLOATS (A_STAGE + B_STAGE)   // 8960
#define NSTAGE 3
#define GEMM_SMEM_BYTES (NSTAGE * STAGE_FLOATS * 4)  // 107520

__device__ __forceinline__ void load_a_stage(float* As, const float* A, int K,
                                             int brow, int ktile, int tid) {
#pragma unroll
    for (int v = 0; v < 4; v++) {
        int idx = v * 256 + tid;
        int row = idx >> 3;
        int ch = idx & 7;
        cp_async16(As + row * ASTRIDE + ch * 4,
                   A + (size_t)(brow + row) * K + ktile * BK + ch * 4);
    }
}
__device__ __forceinline__ void load_b_stage(float* Bs, const float* B, int N,
                                             int bcol, int ktile, int tid) {
#pragma unroll
    for (int v = 0; v < 4; v++) {
        int idx = v * 256 + tid;
        int row = idx >> 5;
        int ch = idx & 31;
        cp_async16(Bs + row * BSTRIDE + ch * 4,
                   B + (size_t)(ktile * BK + row) * N + bcol + ch * 4);
    }
}

__global__ __launch_bounds__(256, 2)
void gemm_tf32(const float* __restrict__ A, const float* __restrict__ B,
               const float* __restrict__ bias, float* __restrict__ C,
               int M, int N, int K, int rnd_out, int do_rope) {
    extern __shared__ float sm[];
    int tid = threadIdx.x;
    int brow = blockIdx.y * BM;
    int bcol = blockIdx.x * BN;
    int warp = tid >> 5, lane = tid & 31;
    int wm = warp >> 1, wn = warp & 1;
    int g = lane >> 2, t = lane & 3;

    float c[2][8][4];
#pragma unroll
    for (int i = 0; i < 2; i++)
#pragma unroll
        for (int j = 0; j < 8; j++)
#pragma unroll
            for (int r = 0; r < 4; r++) c[i][j][r] = 0.f;

    const int NK = K / BK;

    // Prologue: stages 0, 1
#pragma unroll
    for (int s = 0; s < NSTAGE - 1; s++) {
        float* st = sm + s * STAGE_FLOATS;
        load_a_stage(st, A, K, brow, s, tid);
        load_b_stage(st + A_STAGE, B, N, bcol, s, tid);
        cp_commit();
    }

    for (int kt = 0; kt < NK; kt++) {
        cp_wait1();        // stage kt complete
        __syncthreads();   // prior reads of buf (kt+2)%NSTAGE finished

        if (kt + NSTAGE - 1 < NK) {
            float* st = sm + ((kt + NSTAGE - 1) % NSTAGE) * STAGE_FLOATS;
            load_a_stage(st, A, K, brow, kt + NSTAGE - 1, tid);
            load_b_stage(st + A_STAGE, B, N, bcol, kt + NSTAGE - 1, tid);
        }
        cp_commit();       // keep one commit per iteration

        const float* As = sm + (kt % NSTAGE) * STAGE_FLOATS;
        const float* Bs = As + A_STAGE;

#pragma unroll
        for (int ks = 0; ks < 4; ks++) {
            int k0 = ks * 8;
            uint32_t a[2][4], b[8][2];
#pragma unroll
            for (int mt = 0; mt < 2; mt++) {
                const float* ap = As + (wm * 32 + mt * 16 + g) * ASTRIDE + k0 + t;
                a[mt][0] = fu(ap[0]);
                a[mt][1] = fu(ap[8 * ASTRIDE]);
                a[mt][2] = fu(ap[4]);
                a[mt][3] = fu(ap[8 * ASTRIDE + 4]);
            }
#pragma unroll
            for (int nt = 0; nt < 8; nt++) {
                const float* bp = Bs + (k0 + t) * BSTRIDE + wn * 64 + nt * 8 + g;
                b[nt][0] = fu(bp[0]);
                b[nt][1] = fu(bp[4 * BSTRIDE]);
            }
#pragma unroll
            for (int mt = 0; mt < 2; mt++)
#pragma unroll
                for (int nt = 0; nt < 8; nt++)
                    mma_tf32(c[mt][nt], a[mt], b[nt]);
        }
    }

    // Epilogue: bias (+ optional fused RoPE) (+ optional tf32 rounding)
    int rope_here = do_rope && (bcol < 2 * DIM);   // CTA-uniform
#pragma unroll
    for (int mt = 0; mt < 2; mt++) {
        int r0 = brow + wm * 32 + mt * 16 + g;
        int pos0 = r0 & (SEQ - 1);
        int pos1 = (r0 + 8) & (SEQ - 1);
#pragma unroll
        for (int nt = 0; nt < 8; nt++) {
            int col = bcol + wn * 64 + nt * 8 + 2 * t;
            float b0 = bias[col], b1 = bias[col + 1];
            float v00 = c[mt][nt][0] + b0, v01 = c[mt][nt][1] + b1;
            float v10 = c[mt][nt][2] + b0, v11 = c[mt][nt][3] + b1;
            if (rope_here) {
                int i = (col & (HD - 1)) >> 1;
                float c0 = g_cos[pos0 * (HD / 2) + i];
                float s0 = g_sin[pos0 * (HD / 2) + i];
                float c1 = g_cos[pos1 * (HD / 2) + i];
                float s1 = g_sin[pos1 * (HD / 2) + i];
                float n00 = v00 * c0 - v01 * s0;
                float n01 = v01 * c0 + v00 * s0;
                float n10 = v10 * c1 - v11 * s1;
                float n11 = v11 * c1 + v10 * s1;
                v00 = n00; v01 = n01; v10 = n10; v11 = n11;
            }
            if (rnd_out) {
                v00 = tf32r(v00); v01 = tf32r(v01);
                v10 = tf32r(v10); v11 = tf32r(v11);
            }
            *(float2*)(C + (size_t)r0 * N + col) = make_float2(v00, v01);
            *(float2*)(C + (size_t)(r0 + 8) * N + col) = make_float2(v10, v11);
        }
    }
}

// ---------------------------------------------------------------------------
// Tensor-core flash attention (unchanged from R4 best)
// ---------------------------------------------------------------------------
#define FQT 128
#define FKT 64
#define QPAD 132
#define KPAD 132
#define VPAD 132
#define SPAD 76
#define KSTG (FKT * KPAD)
#define FA_SMEM_FLOATS (FQT * QPAD + 2 * KSTG + FKT * VPAD + FQT * SPAD + 256)
#define FA_SMEM_BYTES (FA_SMEM_FLOATS * 4)

__device__ __forceinline__ void fa_load_tile_async(float* dst, const float* gsrc,
                                                   int tid) {
#pragma unroll
    for (int v = 0; v < 8; v++) {
        int idx = v * 256 + tid;
        int row = idx >> 5, ch = (idx & 31) << 2;
        cp_async16(dst + row * KPAD + ch, gsrc + (size_t)row * QKVC + ch);
    }
}

__global__ __launch_bounds__(256, 1)
void flash_attn_mma(const float* __restrict__ qkv, float* __restrict__ ctx) {
    int qtile = blockIdx.x, head = blockIdx.y, batch = blockIdx.z;
    int q0 = qtile * FQT;
    int tid = threadIdx.x, warp = tid >> 5, lane = tid & 31;
    int g = lane >> 2, t = lane & 3;

    extern __shared__ float sm[];
    float* Qs = sm;
    float* Ks0 = Qs + FQT * QPAD;
    float* Vs = Ks0 + 2 * KSTG;
    float* Ss = Vs + FKT * VPAD;
    float* cr = Ss + FQT * SPAD;
    float* ls = cr + 128;

    const float scale = 0.08838834764831845f;
    const float* qbase = qkv + (size_t)(batch * SEQ + q0) * QKVC + head * HD;
    const float* kvbase = qkv + (size_t)(batch * SEQ) * QKVC + DIM + head * HD;

    int ntiles = 2 * (qtile + 1);

    fa_load_tile_async(Ks0, kvbase, tid);
    cp_commit();
    fa_load_tile_async(Vs, kvbase + DIM, tid);
    cp_commit();

#pragma unroll
    for (int v = 0; v < 16; v++) {
        int idx = v * 256 + tid;
        int row = idx >> 5, ch = (idx & 31) << 2;
        *(float4*)(Qs + row * QPAD + ch) =
            *(const float4*)(qbase + (size_t)row * QKVC + ch);
    }

    float o[8][2][4];
#pragma unroll
    for (int mt = 0; mt < 8; mt++)
#pragma unroll
        for (int nt = 0; nt < 2; nt++)
#pragma unroll
            for (int r = 0; r < 4; r++) o[mt][nt][r] = 0.f;

    float m_a = -INFINITY, m_b = -INFINITY, l_a = 0.f, l_b = 0.f;
    int rowa = q0 + warp * 16 + g;
    int rowb = rowa + 8;

    int buf = 0;
    for (int kt = 0; kt < ntiles; kt++) {
        int k0g = kt * FKT;
        const float* kvtile = kvbase + (size_t)k0g * QKVC;

        cp_wait1();
        __syncthreads();
        if (kt + 1 < ntiles) {
            fa_load_tile_async(Ks0 + (buf ^ 1) * KSTG,
                               kvtile + (size_t)FKT * QKVC, tid);
            cp_commit();
        }
        const float* Ks = Ks0 + buf * KSTG;

        float sc[8][4];
#pragma unroll
        for (int nt = 0; nt < 8; nt++)
#pragma unroll
            for (int r = 0; r < 4; r++) sc[nt][r] = 0.f;

#pragma unroll
        for (int k8 = 0; k8 < HD; k8 += 8) {
            uint32_t a[4];
            const float* qp = Qs + (warp * 16 + g) * QPAD + k8 + t;
            a[0] = fu(qp[0]);
            a[1] = fu(qp[8 * QPAD]);
            a[2] = fu(qp[4]);
            a[3] = fu(qp[8 * QPAD + 4]);
#pragma unroll
            for (int nt = 0; nt < 8; nt++) {
                uint32_t b[2];
                const float* kp = Ks + (nt * 8 + g) * KPAD + k8 + t;
                b[0] = fu(kp[0]);
                b[1] = fu(kp[4]);
                mma_tf32(sc[nt], a, b);
            }
        }

#pragma unroll
        for (int nt = 0; nt < 8; nt++)
#pragma unroll
            for (int r = 0; r < 4; r++) sc[nt][r] *= scale;

        if (kt >= 2 * qtile) {
#pragma unroll
            for (int nt = 0; nt < 8; nt++) {
                int col = k0g + nt * 8 + 2 * t;
                if (col > rowa) sc[nt][0] = -INFINITY;
                if (col + 1 > rowa) sc[nt][1] = -INFINITY;
                if (col > rowb) sc[nt][2] = -INFINITY;
                if (col + 1 > rowb) sc[nt][3] = -INFINITY;
            }
        }

        float tma = -INFINITY, tmb = -INFINITY;
#pragma unroll
        for (int nt = 0; nt < 8; nt++) {
            tma = fmaxf(tma, fmaxf(sc[nt][0], sc[nt][1]));
            tmb = fmaxf(tmb, fmaxf(sc[nt][2], sc[nt][3]));
        }
        tma = fmaxf(tma, __shfl_xor_sync(0xffffffff, tma, 1));
        tma = fmaxf(tma, __shfl_xor_sync(0xffffffff, tma, 2));
        tmb = fmaxf(tmb, __shfl_xor_sync(0xffffffff, tmb, 1));
        tmb = fmaxf(tmb, __shfl_xor_sync(0xffffffff, tmb, 2));

        float nma = fmaxf(m_a, tma), nmb = fmaxf(m_b, tmb);
        float ca = __expf(m_a - nma), cb = __expf(m_b - nmb);
        m_a = nma; m_b = nmb;

        float sa = 0.f, sb = 0.f;
#pragma unroll
        for (int nt = 0; nt < 8; nt++) {
            float p0 = __expf(sc[nt][0] - nma);
            float p1 = __expf(sc[nt][1] - nma);
            float p2 = __expf(sc[nt][2] - nmb);
            float p3 = __expf(sc[nt][3] - nmb);
            sc[nt][0] = p0; sc[nt][1] = p1; sc[nt][2] = p2; sc[nt][3] = p3;
            sa += p0 + p1;
            sb += p2 + p3;
        }
        sa += __shfl_xor_sync(0xffffffff, sa, 1);
        sa += __shfl_xor_sync(0xffffffff, sa, 2);
        sb += __shfl_xor_sync(0xffffffff, sb, 1);
        sb += __shfl_xor_sync(0xffffffff, sb, 2);
        l_a = l_a * ca + sa;
        l_b = l_b * cb + sb;

        if (t == 0) {
            cr[warp * 16 + g] = ca;
            cr[warp * 16 + g + 8] = cb;
        }

#pragma unroll
        for (int nt = 0; nt < 8; nt++) {
            *(float2*)(Ss + (warp * 16 + g) * SPAD + nt * 8 + 2 * t) =
                make_float2(sc[nt][0], sc[nt][1]);
            *(float2*)(Ss + (warp * 16 + g + 8) * SPAD + nt * 8 + 2 * t) =
                make_float2(sc[nt][2], sc[nt][3]);
        }

        if (kt + 1 < ntiles) cp_wait1(); else cp_wait0();
        __syncthreads();

#pragma unroll
        for (int nt = 0; nt < 2; nt++) {
            float c0 = cr[warp * 16 + nt * 8 + 2 * t];
            float c1 = cr[warp * 16 + nt * 8 + 2 * t + 1];
#pragma unroll
            for (int mt = 0; mt < 8; mt++) {
                o[mt][nt][0] *= c0;
                o[mt][nt][1] *= c1;
                o[mt][nt][2] *= c0;
                o[mt][nt][3] *= c1;
            }
        }

#pragma unroll
        for (int k8 = 0; k8 < FKT; k8 += 8) {
            uint32_t b[2][2];
#pragma unroll
            for (int nt = 0; nt < 2; nt++) {
                const float* pp = Ss + (warp * 16 + nt * 8 + g) * SPAD + k8 + t;
                b[nt][0] = f2tf32(pp[0]);
                b[nt][1] = f2tf32(pp[4]);
            }
#pragma unroll
            for (int mt = 0; mt < 8; mt++) {
                uint32_t a[4];
                const float* vp = Vs + (k8 + t) * VPAD + mt * 16 + g;
                a[0] = fu(vp[0]);
                a[1] = fu(vp[8]);
                a[2] = fu(vp[4 * VPAD]);
                a[3] = fu(vp[4 * VPAD + 8]);
                mma_tf32(o[mt][0], a, b[0]);
                mma_tf32(o[mt][1], a, b[1]);
            }
        }

        __syncthreads();
        if (kt + 1 < ntiles) {
            fa_load_tile_async(Vs, kvtile + (size_t)FKT * QKVC + DIM, tid);
            cp_commit();
        }
        buf ^= 1;
    }

    if (t == 0) {
        ls[warp * 16 + g] = l_a;
        ls[warp * 16 + g + 8] = l_b;
    }
    __syncwarp();

#pragma unroll
    for (int nt = 0; nt < 2; nt++) {
        int q_loc = warp * 16 + nt * 8 + 2 * t;
        float il0 = 1.0f / ls[q_loc];
        float il1 = 1.0f / ls[q_loc + 1];
        size_t r0 = (size_t)(batch * SEQ + q0 + q_loc) * DIM + head * HD;
        size_t r1 = r0 + DIM;
#pragma unroll
        for (int mt = 0; mt < 8; mt++) {
            int d = mt * 16 + g;
            ctx[r0 + d] = tf32r(o[mt][nt][0] * il0);
            ctx[r1 + d] = tf32r(o[mt][nt][1] * il1);
            ctx[r0 + d + 8] = tf32r(o[mt][nt][2] * il0);
            ctx[r1 + d + 8] = tf32r(o[mt][nt][3] * il1);
        }
    }
}

// ---------------------------------------------------------------------------
// Launch
// ---------------------------------------------------------------------------
extern "C" void kernel_launch(void* const* d_in, const int* in_sizes, int n_in,
                              void* d_out, int out_size) {
    const float* x      = (const float*)d_in[0];
    const float* Wqkv_w = (const float*)d_in[2];
    const float* Wqkv_b = (const float*)d_in[3];
    const float* Wout_w = (const float*)d_in[4];
    const float* Wout_b = (const float*)d_in[5];
    float* out = (float*)d_out;

    void *qkv_p, *ctx_p, *xr_p, *w1_p, *w2_p;
    cudaGetSymbolAddress(&qkv_p, g_qkv);
    cudaGetSymbolAddress(&ctx_p, g_ctx);
    cudaGetSymbolAddress(&xr_p, g_xr);
    cudaGetSymbolAddress(&w1_p, g_w1);
    cudaGetSymbolAddress(&w2_p, g_w2);
    float* qkv = (float*)qkv_p;
    float* ctx = (float*)ctx_p;
    float* xr  = (float*)xr_p;
    float* w1  = (float*)w1_p;
    float* w2  = (float*)w2_p;

    cudaFuncSetAttribute(gemm_tf32, cudaFuncAttributeMaxDynamicSharedMemorySize,
                         GEMM_SMEM_BYTES);
    cudaFuncSetAttribute(flash_attn_mma,
                         cudaFuncAttributeMaxDynamicSharedMemorySize, FA_SMEM_BYTES);

    // 0) Pre-round operands to tf32
    round_tf32<<<(NTOK * DIM / 4 + 255) / 256, 256>>>(x, xr, NTOK * DIM / 4);
    round_tf32<<<(DIM * QKVC / 4 + 255) / 256, 256>>>(Wqkv_w, w1, DIM * QKVC / 4);
    round_tf32<<<(DIM * DIM / 4 + 255) / 256, 256>>>(Wout_w, w2, DIM * DIM / 4);

    // 1) RoPE tables (needed by gemm1 epilogue)
    build_rope_tables<<<(SEQ * (HD / 2) + 255) / 256, 256>>>();

    // 2) QKV projection with fused RoPE + tf32-rounded output
    gemm_tf32<<<dim3(QKVC / BN, NTOK / BM), 256, GEMM_SMEM_BYTES>>>(
        xr, w1, Wqkv_b, qkv, NTOK, QKVC, DIM, 1, 1);

    // 3) Flash attention
    flash_attn_mma<<<dim3(SEQ / FQT, NH, BB), 256, FA_SMEM_BYTES>>>(qkv, ctx);

    // 4) Output projection (fp32 output)
    gemm_tf32<<<dim3(DIM / BN, NTOK / BM), 256, GEMM_SMEM_BYTES>>>(
        ctx, w2, Wout_b, out, NTOK, DIM, DIM, 0, 0);
}

// round 8
// speedup vs baseline: 1.5213x; 1.4519x over previous
#include <cuda_runtime.h>
#include <cuda_fp16.h>
#include <math.h>
#include <stdint.h>

// Problem constants
#define BB 4
#define SEQ 2048
#define DIM 2048
#define NH 16
#define HD 128
#define NTOK (BB * SEQ)        // 8192
#define QKVC (3 * DIM)         // 6144

// Scratch (device globals: allocation-free)
__device__ float  g_qkv[(size_t)NTOK * QKVC];   // 192 MB (fp32, tf32-rounded)
__device__ __half g_ctxh[(size_t)NTOK * DIM];   // 32 MB  fp16 ctx
__device__ __half g_xh[(size_t)NTOK * DIM];     // 32 MB  fp16 x
__device__ __half g_w1t[(size_t)QKVC * DIM];    // 25 MB  Wqkv^T fp16 [6144][2048]
__device__ __half g_w2t[(size_t)DIM * DIM];     // 8 MB   Wout^T fp16 [2048][2048]
__device__ float g_cos[SEQ * (HD / 2)];
__device__ float g_sin[SEQ * (HD / 2)];

// ---------------------------------------------------------------------------
// PTX helpers
// ---------------------------------------------------------------------------
__device__ __forceinline__ void cp_async16(const void* smem, const void* gmem) {
    uint32_t s = (uint32_t)__cvta_generic_to_shared(smem);
    asm volatile("cp.async.cg.shared.global [%0], [%1], 16;\n" :: "r"(s), "l"(gmem));
}
__device__ __forceinline__ void cp_commit() {
    asm volatile("cp.async.commit_group;\n");
}
__device__ __forceinline__ void cp_wait0() {
    asm volatile("cp.async.wait_group 0;\n");
}
__device__ __forceinline__ void cp_wait1() {
    asm volatile("cp.async.wait_group 1;\n");
}
__device__ __forceinline__ uint32_t f2tf32(float f) {
    uint32_t u;
    asm("cvt.rna.tf32.f32 %0, %1;\n" : "=r"(u) : "f"(f));
    return u;
}
__device__ __forceinline__ float tf32r(float f) {
    return __uint_as_float(f2tf32(f));
}
__device__ __forceinline__ uint32_t fu(float f) { return __float_as_uint(f); }

__device__ __forceinline__ void mma_tf32(float* c, const uint32_t* a, const uint32_t* b) {
    asm volatile(
        "mma.sync.aligned.m16n8k8.row.col.f32.tf32.tf32.f32 "
        "{%0,%1,%2,%3}, {%4,%5,%6,%7}, {%8,%9}, {%0,%1,%2,%3};\n"
        : "+f"(c[0]), "+f"(c[1]), "+f"(c[2]), "+f"(c[3])
        : "r"(a[0]), "r"(a[1]), "r"(a[2]), "r"(a[3]), "r"(b[0]), "r"(b[1]));
}
__device__ __forceinline__ void mma_f16(float* c, const uint32_t* a, const uint32_t* b) {
    asm volatile(
        "mma.sync.aligned.m16n8k16.row.col.f32.f16.f16.f32 "
        "{%0,%1,%2,%3}, {%4,%5,%6,%7}, {%8,%9}, {%0,%1,%2,%3};\n"
        : "+f"(c[0]), "+f"(c[1]), "+f"(c[2]), "+f"(c[3])
        : "r"(a[0]), "r"(a[1]), "r"(a[2]), "r"(a[3]), "r"(b[0]), "r"(b[1]));
}

// ---------------------------------------------------------------------------
// Prep kernels
// ---------------------------------------------------------------------------
__global__ void conv_half(const float* __restrict__ src, __half* __restrict__ dst,
                          int n4) {
    int i = blockIdx.x * blockDim.x + threadIdx.x;
    if (i >= n4) return;
    float4 v = ((const float4*)src)[i];
    __half2 h0 = __floats2half2_rn(v.x, v.y);
    __half2 h1 = __floats2half2_rn(v.z, v.w);
    ((__half2*)dst)[2 * i] = h0;
    ((__half2*)dst)[2 * i + 1] = h1;
}

// dst[c][r] = half(src[r][c]);  src: [R][C] fp32
__global__ void transpose_half(const float* __restrict__ src,
                               __half* __restrict__ dst, int R, int C) {
    __shared__ float t[32][33];
    int bx = blockIdx.x * 32, by = blockIdx.y * 32;
    int tx = threadIdx.x, ty = threadIdx.y;
#pragma unroll
    for (int j = 0; j < 32; j += 8)
        t[ty + j][tx] = src[(size_t)(by + ty + j) * C + bx + tx];
    __syncthreads();
#pragma unroll
    for (int j = 0; j < 32; j += 8)
        dst[(size_t)(bx + ty + j) * R + by + tx] = __float2half_rn(t[tx][ty + j]);
}

__global__ void build_rope_tables() {
    int idx = blockIdx.x * blockDim.x + threadIdx.x;
    if (idx >= SEQ * (HD / 2)) return;
    int pos = idx / (HD / 2);
    int i = idx % (HD / 2);
    double inv = exp(-((double)(2 * i) / (double)HD) * log(10000.0));
    double ang = (double)pos * inv;
    g_cos[idx] = (float)cos(ang);
    g_sin[idx] = (float)sin(ang);
}

// ---------------------------------------------------------------------------
// FP16 mma.sync GEMM: C[M,N](fp32) = A[M,K](fp16) @ Bt[N,K](fp16)^T + bias
// BM=BN=128, BK=64 halves, 3-stage cp.async, occ 2.
// do_rope: fused RoPE on cols < 2*DIM.  rnd_out: tf32-round output.
// ---------------------------------------------------------------------------
#define BM 128
#define BN 128
#define HBK 64
#define HSTRIDE 72                          // halves; fragment bank = 4g+t
#define HA_STAGE (BM * HSTRIDE)             // 9216 halves
#define HB_STAGE (BN * HSTRIDE)
#define HSTAGE (HA_STAGE + HB_STAGE)        // 18432 halves = 36864 B
#define NSTAGE 3
#define GEMM_SMEM_BYTES (NSTAGE * HSTAGE * 2)   // 110592

__device__ __forceinline__ void load_h_tile(__half* S, const __half* G, int ldg,
                                            int k0, int tid) {
    // 128 rows x 8 chunks(16B); 4 chunks per thread
#pragma unroll
    for (int v = 0; v < 4; v++) {
        int idx = v * 256 + tid;
        int r = idx >> 3, ch = idx & 7;
        cp_async16(S + r * HSTRIDE + ch * 8, G + (size_t)r * ldg + k0 + ch * 8);
    }
}

__global__ __launch_bounds__(256, 2)
void gemm_fp16(const __half* __restrict__ A, const __half* __restrict__ Bt,
               const float* __restrict__ bias, float* __restrict__ C,
               int M, int N, int K, int rnd_out, int do_rope) {
    extern __shared__ __half smh[];
    int tid = threadIdx.x;
    int brow = blockIdx.y * BM;
    int bcol = blockIdx.x * BN;
    int warp = tid >> 5, lane = tid & 31;
    int wm = warp >> 1, wn = warp & 1;
    int g = lane >> 2, t = lane & 3;

    float c[2][8][4];
#pragma unroll
    for (int i = 0; i < 2; i++)
#pragma unroll
        for (int j = 0; j < 8; j++)
#pragma unroll
            for (int r = 0; r < 4; r++) c[i][j][r] = 0.f;

    const int NK = K / HBK;
    const __half* Ab = A + (size_t)brow * K;
    const __half* Bb = Bt + (size_t)bcol * K;

    // Prologue: stages 0, 1
#pragma unroll
    for (int s = 0; s < NSTAGE - 1; s++) {
        __half* st = smh + s * HSTAGE;
        load_h_tile(st, Ab, K, s * HBK, tid);
        load_h_tile(st + HA_STAGE, Bb, K, s * HBK, tid);
        cp_commit();
    }

    for (int kt = 0; kt < NK; kt++) {
        cp_wait1();
        __syncthreads();

        if (kt + NSTAGE - 1 < NK) {
            __half* st = smh + ((kt + NSTAGE - 1) % NSTAGE) * HSTAGE;
            load_h_tile(st, Ab, K, (kt + NSTAGE - 1) * HBK, tid);
            load_h_tile(st + HA_STAGE, Bb, K, (kt + NSTAGE - 1) * HBK, tid);
        }
        cp_commit();

        const __half* As = smh + (kt % NSTAGE) * HSTAGE;
        const __half* Bs = As + HA_STAGE;

#pragma unroll
        for (int j = 0; j < 4; j++) {       // k16 steps
            int k0 = j * 16;
            uint32_t a[2][4], b[8][2];
#pragma unroll
            for (int mt = 0; mt < 2; mt++) {
                const __half* ap = As + (wm * 32 + mt * 16 + g) * HSTRIDE + k0 + 2 * t;
                a[mt][0] = *(const uint32_t*)ap;
                a[mt][1] = *(const uint32_t*)(ap + 8 * HSTRIDE);
                a[mt][2] = *(const uint32_t*)(ap + 8);
                a[mt][3] = *(const uint32_t*)(ap + 8 * HSTRIDE + 8);
            }
#pragma unroll
            for (int nt = 0; nt < 8; nt++) {
                const __half* bp = Bs + (wn * 64 + nt * 8 + g) * HSTRIDE + k0 + 2 * t;
                b[nt][0] = *(const uint32_t*)bp;
                b[nt][1] = *(const uint32_t*)(bp + 8);
            }
#pragma unroll
            for (int mt = 0; mt < 2; mt++)
#pragma unroll
                for (int nt = 0; nt < 8; nt++)
                    mma_f16(c[mt][nt], a[mt], b[nt]);
        }
    }

    // Epilogue: bias (+ fused RoPE) (+ tf32 rounding), fp32 out
    int rope_here = do_rope && (bcol < 2 * DIM);
#pragma unroll
    for (int mt = 0; mt < 2; mt++) {
        int r0 = brow + wm * 32 + mt * 16 + g;
        int pos0 = r0 & (SEQ - 1);
        int pos1 = (r0 + 8) & (SEQ - 1);
#pragma unroll
        for (int nt = 0; nt < 8; nt++) {
            int col = bcol + wn * 64 + nt * 8 + 2 * t;
            float b0 = bias[col], b1 = bias[col + 1];
            float v00 = c[mt][nt][0] + b0, v01 = c[mt][nt][1] + b1;
            float v10 = c[mt][nt][2] + b0, v11 = c[mt][nt][3] + b1;
            if (rope_here) {
                int i = (col & (HD - 1)) >> 1;
                float c0 = g_cos[pos0 * (HD / 2) + i];
                float s0 = g_sin[pos0 * (HD / 2) + i];
                float c1 = g_cos[pos1 * (HD / 2) + i];
                float s1 = g_sin[pos1 * (HD / 2) + i];
                float n00 = v00 * c0 - v01 * s0;
                float n01 = v01 * c0 + v00 * s0;
                float n10 = v10 * c1 - v11 * s1;
                float n11 = v11 * c1 + v10 * s1;
                v00 = n00; v01 = n01; v10 = n10; v11 = n11;
            }
            if (rnd_out) {
                v00 = tf32r(v00); v01 = tf32r(v01);
                v10 = tf32r(v10); v11 = tf32r(v11);
            }
            *(float2*)(C + (size_t)r0 * N + col) = make_float2(v00, v01);
            *(float2*)(C + (size_t)(r0 + 8) * N + col) = make_float2(v10, v11);
        }
    }
}

// ---------------------------------------------------------------------------
// Tensor-core flash attention (tf32, unchanged core; epilogue writes fp16 ctx)
// ---------------------------------------------------------------------------
#define FQT 128
#define FKT 64
#define QPAD 132
#define KPAD 132
#define VPAD 132
#define SPAD 76
#define KSTG (FKT * KPAD)
#define FA_SMEM_FLOATS (FQT * QPAD + 2 * KSTG + FKT * VPAD + FQT * SPAD + 256)
#define FA_SMEM_BYTES (FA_SMEM_FLOATS * 4)

__device__ __forceinline__ void fa_load_tile_async(float* dst, const float* gsrc,
                                                   int tid) {
#pragma unroll
    for (int v = 0; v < 8; v++) {
        int idx = v * 256 + tid;
        int row = idx >> 5, ch = (idx & 31) << 2;
        cp_async16(dst + row * KPAD + ch, gsrc + (size_t)row * QKVC + ch);
    }
}

__global__ __launch_bounds__(256, 1)
void flash_attn_mma(const float* __restrict__ qkv, __half* __restrict__ ctx) {
    int qtile = blockIdx.x, head = blockIdx.y, batch = blockIdx.z;
    int q0 = qtile * FQT;
    int tid = threadIdx.x, warp = tid >> 5, lane = tid & 31;
    int g = lane >> 2, t = lane & 3;

    extern __shared__ float sm[];
    float* Qs = sm;
    float* Ks0 = Qs + FQT * QPAD;
    float* Vs = Ks0 + 2 * KSTG;
    float* Ss = Vs + FKT * VPAD;
    float* cr = Ss + FQT * SPAD;
    float* ls = cr + 128;

    const float scale = 0.08838834764831845f;
    const float* qbase = qkv + (size_t)(batch * SEQ + q0) * QKVC + head * HD;
    const float* kvbase = qkv + (size_t)(batch * SEQ) * QKVC + DIM + head * HD;

    int ntiles = 2 * (qtile + 1);

    fa_load_tile_async(Ks0, kvbase, tid);
    cp_commit();
    fa_load_tile_async(Vs, kvbase + DIM, tid);
    cp_commit();

#pragma unroll
    for (int v = 0; v < 16; v++) {
        int idx = v * 256 + tid;
        int row = idx >> 5, ch = (idx & 31) << 2;
        *(float4*)(Qs + row * QPAD + ch) =
            *(const float4*)(qbase + (size_t)row * QKVC + ch);
    }

    float o[8][2][4];
#pragma unroll
    for (int mt = 0; mt < 8; mt++)
#pragma unroll
        for (int nt = 0; nt < 2; nt++)
#pragma unroll
            for (int r = 0; r < 4; r++) o[mt][nt][r] = 0.f;

    float m_a = -INFINITY, m_b = -INFINITY, l_a = 0.f, l_b = 0.f;
    int rowa = q0 + warp * 16 + g;
    int rowb = rowa + 8;

    int buf = 0;
    for (int kt = 0; kt < ntiles; kt++) {
        int k0g = kt * FKT;
        const float* kvtile = kvbase + (size_t)k0g * QKVC;

        cp_wait1();
        __syncthreads();
        if (kt + 1 < ntiles) {
            fa_load_tile_async(Ks0 + (buf ^ 1) * KSTG,
                               kvtile + (size_t)FKT * QKVC, tid);
            cp_commit();
        }
        const float* Ks = Ks0 + buf * KSTG;

        float sc[8][4];
#pragma unroll
        for (int nt = 0; nt < 8; nt++)
#pragma unroll
            for (int r = 0; r < 4; r++) sc[nt][r] = 0.f;

#pragma unroll
        for (int k8 = 0; k8 < HD; k8 += 8) {
            uint32_t a[4];
            const float* qp = Qs + (warp * 16 + g) * QPAD + k8 + t;
            a[0] = fu(qp[0]);
            a[1] = fu(qp[8 * QPAD]);
            a[2] = fu(qp[4]);
            a[3] = fu(qp[8 * QPAD + 4]);
#pragma unroll
            for (int nt = 0; nt < 8; nt++) {
                uint32_t b[2];
                const float* kp = Ks + (nt * 8 + g) * KPAD + k8 + t;
                b[0] = fu(kp[0]);
                b[1] = fu(kp[4]);
                mma_tf32(sc[nt], a, b);
            }
        }

#pragma unroll
        for (int nt = 0; nt < 8; nt++)
#pragma unroll
            for (int r = 0; r < 4; r++) sc[nt][r] *= scale;

        if (kt >= 2 * qtile) {
#pragma unroll
            for (int nt = 0; nt < 8; nt++) {
                int col = k0g + nt * 8 + 2 * t;
                if (col > rowa) sc[nt][0] = -INFINITY;
                if (col + 1 > rowa) sc[nt][1] = -INFINITY;
                if (col > rowb) sc[nt][2] = -INFINITY;
                if (col + 1 > rowb) sc[nt][3] = -INFINITY;
            }
        }

        float tma = -INFINITY, tmb = -INFINITY;
#pragma unroll
        for (int nt = 0; nt < 8; nt++) {
            tma = fmaxf(tma, fmaxf(sc[nt][0], sc[nt][1]));
            tmb = fmaxf(tmb, fmaxf(sc[nt][2], sc[nt][3]));
        }
        tma = fmaxf(tma, __shfl_xor_sync(0xffffffff, tma, 1));
        tma = fmaxf(tma, __shfl_xor_sync(0xffffffff, tma, 2));
        tmb = fmaxf(tmb, __shfl_xor_sync(0xffffffff, tmb, 1));
        tmb = fmaxf(tmb, __shfl_xor_sync(0xffffffff, tmb, 2));

        float nma = fmaxf(m_a, tma), nmb = fmaxf(m_b, tmb);
        float ca = __expf(m_a - nma), cb = __expf(m_b - nmb);
        m_a = nma; m_b = nmb;

        float sa = 0.f, sb = 0.f;
#pragma unroll
        for (int nt = 0; nt < 8; nt++) {
            float p0 = __expf(sc[nt][0] - nma);
            float p1 = __expf(sc[nt][1] - nma);
            float p2 = __expf(sc[nt][2] - nmb);
            float p3 = __expf(sc[nt][3] - nmb);
            sc[nt][0] = p0; sc[nt][1] = p1; sc[nt][2] = p2; sc[nt][3] = p3;
            sa += p0 + p1;
            sb += p2 + p3;
        }
        sa += __shfl_xor_sync(0xffffffff, sa, 1);
        sa += __shfl_xor_sync(0xffffffff, sa, 2);
        sb += __shfl_xor_sync(0xffffffff, sb, 1);
        sb += __shfl_xor_sync(0xffffffff, sb, 2);
        l_a = l_a * ca + sa;
        l_b = l_b * cb + sb;

        if (t == 0) {
            cr[warp * 16 + g] = ca;
            cr[warp * 16 + g + 8] = cb;
        }

#pragma unroll
        for (int nt = 0; nt < 8; nt++) {
            *(float2*)(Ss + (warp * 16 + g) * SPAD + nt * 8 + 2 * t) =
                make_float2(sc[nt][0], sc[nt][1]);
            *(float2*)(Ss + (warp * 16 + g + 8) * SPAD + nt * 8 + 2 * t) =
                make_float2(sc[nt][2], sc[nt][3]);
        }

        if (kt + 1 < ntiles) cp_wait1(); else cp_wait0();
        __syncthreads();

#pragma unroll
        for (int nt = 0; nt < 2; nt++) {
            float c0 = cr[warp * 16 + nt * 8 + 2 * t];
            float c1 = cr[warp * 16 + nt * 8 + 2 * t + 1];
#pragma unroll
            for (int mt = 0; mt < 8; mt++) {
                o[mt][nt][0] *= c0;
                o[mt][nt][1] *= c1;
                o[mt][nt][2] *= c0;
                o[mt][nt][3] *= c1;
            }
        }

#pragma unroll
        for (int k8 = 0; k8 < FKT; k8 += 8) {
            uint32_t b[2][2];
#pragma unroll
            for (int nt = 0; nt < 2; nt++) {
                const float* pp = Ss + (warp * 16 + nt * 8 + g) * SPAD + k8 + t;
                b[nt][0] = f2tf32(pp[0]);
                b[nt][1] = f2tf32(pp[4]);
            }
#pragma unroll
            for (int mt = 0; mt < 8; mt++) {
                uint32_t a[4];
                const float* vp = Vs + (k8 + t) * VPAD + mt * 16 + g;
                a[0] = fu(vp[0]);
                a[1] = fu(vp[8]);
                a[2] = fu(vp[4 * VPAD]);
                a[3] = fu(vp[4 * VPAD + 8]);
                mma_tf32(o[mt][0], a, b[0]);
                mma_tf32(o[mt][1], a, b[1]);
            }
        }

        __syncthreads();
        if (kt + 1 < ntiles) {
            fa_load_tile_async(Vs, kvtile + (size_t)FKT * QKVC + DIM, tid);
            cp_commit();
        }
        buf ^= 1;
    }

    if (t == 0) {
        ls[warp * 16 + g] = l_a;
        ls[warp * 16 + g + 8] = l_b;
    }
    __syncwarp();

#pragma unroll
    for (int nt = 0; nt < 2; nt++) {
        int q_loc = warp * 16 + nt * 8 + 2 * t;
        float il0 = 1.0f / ls[q_loc];
        float il1 = 1.0f / ls[q_loc + 1];
        size_t r0 = (size_t)(batch * SEQ + q0 + q_loc) * DIM + head * HD;
        size_t r1 = r0 + DIM;
#pragma unroll
        for (int mt = 0; mt < 8; mt++) {
            int d = mt * 16 + g;
            ctx[r0 + d] = __float2half_rn(o[mt][nt][0] * il0);
            ctx[r1 + d] = __float2half_rn(o[mt][nt][1] * il1);
            ctx[r0 + d + 8] = __float2half_rn(o[mt][nt][2] * il0);
            ctx[r1 + d + 8] = __float2half_rn(o[mt][nt][3] * il1);
        }
    }
}

// ---------------------------------------------------------------------------
// Launch
// ---------------------------------------------------------------------------
extern "C" void kernel_launch(void* const* d_in, const int* in_sizes, int n_in,
                              void* d_out, int out_size) {
    const float* x      = (const float*)d_in[0];
    const float* Wqkv_w = (const float*)d_in[2];
    const float* Wqkv_b = (const float*)d_in[3];
    const float* Wout_w = (const float*)d_in[4];
    const float* Wout_b = (const float*)d_in[5];
    float* out = (float*)d_out;

    void *qkv_p, *ctx_p, *xh_p, *w1_p, *w2_p;
    cudaGetSymbolAddress(&qkv_p, g_qkv);
    cudaGetSymbolAddress(&ctx_p, g_ctxh);
    cudaGetSymbolAddress(&xh_p, g_xh);
    cudaGetSymbolAddress(&w1_p, g_w1t);
    cudaGetSymbolAddress(&w2_p, g_w2t);
    float*  qkv = (float*)qkv_p;
    __half* ctx = (__half*)ctx_p;
    __half* xh  = (__half*)xh_p;
    __half* w1t = (__half*)w1_p;
    __half* w2t = (__half*)w2_p;

    cudaFuncSetAttribute(gemm_fp16, cudaFuncAttributeMaxDynamicSharedMemorySize,
                         GEMM_SMEM_BYTES);
    cudaFuncSetAttribute(flash_attn_mma,
                         cudaFuncAttributeMaxDynamicSharedMemorySize, FA_SMEM_BYTES);

    // 0) Prep: x -> fp16; weights -> transposed fp16 [N][K]
    conv_half<<<(NTOK * DIM / 4 + 255) / 256, 256>>>(x, xh, NTOK * DIM / 4);
    transpose_half<<<dim3(QKVC / 32, DIM / 32), dim3(32, 8)>>>(Wqkv_w, w1t,
                                                               DIM, QKVC);
    transpose_half<<<dim3(DIM / 32, DIM / 32), dim3(32, 8)>>>(Wout_w, w2t,
                                                              DIM, DIM);

    // 1) RoPE tables
    build_rope_tables<<<(SEQ * (HD / 2) + 255) / 256, 256>>>();

    // 2) QKV projection (fp16 MMA) with fused RoPE, tf32-rounded fp32 output
    gemm_fp16<<<dim3(QKVC / BN, NTOK / BM), 256, GEMM_SMEM_BYTES>>>(
        xh, w1t, Wqkv_b, qkv, NTOK, QKVC, DIM, 1, 1);

    // 3) Flash attention (tf32 MMA; writes fp16 ctx)
    flash_attn_mma<<<dim3(SEQ / FQT, NH, BB), 256, FA_SMEM_BYTES>>>(qkv, ctx);

    // 4) Output projection (fp16 MMA, fp32 output)
    gemm_fp16<<<dim3(DIM / BN, NTOK / BM), 256, GEMM_SMEM_BYTES>>>(
        ctx, w2t, Wout_b, out, NTOK, DIM, DIM, 0, 0);
}

// round 9
// speedup vs baseline: 1.9585x; 1.2874x over previous
#include <cuda_runtime.h>
#include <cuda_fp16.h>
#include <math.h>
#include <stdint.h>

// Problem constants
#define BB 4
#define SEQ 2048
#define DIM 2048
#define NH 16
#define HD 128
#define NTOK (BB * SEQ)        // 8192
#define QKVC (3 * DIM)         // 6144

// Scratch (device globals: allocation-free)
__device__ __half g_qkvh[(size_t)NTOK * QKVC];  // 96 MB fp16 qkv (post-RoPE)
__device__ __half g_ctxh[(size_t)NTOK * DIM];   // 32 MB fp16 ctx
__device__ __half g_xh[(size_t)NTOK * DIM];     // 32 MB fp16 x
__device__ __half g_w1t[(size_t)QKVC * DIM];    // 25 MB Wqkv^T fp16
__device__ __half g_w2t[(size_t)DIM * DIM];     // 8 MB  Wout^T fp16
__device__ float g_cos[SEQ * (HD / 2)];
__device__ float g_sin[SEQ * (HD / 2)];

// ---------------------------------------------------------------------------
// PTX helpers
// ---------------------------------------------------------------------------
__device__ __forceinline__ void cp_async16(const void* smem, const void* gmem) {
    uint32_t s = (uint32_t)__cvta_generic_to_shared(smem);
    asm volatile("cp.async.cg.shared.global [%0], [%1], 16;\n" :: "r"(s), "l"(gmem));
}
__device__ __forceinline__ void cp_commit() {
    asm volatile("cp.async.commit_group;\n");
}
__device__ __forceinline__ void cp_wait0() {
    asm volatile("cp.async.wait_group 0;\n");
}
__device__ __forceinline__ void cp_wait1() {
    asm volatile("cp.async.wait_group 1;\n");
}
__device__ __forceinline__ void mma_f16(float* c, const uint32_t* a, const uint32_t* b) {
    asm volatile(
        "mma.sync.aligned.m16n8k16.row.col.f32.f16.f16.f32 "
        "{%0,%1,%2,%3}, {%4,%5,%6,%7}, {%8,%9}, {%0,%1,%2,%3};\n"
        : "+f"(c[0]), "+f"(c[1]), "+f"(c[2]), "+f"(c[3])
        : "r"(a[0]), "r"(a[1]), "r"(a[2]), "r"(a[3]), "r"(b[0]), "r"(b[1]));
}
__device__ __forceinline__ void ldmatrix_x4_trans(uint32_t& r0, uint32_t& r1,
                                                  uint32_t& r2, uint32_t& r3,
                                                  uint32_t addr) {
    asm volatile(
        "ldmatrix.sync.aligned.m8n8.x4.trans.shared.b16 {%0,%1,%2,%3}, [%4];"
        : "=r"(r0), "=r"(r1), "=r"(r2), "=r"(r3) : "r"(addr));
}
__device__ __forceinline__ uint32_t pack_half2(float a, float b) {
    __half2 h = __floats2half2_rn(a, b);
    return *(uint32_t*)&h;
}

// ---------------------------------------------------------------------------
// Prep kernels
// ---------------------------------------------------------------------------
__global__ void conv_half(const float* __restrict__ src, __half* __restrict__ dst,
                          int n4) {
    int i = blockIdx.x * blockDim.x + threadIdx.x;
    if (i >= n4) return;
    float4 v = ((const float4*)src)[i];
    ((__half2*)dst)[2 * i] = __floats2half2_rn(v.x, v.y);
    ((__half2*)dst)[2 * i + 1] = __floats2half2_rn(v.z, v.w);
}

__global__ void transpose_half(const float* __restrict__ src,
                               __half* __restrict__ dst, int R, int C) {
    __shared__ float t[32][33];
    int bx = blockIdx.x * 32, by = blockIdx.y * 32;
    int tx = threadIdx.x, ty = threadIdx.y;
#pragma unroll
    for (int j = 0; j < 32; j += 8)
        t[ty + j][tx] = src[(size_t)(by + ty + j) * C + bx + tx];
    __syncthreads();
#pragma unroll
    for (int j = 0; j < 32; j += 8)
        dst[(size_t)(bx + ty + j) * R + by + tx] = __float2half_rn(t[tx][ty + j]);
}

__global__ void build_rope_tables() {
    int idx = blockIdx.x * blockDim.x + threadIdx.x;
    if (idx >= SEQ * (HD / 2)) return;
    int pos = idx / (HD / 2);
    int i = idx % (HD / 2);
    double inv = exp(-((double)(2 * i) / (double)HD) * log(10000.0));
    double ang = (double)pos * inv;
    g_cos[idx] = (float)cos(ang);
    g_sin[idx] = (float)sin(ang);
}

// ---------------------------------------------------------------------------
// FP16 mma.sync GEMM.  C(fp32) or Ch(fp16) = A(fp16) @ Bt(fp16)^T + bias.
// BM=BN=128, BK=64 halves, 3-stage cp.async, occ 2. do_rope on cols < 2*DIM.
// ---------------------------------------------------------------------------
#define BM 128
#define BN 128
#define HBK 64
#define HSTRIDE 72
#define HA_STAGE (BM * HSTRIDE)
#define HB_STAGE (BN * HSTRIDE)
#define HSTAGE (HA_STAGE + HB_STAGE)
#define NSTAGE 3
#define GEMM_SMEM_BYTES (NSTAGE * HSTAGE * 2)   // 110592

__device__ __forceinline__ void load_h_tile(__half* S, const __half* G, int ldg,
                                            int k0, int tid) {
#pragma unroll
    for (int v = 0; v < 4; v++) {
        int idx = v * 256 + tid;
        int r = idx >> 3, ch = idx & 7;
        cp_async16(S + r * HSTRIDE + ch * 8, G + (size_t)r * ldg + k0 + ch * 8);
    }
}

__global__ __launch_bounds__(256, 2)
void gemm_fp16(const __half* __restrict__ A, const __half* __restrict__ Bt,
               const float* __restrict__ bias, float* __restrict__ C,
               __half* __restrict__ Ch, int M, int N, int K, int do_rope) {
    extern __shared__ __half smh[];
    int tid = threadIdx.x;
    int brow = blockIdx.y * BM;
    int bcol = blockIdx.x * BN;
    int warp = tid >> 5, lane = tid & 31;
    int wm = warp >> 1, wn = warp & 1;
    int g = lane >> 2, t = lane & 3;

    float c[2][8][4];
#pragma unroll
    for (int i = 0; i < 2; i++)
#pragma unroll
        for (int j = 0; j < 8; j++)
#pragma unroll
            for (int r = 0; r < 4; r++) c[i][j][r] = 0.f;

    const int NK = K / HBK;
    const __half* Ab = A + (size_t)brow * K;
    const __half* Bb = Bt + (size_t)bcol * K;

#pragma unroll
    for (int s = 0; s < NSTAGE - 1; s++) {
        __half* st = smh + s * HSTAGE;
        load_h_tile(st, Ab, K, s * HBK, tid);
        load_h_tile(st + HA_STAGE, Bb, K, s * HBK, tid);
        cp_commit();
    }

    for (int kt = 0; kt < NK; kt++) {
        cp_wait1();
        __syncthreads();

        if (kt + NSTAGE - 1 < NK) {
            __half* st = smh + ((kt + NSTAGE - 1) % NSTAGE) * HSTAGE;
            load_h_tile(st, Ab, K, (kt + NSTAGE - 1) * HBK, tid);
            load_h_tile(st + HA_STAGE, Bb, K, (kt + NSTAGE - 1) * HBK, tid);
        }
        cp_commit();

        const __half* As = smh + (kt % NSTAGE) * HSTAGE;
        const __half* Bs = As + HA_STAGE;

#pragma unroll
        for (int j = 0; j < 4; j++) {
            int k0 = j * 16;
            uint32_t a[2][4], b[8][2];
#pragma unroll
            for (int mt = 0; mt < 2; mt++) {
                const __half* ap = As + (wm * 32 + mt * 16 + g) * HSTRIDE + k0 + 2 * t;
                a[mt][0] = *(const uint32_t*)ap;
                a[mt][1] = *(const uint32_t*)(ap + 8 * HSTRIDE);
                a[mt][2] = *(const uint32_t*)(ap + 8);
                a[mt][3] = *(const uint32_t*)(ap + 8 * HSTRIDE + 8);
            }
#pragma unroll
            for (int nt = 0; nt < 8; nt++) {
                const __half* bp = Bs + (wn * 64 + nt * 8 + g) * HSTRIDE + k0 + 2 * t;
                b[nt][0] = *(const uint32_t*)bp;
                b[nt][1] = *(const uint32_t*)(bp + 8);
            }
#pragma unroll
            for (int mt = 0; mt < 2; mt++)
#pragma unroll
                for (int nt = 0; nt < 8; nt++)
                    mma_f16(c[mt][nt], a[mt], b[nt]);
        }
    }

    int rope_here = do_rope && (bcol < 2 * DIM);
#pragma unroll
    for (int mt = 0; mt < 2; mt++) {
        int r0 = brow + wm * 32 + mt * 16 + g;
        int pos0 = r0 & (SEQ - 1);
        int pos1 = (r0 + 8) & (SEQ - 1);
#pragma unroll
        for (int nt = 0; nt < 8; nt++) {
            int col = bcol + wn * 64 + nt * 8 + 2 * t;
            float b0 = bias[col], b1 = bias[col + 1];
            float v00 = c[mt][nt][0] + b0, v01 = c[mt][nt][1] + b1;
            float v10 = c[mt][nt][2] + b0, v11 = c[mt][nt][3] + b1;
            if (rope_here) {
                int i = (col & (HD - 1)) >> 1;
                float c0 = g_cos[pos0 * (HD / 2) + i];
                float s0 = g_sin[pos0 * (HD / 2) + i];
                float c1 = g_cos[pos1 * (HD / 2) + i];
                float s1 = g_sin[pos1 * (HD / 2) + i];
                float n00 = v00 * c0 - v01 * s0;
                float n01 = v01 * c0 + v00 * s0;
                float n10 = v10 * c1 - v11 * s1;
                float n11 = v11 * c1 + v10 * s1;
                v00 = n00; v01 = n01; v10 = n10; v11 = n11;
            }
            if (Ch) {
                *(__half2*)(Ch + (size_t)r0 * N + col) = __floats2half2_rn(v00, v01);
                *(__half2*)(Ch + (size_t)(r0 + 8) * N + col) = __floats2half2_rn(v10, v11);
            } else {
                *(float2*)(C + (size_t)r0 * N + col) = make_float2(v00, v01);
                *(float2*)(C + (size_t)(r0 + 8) * N + col) = make_float2(v10, v11);
            }
        }
    }
}

// ---------------------------------------------------------------------------
// FP16 tensor-core flash attention (fp32 softmax/accum, causal).
// CTA: 128 q-rows x 1 head, 8 warps. K double-buffered, V early-issued.
// S = Q@K^T (m16n8k16); O^T = V^T @ P^T with V^T via ldmatrix.x4.trans.
// ---------------------------------------------------------------------------
#define FQT 128
#define FKT 64
#define QPADh 136
#define KPADh 136
#define VPADh 136
#define SPADh 72
#define KSTGh (FKT * KPADh)
// halves: Q 17408, K 2*8704, V 8704, S 9216 = 52736
#define FA_HALves (FQT * QPADh + 2 * KSTGh + FKT * VPADh + FQT * SPADh)
#define FA_SMEM_BYTES (FA_HALves * 2 + 1024)

__device__ __forceinline__ void fa_load_kv_async(__half* dst, const __half* gsrc,
                                                 int tid) {
    // 64 rows x 16 chunks(16B) = 1024 chunks; 4 per thread
#pragma unroll
    for (int v = 0; v < 4; v++) {
        int idx = v * 256 + tid;
        int row = idx >> 4, ch = idx & 15;
        cp_async16(dst + row * KPADh + ch * 8, gsrc + (size_t)row * QKVC + ch * 8);
    }
}

__global__ __launch_bounds__(256, 1)
void flash_attn_f16(const __half* __restrict__ qkv, __half* __restrict__ ctx) {
    int qtile = blockIdx.x, head = blockIdx.y, batch = blockIdx.z;
    int q0 = qtile * FQT;
    int tid = threadIdx.x, warp = tid >> 5, lane = tid & 31;
    int g = lane >> 2, t = lane & 3;

    extern __shared__ __half smh[];
    __half* Qs = smh;
    __half* Ks0 = Qs + FQT * QPADh;
    __half* Vs = Ks0 + 2 * KSTGh;
    __half* Ss = Vs + FKT * VPADh;
    float* cr = (float*)(smh + FA_HALves);
    float* ls = cr + 128;

    const float scale = 0.08838834764831845f;  // 1/sqrt(128)
    const __half* qbase = qkv + (size_t)(batch * SEQ + q0) * QKVC + head * HD;
    const __half* kvbase = qkv + (size_t)(batch * SEQ) * QKVC + DIM + head * HD;

    int ntiles = 2 * (qtile + 1);

    fa_load_kv_async(Ks0, kvbase, tid);
    cp_commit();
    fa_load_kv_async(Vs, kvbase + DIM, tid);
    cp_commit();

    // Q load (plain LDG.128 -> STS)
#pragma unroll
    for (int v = 0; v < 8; v++) {
        int idx = v * 256 + tid;
        int row = idx >> 4, ch = (idx & 15) * 8;
        *(float4*)(Qs + row * QPADh + ch) =
            *(const float4*)(qbase + (size_t)row * QKVC + ch);
    }

    // ldmatrix base address for V^T fragments
    uint32_t vs_u32 = (uint32_t)__cvta_generic_to_shared(Vs);
    uint32_t v_lm = vs_u32 + (((lane & 15) * VPADh) + ((lane >> 4) * 8)) * 2;

    float o[8][2][4];
#pragma unroll
    for (int mt = 0; mt < 8; mt++)
#pragma unroll
        for (int nt = 0; nt < 2; nt++)
#pragma unroll
            for (int r = 0; r < 4; r++) o[mt][nt][r] = 0.f;

    float m_a = -INFINITY, m_b = -INFINITY, l_a = 0.f, l_b = 0.f;
    int rowa = q0 + warp * 16 + g;
    int rowb = rowa + 8;

    int buf = 0;
    for (int kt = 0; kt < ntiles; kt++) {
        int k0g = kt * FKT;
        const __half* kvtile = kvbase + (size_t)k0g * QKVC;

        cp_wait1();
        __syncthreads();
        if (kt + 1 < ntiles) {
            fa_load_kv_async(Ks0 + (buf ^ 1) * KSTGh,
                             kvtile + (size_t)FKT * QKVC, tid);
            cp_commit();
        }
        const __half* Ks = Ks0 + buf * KSTGh;

        // ---- S = Q @ K^T (fp16 k16) ----
        float sc[8][4];
#pragma unroll
        for (int nt = 0; nt < 8; nt++)
#pragma unroll
            for (int r = 0; r < 4; r++) sc[nt][r] = 0.f;

#pragma unroll
        for (int k0 = 0; k0 < HD; k0 += 16) {
            uint32_t a[4];
            const __half* qp = Qs + (warp * 16 + g) * QPADh + k0 + 2 * t;
            a[0] = *(const uint32_t*)qp;
            a[1] = *(const uint32_t*)(qp + 8 * QPADh);
            a[2] = *(const uint32_t*)(qp + 8);
            a[3] = *(const uint32_t*)(qp + 8 * QPADh + 8);
#pragma unroll
            for (int nt = 0; nt < 8; nt++) {
                uint32_t b[2];
                const __half* kp = Ks + (nt * 8 + g) * KPADh + k0 + 2 * t;
                b[0] = *(const uint32_t*)kp;
                b[1] = *(const uint32_t*)(kp + 8);
                mma_f16(sc[nt], a, b);
            }
        }

#pragma unroll
        for (int nt = 0; nt < 8; nt++)
#pragma unroll
            for (int r = 0; r < 4; r++) sc[nt][r] *= scale;

        if (kt >= 2 * qtile) {
#pragma unroll
            for (int nt = 0; nt < 8; nt++) {
                int col = k0g + nt * 8 + 2 * t;
                if (col > rowa) sc[nt][0] = -INFINITY;
                if (col + 1 > rowa) sc[nt][1] = -INFINITY;
                if (col > rowb) sc[nt][2] = -INFINITY;
                if (col + 1 > rowb) sc[nt][3] = -INFINITY;
            }
        }

        // ---- online softmax ----
        float tma = -INFINITY, tmb = -INFINITY;
#pragma unroll
        for (int nt = 0; nt < 8; nt++) {
            tma = fmaxf(tma, fmaxf(sc[nt][0], sc[nt][1]));
            tmb = fmaxf(tmb, fmaxf(sc[nt][2], sc[nt][3]));
        }
        tma = fmaxf(tma, __shfl_xor_sync(0xffffffff, tma, 1));
        tma = fmaxf(tma, __shfl_xor_sync(0xffffffff, tma, 2));
        tmb = fmaxf(tmb, __shfl_xor_sync(0xffffffff, tmb, 1));
        tmb = fmaxf(tmb, __shfl_xor_sync(0xffffffff, tmb, 2));

        float nma = fmaxf(m_a, tma), nmb = fmaxf(m_b, tmb);
        float ca = __expf(m_a - nma), cb = __expf(m_b - nmb);
        m_a = nma; m_b = nmb;

        float sa = 0.f, sb = 0.f;
#pragma unroll
        for (int nt = 0; nt < 8; nt++) {
            float p0 = __expf(sc[nt][0] - nma);
            float p1 = __expf(sc[nt][1] - nma);
            float p2 = __expf(sc[nt][2] - nmb);
            float p3 = __expf(sc[nt][3] - nmb);
            sc[nt][0] = p0; sc[nt][1] = p1; sc[nt][2] = p2; sc[nt][3] = p3;
            sa += p0 + p1;
            sb += p2 + p3;
        }
        sa += __shfl_xor_sync(0xffffffff, sa, 1);
        sa += __shfl_xor_sync(0xffffffff, sa, 2);
        sb += __shfl_xor_sync(0xffffffff, sb, 1);
        sb += __shfl_xor_sync(0xffffffff, sb, 2);
        l_a = l_a * ca + sa;
        l_b = l_b * cb + sb;

        if (t == 0) {
            cr[warp * 16 + g] = ca;
            cr[warp * 16 + g + 8] = cb;
        }

        // ---- write P as fp16 pairs ----
#pragma unroll
        for (int nt = 0; nt < 8; nt++) {
            *(uint32_t*)(Ss + (warp * 16 + g) * SPADh + nt * 8 + 2 * t) =
                pack_half2(sc[nt][0], sc[nt][1]);
            *(uint32_t*)(Ss + (warp * 16 + g + 8) * SPADh + nt * 8 + 2 * t) =
                pack_half2(sc[nt][2], sc[nt][3]);
        }

        // V[kt] ready
        if (kt + 1 < ntiles) cp_wait1(); else cp_wait0();
        __syncthreads();

        // ---- rescale O^T ----
#pragma unroll
        for (int nt = 0; nt < 2; nt++) {
            float c0 = cr[warp * 16 + nt * 8 + 2 * t];
            float c1 = cr[warp * 16 + nt * 8 + 2 * t + 1];
#pragma unroll
            for (int mt = 0; mt < 8; mt++) {
                o[mt][nt][0] *= c0;
                o[mt][nt][1] *= c1;
                o[mt][nt][2] *= c0;
                o[mt][nt][3] *= c1;
            }
        }

        // ---- O^T += V^T @ P^T (A via ldmatrix.trans) ----
#pragma unroll
        for (int k0 = 0; k0 < FKT; k0 += 16) {
            uint32_t b[2][2];
#pragma unroll
            for (int nt = 0; nt < 2; nt++) {
                const __half* pp = Ss + (warp * 16 + nt * 8 + g) * SPADh + k0 + 2 * t;
                b[nt][0] = *(const uint32_t*)pp;
                b[nt][1] = *(const uint32_t*)(pp + 8);
            }
#pragma unroll
            for (int mt = 0; mt < 8; mt++) {
                uint32_t r0, r1, r2, r3;
                ldmatrix_x4_trans(r0, r1, r2, r3,
                                  v_lm + (uint32_t)(k0 * VPADh + mt * 16) * 2);
                uint32_t a[4] = {r0, r2, r1, r3};
                mma_f16(o[mt][0], a, b[0]);
                mma_f16(o[mt][1], a, b[1]);
            }
        }

        __syncthreads();
        if (kt + 1 < ntiles) {
            fa_load_kv_async(Vs, kvtile + (size_t)FKT * QKVC + DIM, tid);
            cp_commit();
        }
        buf ^= 1;
    }

    // ---- epilogue: O = O^T / l, fp16 out ----
    if (t == 0) {
        ls[warp * 16 + g] = l_a;
        ls[warp * 16 + g + 8] = l_b;
    }
    __syncwarp();

#pragma unroll
    for (int nt = 0; nt < 2; nt++) {
        int q_loc = warp * 16 + nt * 8 + 2 * t;
        float il0 = 1.0f / ls[q_loc];
        float il1 = 1.0f / ls[q_loc + 1];
        size_t r0 = (size_t)(batch * SEQ + q0 + q_loc) * DIM + head * HD;
        size_t r1 = r0 + DIM;
#pragma unroll
        for (int mt = 0; mt < 8; mt++) {
            int d = mt * 16 + g;
            ctx[r0 + d] = __float2half_rn(o[mt][nt][0] * il0);
            ctx[r1 + d] = __float2half_rn(o[mt][nt][1] * il1);
            ctx[r0 + d + 8] = __float2half_rn(o[mt][nt][2] * il0);
            ctx[r1 + d + 8] = __float2half_rn(o[mt][nt][3] * il1);
        }
    }
}

// ---------------------------------------------------------------------------
// Launch
// ---------------------------------------------------------------------------
extern "C" void kernel_launch(void* const* d_in, const int* in_sizes, int n_in,
                              void* d_out, int out_size) {
    const float* x      = (const float*)d_in[0];
    const float* Wqkv_w = (const float*)d_in[2];
    const float* Wqkv_b = (const float*)d_in[3];
    const float* Wout_w = (const float*)d_in[4];
    const float* Wout_b = (const float*)d_in[5];
    float* out = (float*)d_out;

    void *qkv_p, *ctx_p, *xh_p, *w1_p, *w2_p;
    cudaGetSymbolAddress(&qkv_p, g_qkvh);
    cudaGetSymbolAddress(&ctx_p, g_ctxh);
    cudaGetSymbolAddress(&xh_p, g_xh);
    cudaGetSymbolAddress(&w1_p, g_w1t);
    cudaGetSymbolAddress(&w2_p, g_w2t);
    __half* qkv = (__half*)qkv_p;
    __half* ctx = (__half*)ctx_p;
    __half* xh  = (__half*)xh_p;
    __half* w1t = (__half*)w1_p;
    __half* w2t = (__half*)w2_p;

    cudaFuncSetAttribute(gemm_fp16, cudaFuncAttributeMaxDynamicSharedMemorySize,
                         GEMM_SMEM_BYTES);
    cudaFuncSetAttribute(flash_attn_f16,
                         cudaFuncAttributeMaxDynamicSharedMemorySize, FA_SMEM_BYTES);

    // 0) Prep
    conv_half<<<(NTOK * DIM / 4 + 255) / 256, 256>>>(x, xh, NTOK * DIM / 4);
    transpose_half<<<dim3(QKVC / 32, DIM / 32), dim3(32, 8)>>>(Wqkv_w, w1t,
                                                               DIM, QKVC);
    transpose_half<<<dim3(DIM / 32, DIM / 32), dim3(32, 8)>>>(Wout_w, w2t,
                                                              DIM, DIM);

    // 1) RoPE tables
    build_rope_tables<<<(SEQ * (HD / 2) + 255) / 256, 256>>>();

    // 2) QKV projection (fp16 MMA) with fused RoPE, fp16 output
    gemm_fp16<<<dim3(QKVC / BN, NTOK / BM), 256, GEMM_SMEM_BYTES>>>(
        xh, w1t, Wqkv_b, nullptr, qkv, NTOK, QKVC, DIM, 1);

    // 3) Flash attention (fp16 MMA; fp16 ctx)
    flash_attn_f16<<<dim3(SEQ / FQT, NH, BB), 256, FA_SMEM_BYTES>>>(qkv, ctx);

    // 4) Output projection (fp16 MMA, fp32 output)
    gemm_fp16<<<dim3(DIM / BN, NTOK / BM), 256, GEMM_SMEM_BYTES>>>(
        ctx, w2t, Wout_b, out, nullptr, NTOK, DIM, DIM, 0);
}

// round 10
// speedup vs baseline: 1.9782x; 1.0100x over previous
#include <cuda_runtime.h>
#include <cuda_fp16.h>
#include <math.h>
#include <stdint.h>

// Problem constants
#define BB 4
#define SEQ 2048
#define DIM 2048
#define NH 16
#define HD 128
#define NTOK (BB * SEQ)        // 8192
#define QKVC (3 * DIM)         // 6144

// Scratch (device globals: allocation-free)
__device__ __half g_qkvh[(size_t)NTOK * QKVC];  // 96 MB fp16 qkv (post-RoPE)
__device__ __half g_ctxh[(size_t)NTOK * DIM];   // 32 MB fp16 ctx
__device__ __half g_xh[(size_t)NTOK * DIM];     // 32 MB fp16 x
__device__ __half g_w1t[(size_t)QKVC * DIM];    // 25 MB Wqkv^T fp16
__device__ __half g_w2t[(size_t)DIM * DIM];     // 8 MB  Wout^T fp16
__device__ float g_cos[SEQ * (HD / 2)];
__device__ float g_sin[SEQ * (HD / 2)];

// ---------------------------------------------------------------------------
// PTX helpers
// ---------------------------------------------------------------------------
__device__ __forceinline__ void cp_async16(const void* smem, const void* gmem) {
    uint32_t s = (uint32_t)__cvta_generic_to_shared(smem);
    asm volatile("cp.async.cg.shared.global [%0], [%1], 16;\n" :: "r"(s), "l"(gmem));
}
__device__ __forceinline__ void cp_commit() {
    asm volatile("cp.async.commit_group;\n");
}
__device__ __forceinline__ void cp_wait0() {
    asm volatile("cp.async.wait_group 0;\n");
}
__device__ __forceinline__ void cp_wait1() {
    asm volatile("cp.async.wait_group 1;\n");
}
__device__ __forceinline__ void mma_f16(float* c, const uint32_t* a, const uint32_t* b) {
    asm volatile(
        "mma.sync.aligned.m16n8k16.row.col.f32.f16.f16.f32 "
        "{%0,%1,%2,%3}, {%4,%5,%6,%7}, {%8,%9}, {%0,%1,%2,%3};\n"
        : "+f"(c[0]), "+f"(c[1]), "+f"(c[2]), "+f"(c[3])
        : "r"(a[0]), "r"(a[1]), "r"(a[2]), "r"(a[3]), "r"(b[0]), "r"(b[1]));
}
__device__ __forceinline__ void ldmatrix_x4_trans(uint32_t& r0, uint32_t& r1,
                                                  uint32_t& r2, uint32_t& r3,
                                                  uint32_t addr) {
    asm volatile(
        "ldmatrix.sync.aligned.m8n8.x4.trans.shared.b16 {%0,%1,%2,%3}, [%4];"
        : "=r"(r0), "=r"(r1), "=r"(r2), "=r"(r3) : "r"(addr));
}
__device__ __forceinline__ uint32_t pack_half2(float a, float b) {
    __half2 h = __floats2half2_rn(a, b);
    return *(uint32_t*)&h;
}

// ---------------------------------------------------------------------------
// Prep kernels
// ---------------------------------------------------------------------------
__global__ void conv_half(const float* __restrict__ src, __half* __restrict__ dst,
                          int n4) {
    int i = blockIdx.x * blockDim.x + threadIdx.x;
    if (i >= n4) return;
    float4 v = ((const float4*)src)[i];
    ((__half2*)dst)[2 * i] = __floats2half2_rn(v.x, v.y);
    ((__half2*)dst)[2 * i + 1] = __floats2half2_rn(v.z, v.w);
}

__global__ void transpose_half(const float* __restrict__ src,
                               __half* __restrict__ dst, int R, int C) {
    __shared__ float t[32][33];
    int bx = blockIdx.x * 32, by = blockIdx.y * 32;
    int tx = threadIdx.x, ty = threadIdx.y;
#pragma unroll
    for (int j = 0; j < 32; j += 8)
        t[ty + j][tx] = src[(size_t)(by + ty + j) * C + bx + tx];
    __syncthreads();
#pragma unroll
    for (int j = 0; j < 32; j += 8)
        dst[(size_t)(bx + ty + j) * R + by + tx] = __float2half_rn(t[tx][ty + j]);
}

__global__ void build_rope_tables() {
    int idx = blockIdx.x * blockDim.x + threadIdx.x;
    if (idx >= SEQ * (HD / 2)) return;
    int pos = idx / (HD / 2);
    int i = idx % (HD / 2);
    double inv = exp(-((double)(2 * i) / (double)HD) * log(10000.0));
    double ang = (double)pos * inv;
    g_cos[idx] = (float)cos(ang);
    g_sin[idx] = (float)sin(ang);
}

// ---------------------------------------------------------------------------
// FP16 mma.sync GEMM (unchanged from R9).
// ---------------------------------------------------------------------------
#define BM 128
#define BN 128
#define HBK 64
#define HSTRIDE 72
#define HA_STAGE (BM * HSTRIDE)
#define HB_STAGE (BN * HSTRIDE)
#define HSTAGE (HA_STAGE + HB_STAGE)
#define NSTAGE 3
#define GEMM_SMEM_BYTES (NSTAGE * HSTAGE * 2)   // 110592

__device__ __forceinline__ void load_h_tile(__half* S, const __half* G, int ldg,
                                            int k0, int tid) {
#pragma unroll
    for (int v = 0; v < 4; v++) {
        int idx = v * 256 + tid;
        int r = idx >> 3, ch = idx & 7;
        cp_async16(S + r * HSTRIDE + ch * 8, G + (size_t)r * ldg + k0 + ch * 8);
    }
}

__global__ __launch_bounds__(256, 2)
void gemm_fp16(const __half* __restrict__ A, const __half* __restrict__ Bt,
               const float* __restrict__ bias, float* __restrict__ C,
               __half* __restrict__ Ch, int M, int N, int K, int do_rope) {
    extern __shared__ __half smh[];
    int tid = threadIdx.x;
    int brow = blockIdx.y * BM;
    int bcol = blockIdx.x * BN;
    int warp = tid >> 5, lane = tid & 31;
    int wm = warp >> 1, wn = warp & 1;
    int g = lane >> 2, t = lane & 3;

    float c[2][8][4];
#pragma unroll
    for (int i = 0; i < 2; i++)
#pragma unroll
        for (int j = 0; j < 8; j++)
#pragma unroll
            for (int r = 0; r < 4; r++) c[i][j][r] = 0.f;

    const int NK = K / HBK;
    const __half* Ab = A + (size_t)brow * K;
    const __half* Bb = Bt + (size_t)bcol * K;

#pragma unroll
    for (int s = 0; s < NSTAGE - 1; s++) {
        __half* st = smh + s * HSTAGE;
        load_h_tile(st, Ab, K, s * HBK, tid);
        load_h_tile(st + HA_STAGE, Bb, K, s * HBK, tid);
        cp_commit();
    }

    for (int kt = 0; kt < NK; kt++) {
        cp_wait1();
        __syncthreads();

        if (kt + NSTAGE - 1 < NK) {
            __half* st = smh + ((kt + NSTAGE - 1) % NSTAGE) * HSTAGE;
            load_h_tile(st, Ab, K, (kt + NSTAGE - 1) * HBK, tid);
            load_h_tile(st + HA_STAGE, Bb, K, (kt + NSTAGE - 1) * HBK, tid);
        }
        cp_commit();

        const __half* As = smh + (kt % NSTAGE) * HSTAGE;
        const __half* Bs = As + HA_STAGE;

#pragma unroll
        for (int j = 0; j < 4; j++) {
            int k0 = j * 16;
            uint32_t a[2][4], b[8][2];
#pragma unroll
            for (int mt = 0; mt < 2; mt++) {
                const __half* ap = As + (wm * 32 + mt * 16 + g) * HSTRIDE + k0 + 2 * t;
                a[mt][0] = *(const uint32_t*)ap;
                a[mt][1] = *(const uint32_t*)(ap + 8 * HSTRIDE);
                a[mt][2] = *(const uint32_t*)(ap + 8);
                a[mt][3] = *(const uint32_t*)(ap + 8 * HSTRIDE + 8);
            }
#pragma unroll
            for (int nt = 0; nt < 8; nt++) {
                const __half* bp = Bs + (wn * 64 + nt * 8 + g) * HSTRIDE + k0 + 2 * t;
                b[nt][0] = *(const uint32_t*)bp;
                b[nt][1] = *(const uint32_t*)(bp + 8);
            }
#pragma unroll
            for (int mt = 0; mt < 2; mt++)
#pragma unroll
                for (int nt = 0; nt < 8; nt++)
                    mma_f16(c[mt][nt], a[mt], b[nt]);
        }
    }

    int rope_here = do_rope && (bcol < 2 * DIM);
#pragma unroll
    for (int mt = 0; mt < 2; mt++) {
        int r0 = brow + wm * 32 + mt * 16 + g;
        int pos0 = r0 & (SEQ - 1);
        int pos1 = (r0 + 8) & (SEQ - 1);
#pragma unroll
        for (int nt = 0; nt < 8; nt++) {
            int col = bcol + wn * 64 + nt * 8 + 2 * t;
            float b0 = bias[col], b1 = bias[col + 1];
            float v00 = c[mt][nt][0] + b0, v01 = c[mt][nt][1] + b1;
            float v10 = c[mt][nt][2] + b0, v11 = c[mt][nt][3] + b1;
            if (rope_here) {
                int i = (col & (HD - 1)) >> 1;
                float c0 = g_cos[pos0 * (HD / 2) + i];
                float s0 = g_sin[pos0 * (HD / 2) + i];
                float c1 = g_cos[pos1 * (HD / 2) + i];
                float s1 = g_sin[pos1 * (HD / 2) + i];
                float n00 = v00 * c0 - v01 * s0;
                float n01 = v01 * c0 + v00 * s0;
                float n10 = v10 * c1 - v11 * s1;
                float n11 = v11 * c1 + v10 * s1;
                v00 = n00; v01 = n01; v10 = n10; v11 = n11;
            }
            if (Ch) {
                *(__half2*)(Ch + (size_t)r0 * N + col) = __floats2half2_rn(v00, v01);
                *(__half2*)(Ch + (size_t)(r0 + 8) * N + col) = __floats2half2_rn(v10, v11);
            } else {
                *(float2*)(C + (size_t)r0 * N + col) = make_float2(v00, v01);
                *(float2*)(C + (size_t)(r0 + 8) * N + col) = make_float2(v10, v11);
            }
        }
    }
}

// ---------------------------------------------------------------------------
// FP16 flash attention — combined KV double-buffer, ONE __syncthreads/iter,
// heavy-qtile-first scheduling.
// ---------------------------------------------------------------------------
#define FQT 128
#define FKT 64
#define QPADh 136
#define KPADh 136
#define SPADh 72
#define V_OFF (FKT * KPADh)          // V tile offset within a KV stage (halves)
#define SKV (2 * FKT * KPADh)        // combined KV stage: 17408 halves
// halves: Q 17408 + KV 2*17408 + S 9216 = 61440; + 256 floats
#define FA_HALVES (FQT * QPADh + 2 * SKV + FQT * SPADh)
#define FA_SMEM_BYTES (FA_HALVES * 2 + 1024)

// Load one combined K+V tile (64 rows each) into a KV stage.
__device__ __forceinline__ void fa_load_kv_async(__half* dst, const __half* ksrc,
                                                 int tid) {
#pragma unroll
    for (int v = 0; v < 4; v++) {
        int idx = v * 256 + tid;
        int row = idx >> 4, ch = idx & 15;
        cp_async16(dst + row * KPADh + ch * 8, ksrc + (size_t)row * QKVC + ch * 8);
    }
    const __half* vsrc = ksrc + DIM;
#pragma unroll
    for (int v = 0; v < 4; v++) {
        int idx = v * 256 + tid;
        int row = idx >> 4, ch = idx & 15;
        cp_async16(dst + V_OFF + row * KPADh + ch * 8,
                   vsrc + (size_t)row * QKVC + ch * 8);
    }
}

__global__ __launch_bounds__(256, 1)
void flash_attn_f16(const __half* __restrict__ qkv, __half* __restrict__ ctx) {
    int qtile = (int)gridDim.x - 1 - (int)blockIdx.x;   // heavy tiles first
    int head = blockIdx.y, batch = blockIdx.z;
    int q0 = qtile * FQT;
    int tid = threadIdx.x, warp = tid >> 5, lane = tid & 31;
    int g = lane >> 2, t = lane & 3;

    extern __shared__ __half smh[];
    __half* Qs = smh;
    __half* KV0 = Qs + FQT * QPADh;
    __half* Ss = KV0 + 2 * SKV;
    float* cr = (float*)(smh + FA_HALVES);
    float* ls = cr + 128;

    const float scale = 0.08838834764831845f;  // 1/sqrt(128)
    const __half* qbase = qkv + (size_t)(batch * SEQ + q0) * QKVC + head * HD;
    const __half* kvbase = qkv + (size_t)(batch * SEQ) * QKVC + DIM + head * HD;

    int ntiles = 2 * (qtile + 1);

    // Prologue: KV[0]
    fa_load_kv_async(KV0, kvbase, tid);
    cp_commit();

    // Q load
#pragma unroll
    for (int v = 0; v < 8; v++) {
        int idx = v * 256 + tid;
        int row = idx >> 4, ch = (idx & 15) * 8;
        *(float4*)(Qs + row * QPADh + ch) =
            *(const float4*)(qbase + (size_t)row * QKVC + ch);
    }

    uint32_t kv0_u32 = (uint32_t)__cvta_generic_to_shared(KV0);
    uint32_t v_lm_lane = (((lane & 15) * KPADh) + ((lane >> 4) * 8)) * 2;

    float o[8][2][4];
#pragma unroll
    for (int mt = 0; mt < 8; mt++)
#pragma unroll
        for (int nt = 0; nt < 2; nt++)
#pragma unroll
            for (int r = 0; r < 4; r++) o[mt][nt][r] = 0.f;

    float m_a = -INFINITY, m_b = -INFINITY, l_a = 0.f, l_b = 0.f;
    int rowa = q0 + warp * 16 + g;
    int rowb = rowa + 8;

    int buf = 0;
    for (int kt = 0; kt < ntiles; kt++) {
        cp_wait0();        // KV[kt] resident
        __syncthreads();   // all warps done reading buf^1 (previous iteration)

        if (kt + 1 < ntiles) {
            fa_load_kv_async(KV0 + (buf ^ 1) * SKV,
                             kvbase + (size_t)(kt + 1) * FKT * QKVC, tid);
            cp_commit();
        }
        const __half* Ks = KV0 + buf * SKV;
        uint32_t v_lm = kv0_u32 + (buf * SKV + V_OFF) * 2 + v_lm_lane;

        // ---- S = Q @ K^T ----
        float sc[8][4];
#pragma unroll
        for (int nt = 0; nt < 8; nt++)
#pragma unroll
            for (int r = 0; r < 4; r++) sc[nt][r] = 0.f;

#pragma unroll
        for (int k0 = 0; k0 < HD; k0 += 16) {
            uint32_t a[4];
            const __half* qp = Qs + (warp * 16 + g) * QPADh + k0 + 2 * t;
            a[0] = *(const uint32_t*)qp;
            a[1] = *(const uint32_t*)(qp + 8 * QPADh);
            a[2] = *(const uint32_t*)(qp + 8);
            a[3] = *(const uint32_t*)(qp + 8 * QPADh + 8);
#pragma unroll
            for (int nt = 0; nt < 8; nt++) {
                uint32_t b[2];
                const __half* kp = Ks + (nt * 8 + g) * KPADh + k0 + 2 * t;
                b[0] = *(const uint32_t*)kp;
                b[1] = *(const uint32_t*)(kp + 8);
                mma_f16(sc[nt], a, b);
            }
        }

#pragma unroll
        for (int nt = 0; nt < 8; nt++)
#pragma unroll
            for (int r = 0; r < 4; r++) sc[nt][r] *= scale;

        if (kt >= 2 * qtile) {
            int k0g = kt * FKT;
#pragma unroll
            for (int nt = 0; nt < 8; nt++) {
                int col = k0g + nt * 8 + 2 * t;
                if (col > rowa) sc[nt][0] = -INFINITY;
                if (col + 1 > rowa) sc[nt][1] = -INFINITY;
                if (col > rowb) sc[nt][2] = -INFINITY;
                if (col + 1 > rowb) sc[nt][3] = -INFINITY;
            }
        }

        // ---- online softmax ----
        float tma = -INFINITY, tmb = -INFINITY;
#pragma unroll
        for (int nt = 0; nt < 8; nt++) {
            tma = fmaxf(tma, fmaxf(sc[nt][0], sc[nt][1]));
            tmb = fmaxf(tmb, fmaxf(sc[nt][2], sc[nt][3]));
        }
        tma = fmaxf(tma, __shfl_xor_sync(0xffffffff, tma, 1));
        tma = fmaxf(tma, __shfl_xor_sync(0xffffffff, tma, 2));
        tmb = fmaxf(tmb, __shfl_xor_sync(0xffffffff, tmb, 1));
        tmb = fmaxf(tmb, __shfl_xor_sync(0xffffffff, tmb, 2));

        float nma = fmaxf(m_a, tma), nmb = fmaxf(m_b, tmb);
        float ca = __expf(m_a - nma), cb = __expf(m_b - nmb);
        m_a = nma; m_b = nmb;

        float sa = 0.f, sb = 0.f;
#pragma unroll
        for (int nt = 0; nt < 8; nt++) {
            float p0 = __expf(sc[nt][0] - nma);
            float p1 = __expf(sc[nt][1] - nma);
            float p2 = __expf(sc[nt][2] - nmb);
            float p3 = __expf(sc[nt][3] - nmb);
            sc[nt][0] = p0; sc[nt][1] = p1; sc[nt][2] = p2; sc[nt][3] = p3;
            sa += p0 + p1;
            sb += p2 + p3;
        }
        sa += __shfl_xor_sync(0xffffffff, sa, 1);
        sa += __shfl_xor_sync(0xffffffff, sa, 2);
        sb += __shfl_xor_sync(0xffffffff, sb, 1);
        sb += __shfl_xor_sync(0xffffffff, sb, 2);
        l_a = l_a * ca + sa;
        l_b = l_b * cb + sb;

        // ---- write P (warp-private rows), then warp-sync before LDS ----
#pragma unroll
        for (int nt = 0; nt < 8; nt++) {
            *(uint32_t*)(Ss + (warp * 16 + g) * SPADh + nt * 8 + 2 * t) =
                pack_half2(sc[nt][0], sc[nt][1]);
            *(uint32_t*)(Ss + (warp * 16 + g + 8) * SPADh + nt * 8 + 2 * t) =
                pack_half2(sc[nt][2], sc[nt][3]);
        }
        if (t == 0) {
            cr[warp * 16 + g] = ca;
            cr[warp * 16 + g + 8] = cb;
        }
        __syncwarp();

        // ---- rescale O^T ----
#pragma unroll
        for (int nt = 0; nt < 2; nt++) {
            float c0 = cr[warp * 16 + nt * 8 + 2 * t];
            float c1 = cr[warp * 16 + nt * 8 + 2 * t + 1];
#pragma unroll
            for (int mt = 0; mt < 8; mt++) {
                o[mt][nt][0] *= c0;
                o[mt][nt][1] *= c1;
                o[mt][nt][2] *= c0;
                o[mt][nt][3] *= c1;
            }
        }

        // ---- O^T += V^T @ P^T ----
#pragma unroll
        for (int k0 = 0; k0 < FKT; k0 += 16) {
            uint32_t b[2][2];
#pragma unroll
            for (int nt = 0; nt < 2; nt++) {
                const __half* pp = Ss + (warp * 16 + nt * 8 + g) * SPADh + k0 + 2 * t;
                b[nt][0] = *(const uint32_t*)pp;
                b[nt][1] = *(const uint32_t*)(pp + 8);
            }
#pragma unroll
            for (int mt = 0; mt < 8; mt++) {
                uint32_t r0, r1, r2, r3;
                ldmatrix_x4_trans(r0, r1, r2, r3,
                                  v_lm + (uint32_t)(k0 * KPADh + mt * 16) * 2);
                uint32_t a[4] = {r0, r2, r1, r3};
                mma_f16(o[mt][0], a, b[0]);
                mma_f16(o[mt][1], a, b[1]);
            }
        }

        buf ^= 1;
    }

    // ---- epilogue ----
    if (t == 0) {
        ls[warp * 16 + g] = l_a;
        ls[warp * 16 + g + 8] = l_b;
    }
    __syncwarp();

#pragma unroll
    for (int nt = 0; nt < 2; nt++) {
        int q_loc = warp * 16 + nt * 8 + 2 * t;
        float il0 = 1.0f / ls[q_loc];
        float il1 = 1.0f / ls[q_loc + 1];
        size_t r0 = (size_t)(batch * SEQ + q0 + q_loc) * DIM + head * HD;
        size_t r1 = r0 + DIM;
#pragma unroll
        for (int mt = 0; mt < 8; mt++) {
            int d = mt * 16 + g;
            ctx[r0 + d] = __float2half_rn(o[mt][nt][0] * il0);
            ctx[r1 + d] = __float2half_rn(o[mt][nt][1] * il1);
            ctx[r0 + d + 8] = __float2half_rn(o[mt][nt][2] * il0);
            ctx[r1 + d + 8] = __float2half_rn(o[mt][nt][3] * il1);
        }
    }
}

// ---------------------------------------------------------------------------
// Launch
// ---------------------------------------------------------------------------
extern "C" void kernel_launch(void* const* d_in, const int* in_sizes, int n_in,
                              void* d_out, int out_size) {
    const float* x      = (const float*)d_in[0];
    const float* Wqkv_w = (const float*)d_in[2];
    const float* Wqkv_b = (const float*)d_in[3];
    const float* Wout_w = (const float*)d_in[4];
    const float* Wout_b = (const float*)d_in[5];
    float* out = (float*)d_out;

    void *qkv_p, *ctx_p, *xh_p, *w1_p, *w2_p;
    cudaGetSymbolAddress(&qkv_p, g_qkvh);
    cudaGetSymbolAddress(&ctx_p, g_ctxh);
    cudaGetSymbolAddress(&xh_p, g_xh);
    cudaGetSymbolAddress(&w1_p, g_w1t);
    cudaGetSymbolAddress(&w2_p, g_w2t);
    __half* qkv = (__half*)qkv_p;
    __half* ctx = (__half*)ctx_p;
    __half* xh  = (__half*)xh_p;
    __half* w1t = (__half*)w1_p;
    __half* w2t = (__half*)w2_p;

    cudaFuncSetAttribute(gemm_fp16, cudaFuncAttributeMaxDynamicSharedMemorySize,
                         GEMM_SMEM_BYTES);
    cudaFuncSetAttribute(flash_attn_f16,
                         cudaFuncAttributeMaxDynamicSharedMemorySize, FA_SMEM_BYTES);

    // 0) Prep
    conv_half<<<(NTOK * DIM / 4 + 255) / 256, 256>>>(x, xh, NTOK * DIM / 4);
    transpose_half<<<dim3(QKVC / 32, DIM / 32), dim3(32, 8)>>>(Wqkv_w, w1t,
                                                               DIM, QKVC);
    transpose_half<<<dim3(DIM / 32, DIM / 32), dim3(32, 8)>>>(Wout_w, w2t,
                                                              DIM, DIM);

    // 1) RoPE tables
    build_rope_tables<<<(SEQ * (HD / 2) + 255) / 256, 256>>>();

    // 2) QKV projection (fp16 MMA) with fused RoPE, fp16 output
    gemm_fp16<<<dim3(QKVC / BN, NTOK / BM), 256, GEMM_SMEM_BYTES>>>(
        xh, w1t, Wqkv_b, nullptr, qkv, NTOK, QKVC, DIM, 1);

    // 3) Flash attention (fp16 MMA; fp16 ctx)
    flash_attn_f16<<<dim3(SEQ / FQT, NH, BB), 256, FA_SMEM_BYTES>>>(qkv, ctx);

    // 4) Output projection (fp16 MMA, fp32 output)
    gemm_fp16<<<dim3(DIM / BN, NTOK / BM), 256, GEMM_SMEM_BYTES>>>(
        ctx, w2t, Wout_b, out, nullptr, NTOK, DIM, DIM, 0);
}

// round 11
// speedup vs baseline: 2.0025x; 1.0123x over previous
#include <cuda_runtime.h>
#include <cuda_fp16.h>
#include <math.h>
#include <stdint.h>

// Problem constants
#define BB 4
#define SEQ 2048
#define DIM 2048
#define NH 16
#define HD 128
#define NTOK (BB * SEQ)        // 8192
#define QKVC (3 * DIM)         // 6144

// Scratch (device globals: allocation-free)
__device__ __half g_qkvh[(size_t)NTOK * QKVC];  // 96 MB fp16 qkv (post-RoPE)
__device__ __half g_ctxh[(size_t)NTOK * DIM];   // 32 MB fp16 ctx
__device__ __half g_xh[(size_t)NTOK * DIM];     // 32 MB fp16 x
__device__ __half g_w1t[(size_t)QKVC * DIM];    // 25 MB Wqkv^T fp16
__device__ __half g_w2t[(size_t)DIM * DIM];     // 8 MB  Wout^T fp16
__device__ float g_cos[SEQ * (HD / 2)];
__device__ float g_sin[SEQ * (HD / 2)];

// ---------------------------------------------------------------------------
// PTX helpers
// ---------------------------------------------------------------------------
__device__ __forceinline__ void cp_async16(const void* smem, const void* gmem) {
    uint32_t s = (uint32_t)__cvta_generic_to_shared(smem);
    asm volatile("cp.async.cg.shared.global [%0], [%1], 16;\n" :: "r"(s), "l"(gmem));
}
__device__ __forceinline__ void cp_commit() {
    asm volatile("cp.async.commit_group;\n");
}
__device__ __forceinline__ void cp_wait0() {
    asm volatile("cp.async.wait_group 0;\n");
}
__device__ __forceinline__ void cp_wait1() {
    asm volatile("cp.async.wait_group 1;\n");
}
__device__ __forceinline__ void mma_f16(float* c, const uint32_t* a, const uint32_t* b) {
    asm volatile(
        "mma.sync.aligned.m16n8k16.row.col.f32.f16.f16.f32 "
        "{%0,%1,%2,%3}, {%4,%5,%6,%7}, {%8,%9}, {%0,%1,%2,%3};\n"
        : "+f"(c[0]), "+f"(c[1]), "+f"(c[2]), "+f"(c[3])
        : "r"(a[0]), "r"(a[1]), "r"(a[2]), "r"(a[3]), "r"(b[0]), "r"(b[1]));
}
__device__ __forceinline__ void ldmatrix_x4_trans(uint32_t& r0, uint32_t& r1,
                                                  uint32_t& r2, uint32_t& r3,
                                                  uint32_t addr) {
    asm volatile(
        "ldmatrix.sync.aligned.m8n8.x4.trans.shared.b16 {%0,%1,%2,%3}, [%4];"
        : "=r"(r0), "=r"(r1), "=r"(r2), "=r"(r3) : "r"(addr));
}
__device__ __forceinline__ uint32_t pack_half2(float a, float b) {
    __half2 h = __floats2half2_rn(a, b);
    return *(uint32_t*)&h;
}

// ---------------------------------------------------------------------------
// Prep kernels
// ---------------------------------------------------------------------------
__global__ void conv_half(const float* __restrict__ src, __half* __restrict__ dst,
                          int n4) {
    int i = blockIdx.x * blockDim.x + threadIdx.x;
    if (i >= n4) return;
    float4 v = ((const float4*)src)[i];
    ((__half2*)dst)[2 * i] = __floats2half2_rn(v.x, v.y);
    ((__half2*)dst)[2 * i + 1] = __floats2half2_rn(v.z, v.w);
}

__global__ void transpose_half(const float* __restrict__ src,
                               __half* __restrict__ dst, int R, int C) {
    __shared__ float t[32][33];
    int bx = blockIdx.x * 32, by = blockIdx.y * 32;
    int tx = threadIdx.x, ty = threadIdx.y;
#pragma unroll
    for (int j = 0; j < 32; j += 8)
        t[ty + j][tx] = src[(size_t)(by + ty + j) * C + bx + tx];
    __syncthreads();
#pragma unroll
    for (int j = 0; j < 32; j += 8)
        dst[(size_t)(bx + ty + j) * R + by + tx] = __float2half_rn(t[tx][ty + j]);
}

__global__ void build_rope_tables() {
    int idx = blockIdx.x * blockDim.x + threadIdx.x;
    if (idx >= SEQ * (HD / 2)) return;
    int pos = idx / (HD / 2);
    int i = idx % (HD / 2);
    double inv = exp(-((double)(2 * i) / (double)HD) * log(10000.0));
    double ang = (double)pos * inv;
    g_cos[idx] = (float)cos(ang);
    g_sin[idx] = (float)sin(ang);
}

// ---------------------------------------------------------------------------
// FP16 mma.sync GEMM (unchanged from R9/R10).
// ---------------------------------------------------------------------------
#define BM 128
#define BN 128
#define HBK 64
#define HSTRIDE 72
#define HA_STAGE (BM * HSTRIDE)
#define HB_STAGE (BN * HSTRIDE)
#define HSTAGE (HA_STAGE + HB_STAGE)
#define NSTAGE 3
#define GEMM_SMEM_BYTES (NSTAGE * HSTAGE * 2)   // 110592

__device__ __forceinline__ void load_h_tile(__half* S, const __half* G, int ldg,
                                            int k0, int tid) {
#pragma unroll
    for (int v = 0; v < 4; v++) {
        int idx = v * 256 + tid;
        int r = idx >> 3, ch = idx & 7;
        cp_async16(S + r * HSTRIDE + ch * 8, G + (size_t)r * ldg + k0 + ch * 8);
    }
}

__global__ __launch_bounds__(256, 2)
void gemm_fp16(const __half* __restrict__ A, const __half* __restrict__ Bt,
               const float* __restrict__ bias, float* __restrict__ C,
               __half* __restrict__ Ch, int M, int N, int K, int do_rope) {
    extern __shared__ __half smh[];
    int tid = threadIdx.x;
    int brow = blockIdx.y * BM;
    int bcol = blockIdx.x * BN;
    int warp = tid >> 5, lane = tid & 31;
    int wm = warp >> 1, wn = warp & 1;
    int g = lane >> 2, t = lane & 3;

    float c[2][8][4];
#pragma unroll
    for (int i = 0; i < 2; i++)
#pragma unroll
        for (int j = 0; j < 8; j++)
#pragma unroll
            for (int r = 0; r < 4; r++) c[i][j][r] = 0.f;

    const int NK = K / HBK;
    const __half* Ab = A + (size_t)brow * K;
    const __half* Bb = Bt + (size_t)bcol * K;

#pragma unroll
    for (int s = 0; s < NSTAGE - 1; s++) {
        __half* st = smh + s * HSTAGE;
        load_h_tile(st, Ab, K, s * HBK, tid);
        load_h_tile(st + HA_STAGE, Bb, K, s * HBK, tid);
        cp_commit();
    }

    for (int kt = 0; kt < NK; kt++) {
        cp_wait1();
        __syncthreads();

        if (kt + NSTAGE - 1 < NK) {
            __half* st = smh + ((kt + NSTAGE - 1) % NSTAGE) * HSTAGE;
            load_h_tile(st, Ab, K, (kt + NSTAGE - 1) * HBK, tid);
            load_h_tile(st + HA_STAGE, Bb, K, (kt + NSTAGE - 1) * HBK, tid);
        }
        cp_commit();

        const __half* As = smh + (kt % NSTAGE) * HSTAGE;
        const __half* Bs = As + HA_STAGE;

#pragma unroll
        for (int j = 0; j < 4; j++) {
            int k0 = j * 16;
            uint32_t a[2][4], b[8][2];
#pragma unroll
            for (int mt = 0; mt < 2; mt++) {
                const __half* ap = As + (wm * 32 + mt * 16 + g) * HSTRIDE + k0 + 2 * t;
                a[mt][0] = *(const uint32_t*)ap;
                a[mt][1] = *(const uint32_t*)(ap + 8 * HSTRIDE);
                a[mt][2] = *(const uint32_t*)(ap + 8);
                a[mt][3] = *(const uint32_t*)(ap + 8 * HSTRIDE + 8);
            }
#pragma unroll
            for (int nt = 0; nt < 8; nt++) {
                const __half* bp = Bs + (wn * 64 + nt * 8 + g) * HSTRIDE + k0 + 2 * t;
                b[nt][0] = *(const uint32_t*)bp;
                b[nt][1] = *(const uint32_t*)(bp + 8);
            }
#pragma unroll
            for (int mt = 0; mt < 2; mt++)
#pragma unroll
                for (int nt = 0; nt < 8; nt++)
                    mma_f16(c[mt][nt], a[mt], b[nt]);
        }
    }

    int rope_here = do_rope && (bcol < 2 * DIM);
#pragma unroll
    for (int mt = 0; mt < 2; mt++) {
        int r0 = brow + wm * 32 + mt * 16 + g;
        int pos0 = r0 & (SEQ - 1);
        int pos1 = (r0 + 8) & (SEQ - 1);
#pragma unroll
        for (int nt = 0; nt < 8; nt++) {
            int col = bcol + wn * 64 + nt * 8 + 2 * t;
            float b0 = bias[col], b1 = bias[col + 1];
            float v00 = c[mt][nt][0] + b0, v01 = c[mt][nt][1] + b1;
            float v10 = c[mt][nt][2] + b0, v11 = c[mt][nt][3] + b1;
            if (rope_here) {
                int i = (col & (HD - 1)) >> 1;
                float c0 = g_cos[pos0 * (HD / 2) + i];
                float s0 = g_sin[pos0 * (HD / 2) + i];
                float c1 = g_cos[pos1 * (HD / 2) + i];
                float s1 = g_sin[pos1 * (HD / 2) + i];
                float n00 = v00 * c0 - v01 * s0;
                float n01 = v01 * c0 + v00 * s0;
                float n10 = v10 * c1 - v11 * s1;
                float n11 = v11 * c1 + v10 * s1;
                v00 = n00; v01 = n01; v10 = n10; v11 = n11;
            }
            if (Ch) {
                *(__half2*)(Ch + (size_t)r0 * N + col) = __floats2half2_rn(v00, v01);
                *(__half2*)(Ch + (size_t)(r0 + 8) * N + col) = __floats2half2_rn(v10, v11);
            } else {
                *(float2*)(C + (size_t)r0 * N + col) = make_float2(v00, v01);
                *(float2*)(C + (size_t)(r0 + 8) * N + col) = make_float2(v10, v11);
            }
        }
    }
}

// ---------------------------------------------------------------------------
// FP16 flash attention — P kept entirely in registers (S-MMA C-layout ==
// PV-MMA B-layout lane-for-lane), corr/l broadcast via shfl, exp2-folded
// softmax. KV double-buffered, one __syncthreads per iteration.
// ---------------------------------------------------------------------------
#define FQT 128
#define FKT 64
#define QPADh 136
#define KPADh 136
#define V_OFF (FKT * KPADh)          // V tile offset within a KV stage (halves)
#define SKV (2 * FKT * KPADh)        // combined KV stage: 17408 halves
#define FA_HALVES (FQT * QPADh + 2 * SKV)    // 52224 halves = 104448 B
#define FA_SMEM_BYTES (FA_HALVES * 2)

__device__ __forceinline__ void fa_load_kv_async(__half* dst, const __half* ksrc,
                                                 int tid) {
#pragma unroll
    for (int v = 0; v < 4; v++) {
        int idx = v * 256 + tid;
        int row = idx >> 4, ch = idx & 15;
        cp_async16(dst + row * KPADh + ch * 8, ksrc + (size_t)row * QKVC + ch * 8);
    }
    const __half* vsrc = ksrc + DIM;
#pragma unroll
    for (int v = 0; v < 4; v++) {
        int idx = v * 256 + tid;
        int row = idx >> 4, ch = idx & 15;
        cp_async16(dst + V_OFF + row * KPADh + ch * 8,
                   vsrc + (size_t)row * QKVC + ch * 8);
    }
}

__global__ __launch_bounds__(256, 1)
void flash_attn_f16(const __half* __restrict__ qkv, __half* __restrict__ ctx) {
    int qtile = (int)gridDim.x - 1 - (int)blockIdx.x;   // heavy tiles first
    int head = blockIdx.y, batch = blockIdx.z;
    int q0 = qtile * FQT;
    int tid = threadIdx.x, warp = tid >> 5, lane = tid & 31;
    int g = lane >> 2, t = lane & 3;

    extern __shared__ __half smh[];
    __half* Qs = smh;
    __half* KV0 = Qs + FQT * QPADh;

    // scale folded with log2(e): softmax runs in exp2 domain
    const float scale2 = 0.08838834764831845f * 1.4426950408889634f;
    const __half* qbase = qkv + (size_t)(batch * SEQ + q0) * QKVC + head * HD;
    const __half* kvbase = qkv + (size_t)(batch * SEQ) * QKVC + DIM + head * HD;

    int ntiles = 2 * (qtile + 1);

    // Prologue: KV[0]
    fa_load_kv_async(KV0, kvbase, tid);
    cp_commit();

    // Q load
#pragma unroll
    for (int v = 0; v < 8; v++) {
        int idx = v * 256 + tid;
        int row = idx >> 4, ch = (idx & 15) * 8;
        *(float4*)(Qs + row * QPADh + ch) =
            *(const float4*)(qbase + (size_t)row * QKVC + ch);
    }

    uint32_t kv0_u32 = (uint32_t)__cvta_generic_to_shared(KV0);
    uint32_t v_lm_lane = (((lane & 15) * KPADh) + ((lane >> 4) * 8)) * 2;

    float o[8][2][4];
#pragma unroll
    for (int mt = 0; mt < 8; mt++)
#pragma unroll
        for (int nt = 0; nt < 2; nt++)
#pragma unroll
            for (int r = 0; r < 4; r++) o[mt][nt][r] = 0.f;

    float m_a = -INFINITY, m_b = -INFINITY, l_a = 0.f, l_b = 0.f;
    int rowa = q0 + warp * 16 + g;
    int rowb = rowa + 8;

    int buf = 0;
    for (int kt = 0; kt < ntiles; kt++) {
        cp_wait0();        // KV[kt] resident
        __syncthreads();   // all warps done reading buf^1

        if (kt + 1 < ntiles) {
            fa_load_kv_async(KV0 + (buf ^ 1) * SKV,
                             kvbase + (size_t)(kt + 1) * FKT * QKVC, tid);
            cp_commit();
        }
        const __half* Ks = KV0 + buf * SKV;
        uint32_t v_lm = kv0_u32 + (buf * SKV + V_OFF) * 2 + v_lm_lane;

        // ---- S = Q @ K^T ----
        float sc[8][4];
#pragma unroll
        for (int nt = 0; nt < 8; nt++)
#pragma unroll
            for (int r = 0; r < 4; r++) sc[nt][r] = 0.f;

#pragma unroll
        for (int k0 = 0; k0 < HD; k0 += 16) {
            uint32_t a[4];
            const __half* qp = Qs + (warp * 16 + g) * QPADh + k0 + 2 * t;
            a[0] = *(const uint32_t*)qp;
            a[1] = *(const uint32_t*)(qp + 8 * QPADh);
            a[2] = *(const uint32_t*)(qp + 8);
            a[3] = *(const uint32_t*)(qp + 8 * QPADh + 8);
#pragma unroll
            for (int nt = 0; nt < 8; nt++) {
                uint32_t b[2];
                const __half* kp = Ks + (nt * 8 + g) * KPADh + k0 + 2 * t;
                b[0] = *(const uint32_t*)kp;
                b[1] = *(const uint32_t*)(kp + 8);
                mma_f16(sc[nt], a, b);
            }
        }

#pragma unroll
        for (int nt = 0; nt < 8; nt++)
#pragma unroll
            for (int r = 0; r < 4; r++) sc[nt][r] *= scale2;

        if (kt >= 2 * qtile) {
            int k0g = kt * FKT;
#pragma unroll
            for (int nt = 0; nt < 8; nt++) {
                int col = k0g + nt * 8 + 2 * t;
                if (col > rowa) sc[nt][0] = -INFINITY;
                if (col + 1 > rowa) sc[nt][1] = -INFINITY;
                if (col > rowb) sc[nt][2] = -INFINITY;
                if (col + 1 > rowb) sc[nt][3] = -INFINITY;
            }
        }

        // ---- online softmax (exp2 domain) ----
        float tma = -INFINITY, tmb = -INFINITY;
#pragma unroll
        for (int nt = 0; nt < 8; nt++) {
            tma = fmaxf(tma, fmaxf(sc[nt][0], sc[nt][1]));
            tmb = fmaxf(tmb, fmaxf(sc[nt][2], sc[nt][3]));
        }
        tma = fmaxf(tma, __shfl_xor_sync(0xffffffff, tma, 1));
        tma = fmaxf(tma, __shfl_xor_sync(0xffffffff, tma, 2));
        tmb = fmaxf(tmb, __shfl_xor_sync(0xffffffff, tmb, 1));
        tmb = fmaxf(tmb, __shfl_xor_sync(0xffffffff, tmb, 2));

        float nma = fmaxf(m_a, tma), nmb = fmaxf(m_b, tmb);
        float ca = exp2f(m_a - nma), cb = exp2f(m_b - nmb);
        m_a = nma; m_b = nmb;

        // P in registers, packed straight into PV B-fragments
        uint32_t pb[8][2];
        float sa = 0.f, sb = 0.f;
#pragma unroll
        for (int nt = 0; nt < 8; nt++) {
            float p0 = exp2f(sc[nt][0] - nma);
            float p1 = exp2f(sc[nt][1] - nma);
            float p2 = exp2f(sc[nt][2] - nmb);
            float p3 = exp2f(sc[nt][3] - nmb);
            pb[nt][0] = pack_half2(p0, p1);
            pb[nt][1] = pack_half2(p2, p3);
            sa += p0 + p1;
            sb += p2 + p3;
        }
        sa += __shfl_xor_sync(0xffffffff, sa, 1);
        sa += __shfl_xor_sync(0xffffffff, sa, 2);
        sb += __shfl_xor_sync(0xffffffff, sb, 1);
        sb += __shfl_xor_sync(0xffffffff, sb, 2);
        l_a = l_a * ca + sa;
        l_b = l_b * cb + sb;

        // ---- rescale O^T (corr via quad-uniform shfl broadcast) ----
        float c0a = __shfl_sync(0xffffffff, ca, (warp * 0) + 8 * t);
        float c1a = __shfl_sync(0xffffffff, ca, 8 * t + 4);
        float c0b = __shfl_sync(0xffffffff, cb, 8 * t);
        float c1b = __shfl_sync(0xffffffff, cb, 8 * t + 4);
#pragma unroll
        for (int mt = 0; mt < 8; mt++) {
            o[mt][0][0] *= c0a; o[mt][0][1] *= c1a;
            o[mt][0][2] *= c0a; o[mt][0][3] *= c1a;
            o[mt][1][0] *= c0b; o[mt][1][1] *= c1b;
            o[mt][1][2] *= c0b; o[mt][1][3] *= c1b;
        }

        // ---- O^T += V^T @ P^T (B operands straight from registers) ----
#pragma unroll
        for (int j = 0; j < 4; j++) {
            uint32_t b0[2] = {pb[2 * j][0], pb[2 * j + 1][0]};
            uint32_t b1[2] = {pb[2 * j][1], pb[2 * j + 1][1]};
#pragma unroll
            for (int mt = 0; mt < 8; mt++) {
                uint32_t r0, r1, r2, r3;
                ldmatrix_x4_trans(r0, r1, r2, r3,
                                  v_lm + (uint32_t)(16 * j * KPADh + mt * 16) * 2);
                uint32_t a[4] = {r0, r2, r1, r3};
                mma_f16(o[mt][0], a, b0);
                mma_f16(o[mt][1], a, b1);
            }
        }

        buf ^= 1;
    }

    // ---- epilogue: O = O^T / l (l via shfl), fp16 out ----
    float l0a = __shfl_sync(0xffffffff, l_a, 8 * t);
    float l1a = __shfl_sync(0xffffffff, l_a, 8 * t + 4);
    float l0b = __shfl_sync(0xffffffff, l_b, 8 * t);
    float l1b = __shfl_sync(0xffffffff, l_b, 8 * t + 4);

#pragma unroll
    for (int nt = 0; nt < 2; nt++) {
        float il0 = 1.0f / (nt ? l0b : l0a);
        float il1 = 1.0f / (nt ? l1b : l1a);
        int q_loc = warp * 16 + nt * 8 + 2 * t;
        size_t r0 = (size_t)(batch * SEQ + q0 + q_loc) * DIM + head * HD;
        size_t r1 = r0 + DIM;
#pragma unroll
        for (int mt = 0; mt < 8; mt++) {
            int d = mt * 16 + g;
            ctx[r0 + d] = __float2half_rn(o[mt][nt][0] * il0);
            ctx[r1 + d] = __float2half_rn(o[mt][nt][1] * il1);
            ctx[r0 + d + 8] = __float2half_rn(o[mt][nt][2] * il0);
            ctx[r1 + d + 8] = __float2half_rn(o[mt][nt][3] * il1);
        }
    }
}

// ---------------------------------------------------------------------------
// Launch
// ---------------------------------------------------------------------------
extern "C" void kernel_launch(void* const* d_in, const int* in_sizes, int n_in,
                              void* d_out, int out_size) {
    const float* x      = (const float*)d_in[0];
    const float* Wqkv_w = (const float*)d_in[2];
    const float* Wqkv_b = (const float*)d_in[3];
    const float* Wout_w = (const float*)d_in[4];
    const float* Wout_b = (const float*)d_in[5];
    float* out = (float*)d_out;

    void *qkv_p, *ctx_p, *xh_p, *w1_p, *w2_p;
    cudaGetSymbolAddress(&qkv_p, g_qkvh);
    cudaGetSymbolAddress(&ctx_p, g_ctxh);
    cudaGetSymbolAddress(&xh_p, g_xh);
    cudaGetSymbolAddress(&w1_p, g_w1t);
    cudaGetSymbolAddress(&w2_p, g_w2t);
    __half* qkv = (__half*)qkv_p;
    __half* ctx = (__half*)ctx_p;
    __half* xh  = (__half*)xh_p;
    __half* w1t = (__half*)w1_p;
    __half* w2t = (__half*)w2_p;

    cudaFuncSetAttribute(gemm_fp16, cudaFuncAttributeMaxDynamicSharedMemorySize,
                         GEMM_SMEM_BYTES);
    cudaFuncSetAttribute(flash_attn_f16,
                         cudaFuncAttributeMaxDynamicSharedMemorySize, FA_SMEM_BYTES);

    // 0) Prep
    conv_half<<<(NTOK * DIM / 4 + 255) / 256, 256>>>(x, xh, NTOK * DIM / 4);
    transpose_half<<<dim3(QKVC / 32, DIM / 32), dim3(32, 8)>>>(Wqkv_w, w1t,
                                                               DIM, QKVC);
    transpose_half<<<dim3(DIM / 32, DIM / 32), dim3(32, 8)>>>(Wout_w, w2t,
                                                              DIM, DIM);

    // 1) RoPE tables
    build_rope_tables<<<(SEQ * (HD / 2) + 255) / 256, 256>>>();

    // 2) QKV projection (fp16 MMA) with fused RoPE, fp16 output
    gemm_fp16<<<dim3(QKVC / BN, NTOK / BM), 256, GEMM_SMEM_BYTES>>>(
        xh, w1t, Wqkv_b, nullptr, qkv, NTOK, QKVC, DIM, 1);

    // 3) Flash attention (fp16 MMA; fp16 ctx)
    flash_attn_f16<<<dim3(SEQ / FQT, NH, BB), 256, FA_SMEM_BYTES>>>(qkv, ctx);

    // 4) Output projection (fp16 MMA, fp32 output)
    gemm_fp16<<<dim3(DIM / BN, NTOK / BM), 256, GEMM_SMEM_BYTES>>>(
        ctx, w2t, Wout_b, out, nullptr, NTOK, DIM, DIM, 0);
}

// round 12
// speedup vs baseline: 2.0209x; 1.0092x over previous
#include <cuda_runtime.h>
#include <cuda_fp16.h>
#include <math.h>
#include <stdint.h>

// Problem constants
#define BB 4
#define SEQ 2048
#define DIM 2048
#define NH 16
#define HD 128
#define NTOK (BB * SEQ)        // 8192
#define QKVC (3 * DIM)         // 6144

// Scratch (device globals: allocation-free)
__device__ __half g_qkvh[(size_t)NTOK * QKVC];  // 96 MB fp16 qkv (post-RoPE)
__device__ __half g_ctxh[(size_t)NTOK * DIM];   // 32 MB fp16 ctx
__device__ __half g_xh[(size_t)NTOK * DIM];     // 32 MB fp16 x
__device__ __half g_w1t[(size_t)QKVC * DIM];    // 25 MB Wqkv^T fp16
__device__ __half g_w2t[(size_t)DIM * DIM];     // 8 MB  Wout^T fp16
__device__ float g_cos[SEQ * (HD / 2)];
__device__ float g_sin[SEQ * (HD / 2)];

// ---------------------------------------------------------------------------
// PTX helpers
// ---------------------------------------------------------------------------
__device__ __forceinline__ void cp_async16(const void* smem, const void* gmem) {
    uint32_t s = (uint32_t)__cvta_generic_to_shared(smem);
    asm volatile("cp.async.cg.shared.global [%0], [%1], 16;\n" :: "r"(s), "l"(gmem));
}
__device__ __forceinline__ void cp_commit() {
    asm volatile("cp.async.commit_group;\n");
}
__device__ __forceinline__ void cp_wait0() {
    asm volatile("cp.async.wait_group 0;\n");
}
__device__ __forceinline__ void cp_wait1() {
    asm volatile("cp.async.wait_group 1;\n");
}
__device__ __forceinline__ void mma_f16(float* c, const uint32_t* a, const uint32_t* b) {
    asm volatile(
        "mma.sync.aligned.m16n8k16.row.col.f32.f16.f16.f32 "
        "{%0,%1,%2,%3}, {%4,%5,%6,%7}, {%8,%9}, {%0,%1,%2,%3};\n"
        : "+f"(c[0]), "+f"(c[1]), "+f"(c[2]), "+f"(c[3])
        : "r"(a[0]), "r"(a[1]), "r"(a[2]), "r"(a[3]), "r"(b[0]), "r"(b[1]));
}
__device__ __forceinline__ void ldmatrix_x4(uint32_t& r0, uint32_t& r1,
                                            uint32_t& r2, uint32_t& r3,
                                            uint32_t addr) {
    asm volatile(
        "ldmatrix.sync.aligned.m8n8.x4.shared.b16 {%0,%1,%2,%3}, [%4];"
        : "=r"(r0), "=r"(r1), "=r"(r2), "=r"(r3) : "r"(addr));
}
__device__ __forceinline__ void ldmatrix_x4_trans(uint32_t& r0, uint32_t& r1,
                                                  uint32_t& r2, uint32_t& r3,
                                                  uint32_t addr) {
    asm volatile(
        "ldmatrix.sync.aligned.m8n8.x4.trans.shared.b16 {%0,%1,%2,%3}, [%4];"
        : "=r"(r0), "=r"(r1), "=r"(r2), "=r"(r3) : "r"(addr));
}
__device__ __forceinline__ uint32_t pack_half2(float a, float b) {
    __half2 h = __floats2half2_rn(a, b);
    return *(uint32_t*)&h;
}

// ---------------------------------------------------------------------------
// Prep kernels
// ---------------------------------------------------------------------------
__global__ void conv_half(const float* __restrict__ src, __half* __restrict__ dst,
                          int n4) {
    int i = blockIdx.x * blockDim.x + threadIdx.x;
    if (i >= n4) return;
    float4 v = ((const float4*)src)[i];
    ((__half2*)dst)[2 * i] = __floats2half2_rn(v.x, v.y);
    ((__half2*)dst)[2 * i + 1] = __floats2half2_rn(v.z, v.w);
}

__global__ void transpose_half(const float* __restrict__ src,
                               __half* __restrict__ dst, int R, int C) {
    __shared__ float t[32][33];
    int bx = blockIdx.x * 32, by = blockIdx.y * 32;
    int tx = threadIdx.x, ty = threadIdx.y;
#pragma unroll
    for (int j = 0; j < 32; j += 8)
        t[ty + j][tx] = src[(size_t)(by + ty + j) * C + bx + tx];
    __syncthreads();
#pragma unroll
    for (int j = 0; j < 32; j += 8)
        dst[(size_t)(bx + ty + j) * R + by + tx] = __float2half_rn(t[tx][ty + j]);
}

__global__ void build_rope_tables() {
    int idx = blockIdx.x * blockDim.x + threadIdx.x;
    if (idx >= SEQ * (HD / 2)) return;
    int pos = idx / (HD / 2);
    int i = idx % (HD / 2);
    double inv = exp(-((double)(2 * i) / (double)HD) * log(10000.0));
    double ang = (double)pos * inv;
    g_cos[idx] = (float)cos(ang);
    g_sin[idx] = (float)sin(ang);
}

// ---------------------------------------------------------------------------
// FP16 mma.sync GEMM — fragment loads via ldmatrix.x4 (6 per k16 step).
// BM=BN=128, BK=64 halves, 3-stage cp.async, occ 2.
// ---------------------------------------------------------------------------
#define BM 128
#define BN 128
#define HBK 64
#define HSTRIDE 72
#define HA_STAGE (BM * HSTRIDE)
#define HB_STAGE (BN * HSTRIDE)
#define HSTAGE (HA_STAGE + HB_STAGE)
#define NSTAGE 3
#define GEMM_SMEM_BYTES (NSTAGE * HSTAGE * 2)   // 110592

__device__ __forceinline__ void load_h_tile(__half* S, const __half* G, int ldg,
                                            int k0, int tid) {
#pragma unroll
    for (int v = 0; v < 4; v++) {
        int idx = v * 256 + tid;
        int r = idx >> 3, ch = idx & 7;
        cp_async16(S + r * HSTRIDE + ch * 8, G + (size_t)r * ldg + k0 + ch * 8);
    }
}

__global__ __launch_bounds__(256, 2)
void gemm_fp16(const __half* __restrict__ A, const __half* __restrict__ Bt,
               const float* __restrict__ bias, float* __restrict__ C,
               __half* __restrict__ Ch, int M, int N, int K, int do_rope) {
    extern __shared__ __half smh[];
    int tid = threadIdx.x;
    int brow = blockIdx.y * BM;
    int bcol = blockIdx.x * BN;
    int warp = tid >> 5, lane = tid & 31;
    int wm = warp >> 1, wn = warp & 1;
    int g = lane >> 2, t = lane & 3;

    float c[2][8][4];
#pragma unroll
    for (int i = 0; i < 2; i++)
#pragma unroll
        for (int j = 0; j < 8; j++)
#pragma unroll
            for (int r = 0; r < 4; r++) c[i][j][r] = 0.f;

    const int NK = K / HBK;
    const __half* Ab = A + (size_t)brow * K;
    const __half* Bb = Bt + (size_t)bcol * K;

    // ldmatrix per-lane offsets (bytes, relative to stage base)
    uint32_t smh_u32 = (uint32_t)__cvta_generic_to_shared(smh);
    int lr = (lane & 7) + ((lane >> 3) & 1) * 8;   // row within a 16-row tile
    int lk = (lane >> 4) * 8;                      // k-half offset (halves)
    uint32_t a_off = (uint32_t)((wm * 32 + lr) * HSTRIDE + lk) * 2;
    uint32_t b_off = (uint32_t)(HA_STAGE + (wn * 64 + lr) * HSTRIDE + lk) * 2;

#pragma unroll
    for (int s = 0; s < NSTAGE - 1; s++) {
        __half* st = smh + s * HSTAGE;
        load_h_tile(st, Ab, K, s * HBK, tid);
        load_h_tile(st + HA_STAGE, Bb, K, s * HBK, tid);
        cp_commit();
    }

    for (int kt = 0; kt < NK; kt++) {
        cp_wait1();
        __syncthreads();

        if (kt + NSTAGE - 1 < NK) {
            __half* st = smh + ((kt + NSTAGE - 1) % NSTAGE) * HSTAGE;
            load_h_tile(st, Ab, K, (kt + NSTAGE - 1) * HBK, tid);
            load_h_tile(st + HA_STAGE, Bb, K, (kt + NSTAGE - 1) * HBK, tid);
        }
        cp_commit();

        uint32_t stage_base = smh_u32 + (uint32_t)((kt % NSTAGE) * HSTAGE * 2);

#pragma unroll
        for (int j = 0; j < 4; j++) {       // k16 steps
            uint32_t ja = stage_base + (uint32_t)(j * 32);  // 16 halves = 32 B
            uint32_t a[2][4], b[8][2];
#pragma unroll
            for (int mt = 0; mt < 2; mt++)
                ldmatrix_x4(a[mt][0], a[mt][1], a[mt][2], a[mt][3],
                            ja + a_off + (uint32_t)(mt * 16 * HSTRIDE * 2));
#pragma unroll
            for (int p = 0; p < 4; p++) {
                uint32_t r0, r1, r2, r3;
                ldmatrix_x4(r0, r1, r2, r3,
                            ja + b_off + (uint32_t)(p * 16 * HSTRIDE * 2));
                b[2 * p][0] = r0; b[2 * p + 1][0] = r1;
                b[2 * p][1] = r2; b[2 * p + 1][1] = r3;
            }
#pragma unroll
            for (int mt = 0; mt < 2; mt++)
#pragma unroll
                for (int nt = 0; nt < 8; nt++)
                    mma_f16(c[mt][nt], a[mt], b[nt]);
        }
    }

    int rope_here = do_rope && (bcol < 2 * DIM);
#pragma unroll
    for (int mt = 0; mt < 2; mt++) {
        int r0 = brow + wm * 32 + mt * 16 + g;
        int pos0 = r0 & (SEQ - 1);
        int pos1 = (r0 + 8) & (SEQ - 1);
#pragma unroll
        for (int nt = 0; nt < 8; nt++) {
            int col = bcol + wn * 64 + nt * 8 + 2 * t;
            float b0 = bias[col], b1 = bias[col + 1];
            float v00 = c[mt][nt][0] + b0, v01 = c[mt][nt][1] + b1;
            float v10 = c[mt][nt][2] + b0, v11 = c[mt][nt][3] + b1;
            if (rope_here) {
                int i = (col & (HD - 1)) >> 1;
                float c0 = g_cos[pos0 * (HD / 2) + i];
                float s0 = g_sin[pos0 * (HD / 2) + i];
                float c1 = g_cos[pos1 * (HD / 2) + i];
                float s1 = g_sin[pos1 * (HD / 2) + i];
                float n00 = v00 * c0 - v01 * s0;
                float n01 = v01 * c0 + v00 * s0;
                float n10 = v10 * c1 - v11 * s1;
                float n11 = v11 * c1 + v10 * s1;
                v00 = n00; v01 = n01; v10 = n10; v11 = n11;
            }
            if (Ch) {
                *(__half2*)(Ch + (size_t)r0 * N + col) = __floats2half2_rn(v00, v01);
                *(__half2*)(Ch + (size_t)(r0 + 8) * N + col) = __floats2half2_rn(v10, v11);
            } else {
                *(float2*)(C + (size_t)r0 * N + col) = make_float2(v00, v01);
                *(float2*)(C + (size_t)(r0 + 8) * N + col) = make_float2(v10, v11);
            }
        }
    }
}

// ---------------------------------------------------------------------------
// FP16 flash attention — register-resident P, 3-stage KV pipeline,
// tree-structured row sums, exp2 softmax, shfl broadcasts.
// ---------------------------------------------------------------------------
#define FQT 128
#define FKT 64
#define QPADh 136
#define KPADh 136
#define V_OFF (FKT * KPADh)
#define SKV (2 * FKT * KPADh)        // 17408 halves per KV stage
#define FA_NSTG 3
#define FA_HALVES (FQT * QPADh + FA_NSTG * SKV)   // 69632 h = 139264 B
#define FA_SMEM_BYTES (FA_HALVES * 2)

__device__ __forceinline__ void fa_load_kv_async(__half* dst, const __half* ksrc,
                                                 int tid) {
#pragma unroll
    for (int v = 0; v < 4; v++) {
        int idx = v * 256 + tid;
        int row = idx >> 4, ch = idx & 15;
        cp_async16(dst + row * KPADh + ch * 8, ksrc + (size_t)row * QKVC + ch * 8);
    }
    const __half* vsrc = ksrc + DIM;
#pragma unroll
    for (int v = 0; v < 4; v++) {
        int idx = v * 256 + tid;
        int row = idx >> 4, ch = idx & 15;
        cp_async16(dst + V_OFF + row * KPADh + ch * 8,
                   vsrc + (size_t)row * QKVC + ch * 8);
    }
}

__global__ __launch_bounds__(256, 1)
void flash_attn_f16(const __half* __restrict__ qkv, __half* __restrict__ ctx) {
    int qtile = (int)gridDim.x - 1 - (int)blockIdx.x;   // heavy tiles first
    int head = blockIdx.y, batch = blockIdx.z;
    int q0 = qtile * FQT;
    int tid = threadIdx.x, warp = tid >> 5, lane = tid & 31;
    int g = lane >> 2, t = lane & 3;

    extern __shared__ __half smh[];
    __half* Qs = smh;
    __half* KV0 = Qs + FQT * QPADh;

    const float scale2 = 0.08838834764831845f * 1.4426950408889634f;
    const __half* qbase = qkv + (size_t)(batch * SEQ + q0) * QKVC + head * HD;
    const __half* kvbase = qkv + (size_t)(batch * SEQ) * QKVC + DIM + head * HD;

    int ntiles = 2 * (qtile + 1);

    // Prologue: KV[0], KV[1]
    fa_load_kv_async(KV0, kvbase, tid);
    cp_commit();
    if (ntiles > 1) {
        fa_load_kv_async(KV0 + SKV, kvbase + (size_t)FKT * QKVC, tid);
    }
    cp_commit();

    // Q load
#pragma unroll
    for (int v = 0; v < 8; v++) {
        int idx = v * 256 + tid;
        int row = idx >> 4, ch = (idx & 15) * 8;
        *(float4*)(Qs + row * QPADh + ch) =
            *(const float4*)(qbase + (size_t)row * QKVC + ch);
    }

    uint32_t kv0_u32 = (uint32_t)__cvta_generic_to_shared(KV0);
    uint32_t v_lm_lane = (((lane & 15) * KPADh) + ((lane >> 4) * 8)) * 2;

    float o[8][2][4];
#pragma unroll
    for (int mt = 0; mt < 8; mt++)
#pragma unroll
        for (int nt = 0; nt < 2; nt++)
#pragma unroll
            for (int r = 0; r < 4; r++) o[mt][nt][r] = 0.f;

    float m_a = -INFINITY, m_b = -INFINITY, l_a = 0.f, l_b = 0.f;
    int rowa = q0 + warp * 16 + g;
    int rowb = rowa + 8;

    for (int kt = 0; kt < ntiles; kt++) {
        cp_wait1();        // KV[kt] resident (KV[kt+1] may be in flight)
        __syncthreads();   // all warps done reading buf (kt-1)%3

        if (kt + 2 < ntiles) {
            fa_load_kv_async(KV0 + ((kt + 2) % FA_NSTG) * SKV,
                             kvbase + (size_t)(kt + 2) * FKT * QKVC, tid);
        }
        cp_commit();

        int buf = kt % FA_NSTG;
        const __half* Ks = KV0 + buf * SKV;
        uint32_t v_lm = kv0_u32 + (buf * SKV + V_OFF) * 2 + v_lm_lane;

        // ---- S = Q @ K^T ----
        float sc[8][4];
#pragma unroll
        for (int nt = 0; nt < 8; nt++)
#pragma unroll
            for (int r = 0; r < 4; r++) sc[nt][r] = 0.f;

#pragma unroll
        for (int k0 = 0; k0 < HD; k0 += 16) {
            uint32_t a[4];
            const __half* qp = Qs + (warp * 16 + g) * QPADh + k0 + 2 * t;
            a[0] = *(const uint32_t*)qp;
            a[1] = *(const uint32_t*)(qp + 8 * QPADh);
            a[2] = *(const uint32_t*)(qp + 8);
            a[3] = *(const uint32_t*)(qp + 8 * QPADh + 8);
#pragma unroll
            for (int nt = 0; nt < 8; nt++) {
                uint32_t b[2];
                const __half* kp = Ks + (nt * 8 + g) * KPADh + k0 + 2 * t;
                b[0] = *(const uint32_t*)kp;
                b[1] = *(const uint32_t*)(kp + 8);
                mma_f16(sc[nt], a, b);
            }
        }

#pragma unroll
        for (int nt = 0; nt < 8; nt++)
#pragma unroll
            for (int r = 0; r < 4; r++) sc[nt][r] *= scale2;

        if (kt >= 2 * qtile) {
            int k0g = kt * FKT;
#pragma unroll
            for (int nt = 0; nt < 8; nt++) {
                int col = k0g + nt * 8 + 2 * t;
                if (col > rowa) sc[nt][0] = -INFINITY;
                if (col + 1 > rowa) sc[nt][1] = -INFINITY;
                if (col > rowb) sc[nt][2] = -INFINITY;
                if (col + 1 > rowb) sc[nt][3] = -INFINITY;
            }
        }

        // ---- online softmax (exp2 domain, tree reductions) ----
        float ma0 = -INFINITY, ma1 = -INFINITY, mb0 = -INFINITY, mb1 = -INFINITY;
#pragma unroll
        for (int nt = 0; nt < 8; nt += 2) {
            ma0 = fmaxf(ma0, fmaxf(sc[nt][0], sc[nt][1]));
            ma1 = fmaxf(ma1, fmaxf(sc[nt + 1][0], sc[nt + 1][1]));
            mb0 = fmaxf(mb0, fmaxf(sc[nt][2], sc[nt][3]));
            mb1 = fmaxf(mb1, fmaxf(sc[nt + 1][2], sc[nt + 1][3]));
        }
        float tma = fmaxf(ma0, ma1), tmb = fmaxf(mb0, mb1);
        tma = fmaxf(tma, __shfl_xor_sync(0xffffffff, tma, 1));
        tma = fmaxf(tma, __shfl_xor_sync(0xffffffff, tma, 2));
        tmb = fmaxf(tmb, __shfl_xor_sync(0xffffffff, tmb, 1));
        tmb = fmaxf(tmb, __shfl_xor_sync(0xffffffff, tmb, 2));

        float nma = fmaxf(m_a, tma), nmb = fmaxf(m_b, tmb);
        float ca = exp2f(m_a - nma), cb = exp2f(m_b - nmb);
        m_a = nma; m_b = nmb;

        uint32_t pb[8][2];
        float sA0 = 0.f, sA1 = 0.f, sB0 = 0.f, sB1 = 0.f;
#pragma unroll
        for (int nt = 0; nt < 8; nt += 2) {
            float p0 = exp2f(sc[nt][0] - nma);
            float p1 = exp2f(sc[nt][1] - nma);
            float p2 = exp2f(sc[nt][2] - nmb);
            float p3 = exp2f(sc[nt][3] - nmb);
            pb[nt][0] = pack_half2(p0, p1);
            pb[nt][1] = pack_half2(p2, p3);
            sA0 += p0 + p1;
            sB0 += p2 + p3;
            float q0f = exp2f(sc[nt + 1][0] - nma);
            float q1f = exp2f(sc[nt + 1][1] - nma);
            float q2f = exp2f(sc[nt + 1][2] - nmb);
            float q3f = exp2f(sc[nt + 1][3] - nmb);
            pb[nt + 1][0] = pack_half2(q0f, q1f);
            pb[nt + 1][1] = pack_half2(q2f, q3f);
            sA1 += q0f + q1f;
            sB1 += q2f + q3f;
        }
        float sa = sA0 + sA1, sb = sB0 + sB1;
        sa += __shfl_xor_sync(0xffffffff, sa, 1);
        sa += __shfl_xor_sync(0xffffffff, sa, 2);
        sb += __shfl_xor_sync(0xffffffff, sb, 1);
        sb += __shfl_xor_sync(0xffffffff, sb, 2);
        l_a = l_a * ca + sa;
        l_b = l_b * cb + sb;

        // ---- rescale O^T (corr via quad-uniform shfl broadcast) ----
        float c0a = __shfl_sync(0xffffffff, ca, 8 * t);
        float c1a = __shfl_sync(0xffffffff, ca, 8 * t + 4);
        float c0b = __shfl_sync(0xffffffff, cb, 8 * t);
        float c1b = __shfl_sync(0xffffffff, cb, 8 * t + 4);
#pragma unroll
        for (int mt = 0; mt < 8; mt++) {
            o[mt][0][0] *= c0a; o[mt][0][1] *= c1a;
            o[mt][0][2] *= c0a; o[mt][0][3] *= c1a;
            o[mt][1][0] *= c0b; o[mt][1][1] *= c1b;
            o[mt][1][2] *= c0b; o[mt][1][3] *= c1b;
        }

        // ---- O^T += V^T @ P^T (B operands straight from registers) ----
#pragma unroll
        for (int j = 0; j < 4; j++) {
            uint32_t b0[2] = {pb[2 * j][0], pb[2 * j + 1][0]};
            uint32_t b1[2] = {pb[2 * j][1], pb[2 * j + 1][1]};
#pragma unroll
            for (int mt = 0; mt < 8; mt++) {
                uint32_t r0, r1, r2, r3;
                ldmatrix_x4_trans(r0, r1, r2, r3,
                                  v_lm + (uint32_t)(16 * j * KPADh + mt * 16) * 2);
                uint32_t a[4] = {r0, r2, r1, r3};
                mma_f16(o[mt][0], a, b0);
                mma_f16(o[mt][1], a, b1);
            }
        }
    }

    // ---- epilogue: O = O^T / l (l via shfl), fp16 out ----
    float l0a = __shfl_sync(0xffffffff, l_a, 8 * t);
    float l1a = __shfl_sync(0xffffffff, l_a, 8 * t + 4);
    float l0b = __shfl_sync(0xffffffff, l_b, 8 * t);
    float l1b = __shfl_sync(0xffffffff, l_b, 8 * t + 4);

#pragma unroll
    for (int nt = 0; nt < 2; nt++) {
        float il0 = 1.0f / (nt ? l0b : l0a);
        float il1 = 1.0f / (nt ? l1b : l1a);
        int q_loc = warp * 16 + nt * 8 + 2 * t;
        size_t r0 = (size_t)(batch * SEQ + q0 + q_loc) * DIM + head * HD;
        size_t r1 = r0 + DIM;
#pragma unroll
        for (int mt = 0; mt < 8; mt++) {
            int d = mt * 16 + g;
            ctx[r0 + d] = __float2half_rn(o[mt][nt][0] * il0);
            ctx[r1 + d] = __float2half_rn(o[mt][nt][1] * il1);
            ctx[r0 + d + 8] = __float2half_rn(o[mt][nt][2] * il0);
            ctx[r1 + d + 8] = __float2half_rn(o[mt][nt][3] * il1);
        }
    }
}

// ---------------------------------------------------------------------------
// Launch
// ---------------------------------------------------------------------------
extern "C" void kernel_launch(void* const* d_in, const int* in_sizes, int n_in,
                              void* d_out, int out_size) {
    const float* x      = (const float*)d_in[0];
    const float* Wqkv_w = (const float*)d_in[2];
    const float* Wqkv_b = (const float*)d_in[3];
    const float* Wout_w = (const float*)d_in[4];
    const float* Wout_b = (const float*)d_in[5];
    float* out = (float*)d_out;

    void *qkv_p, *ctx_p, *xh_p, *w1_p, *w2_p;
    cudaGetSymbolAddress(&qkv_p, g_qkvh);
    cudaGetSymbolAddress(&ctx_p, g_ctxh);
    cudaGetSymbolAddress(&xh_p, g_xh);
    cudaGetSymbolAddress(&w1_p, g_w1t);
    cudaGetSymbolAddress(&w2_p, g_w2t);
    __half* qkv = (__half*)qkv_p;
    __half* ctx = (__half*)ctx_p;
    __half* xh  = (__half*)xh_p;
    __half* w1t = (__half*)w1_p;
    __half* w2t = (__half*)w2_p;

    cudaFuncSetAttribute(gemm_fp16, cudaFuncAttributeMaxDynamicSharedMemorySize,
                         GEMM_SMEM_BYTES);
    cudaFuncSetAttribute(flash_attn_f16,
                         cudaFuncAttributeMaxDynamicSharedMemorySize, FA_SMEM_BYTES);

    // 0) Prep
    conv_half<<<(NTOK * DIM / 4 + 255) / 256, 256>>>(x, xh, NTOK * DIM / 4);
    transpose_half<<<dim3(QKVC / 32, DIM / 32), dim3(32, 8)>>>(Wqkv_w, w1t,
                                                               DIM, QKVC);
    transpose_half<<<dim3(DIM / 32, DIM / 32), dim3(32, 8)>>>(Wout_w, w2t,
                                                              DIM, DIM);

    // 1) RoPE tables
    build_rope_tables<<<(SEQ * (HD / 2) + 255) / 256, 256>>>();

    // 2) QKV projection (fp16 MMA) with fused RoPE, fp16 output
    gemm_fp16<<<dim3(QKVC / BN, NTOK / BM), 256, GEMM_SMEM_BYTES>>>(
        xh, w1t, Wqkv_b, nullptr, qkv, NTOK, QKVC, DIM, 1);

    // 3) Flash attention (fp16 MMA; fp16 ctx)
    flash_attn_f16<<<dim3(SEQ / FQT, NH, BB), 256, FA_SMEM_BYTES>>>(qkv, ctx);

    // 4) Output projection (fp16 MMA, fp32 output)
    gemm_fp16<<<dim3(DIM / BN, NTOK / BM), 256, GEMM_SMEM_BYTES>>>(
        ctx, w2t, Wout_b, out, nullptr, NTOK, DIM, DIM, 0);
}

// round 13
// speedup vs baseline: 2.2136x; 1.0954x over previous
#include <cuda_runtime.h>
#include <cuda_fp16.h>
#include <math.h>
#include <stdint.h>

// Problem constants
#define BB 4
#define SEQ 2048
#define DIM 2048
#define NH 16
#define HD 128
#define NTOK (BB * SEQ)        // 8192
#define QKVC (3 * DIM)         // 6144

// Scratch (device globals: allocation-free)
__device__ __half g_qkvh[(size_t)NTOK * QKVC];  // 96 MB fp16 qkv (post-RoPE)
__device__ __half g_ctxh[(size_t)NTOK * DIM];   // 32 MB fp16 ctx
__device__ __half g_xh[(size_t)NTOK * DIM];     // 32 MB fp16 x
__device__ __half g_w1h[(size_t)DIM * QKVC];    // 25 MB Wqkv fp16 [K][N]
__device__ __half g_w2h[(size_t)DIM * DIM];     // 8 MB  Wout fp16 [K][N]
__device__ float g_cos[SEQ * (HD / 2)];
__device__ float g_sin[SEQ * (HD / 2)];

// ---------------------------------------------------------------------------
// PTX helpers
// ---------------------------------------------------------------------------
__device__ __forceinline__ void cp_async16(const void* smem, const void* gmem) {
    uint32_t s = (uint32_t)__cvta_generic_to_shared(smem);
    asm volatile("cp.async.cg.shared.global [%0], [%1], 16;\n" :: "r"(s), "l"(gmem));
}
__device__ __forceinline__ void cp_commit() {
    asm volatile("cp.async.commit_group;\n");
}
__device__ __forceinline__ void cp_wait1() {
    asm volatile("cp.async.wait_group 1;\n");
}
__device__ __forceinline__ void mma_f16(float* c, const uint32_t* a, const uint32_t* b) {
    asm volatile(
        "mma.sync.aligned.m16n8k16.row.col.f32.f16.f16.f32 "
        "{%0,%1,%2,%3}, {%4,%5,%6,%7}, {%8,%9}, {%0,%1,%2,%3};\n"
        : "+f"(c[0]), "+f"(c[1]), "+f"(c[2]), "+f"(c[3])
        : "r"(a[0]), "r"(a[1]), "r"(a[2]), "r"(a[3]), "r"(b[0]), "r"(b[1]));
}
__device__ __forceinline__ void ldmatrix_x4(uint32_t& r0, uint32_t& r1,
                                            uint32_t& r2, uint32_t& r3,
                                            uint32_t addr) {
    asm volatile(
        "ldmatrix.sync.aligned.m8n8.x4.shared.b16 {%0,%1,%2,%3}, [%4];"
        : "=r"(r0), "=r"(r1), "=r"(r2), "=r"(r3) : "r"(addr));
}
__device__ __forceinline__ void ldmatrix_x4_trans(uint32_t& r0, uint32_t& r1,
                                                  uint32_t& r2, uint32_t& r3,
                                                  uint32_t addr) {
    asm volatile(
        "ldmatrix.sync.aligned.m8n8.x4.trans.shared.b16 {%0,%1,%2,%3}, [%4];"
        : "=r"(r0), "=r"(r1), "=r"(r2), "=r"(r3) : "r"(addr));
}
__device__ __forceinline__ uint32_t pack_half2(float a, float b) {
    __half2 h = __floats2half2_rn(a, b);
    return *(uint32_t*)&h;
}

// ---------------------------------------------------------------------------
// Prep kernels
// ---------------------------------------------------------------------------
__global__ void conv_half(const float* __restrict__ src, __half* __restrict__ dst,
                          int n4) {
    int i = blockIdx.x * blockDim.x + threadIdx.x;
    if (i >= n4) return;
    float4 v = ((const float4*)src)[i];
    ((__half2*)dst)[2 * i] = __floats2half2_rn(v.x, v.y);
    ((__half2*)dst)[2 * i + 1] = __floats2half2_rn(v.z, v.w);
}

__global__ void build_rope_tables() {
    int idx = blockIdx.x * blockDim.x + threadIdx.x;
    if (idx >= SEQ * (HD / 2)) return;
    int pos = idx / (HD / 2);
    int i = idx % (HD / 2);
    double inv = exp(-((double)(2 * i) / (double)HD) * log(10000.0));
    double ang = (double)pos * inv;
    g_cos[idx] = (float)cos(ang);
    g_sin[idx] = (float)sin(ang);
}

// ---------------------------------------------------------------------------
// FP16 mma.sync GEMM.  A[M,K] fp16 row-major; B[K,N] fp16 row-major.
// A frags via ldmatrix.x4; B frags via ldmatrix.x4.trans from [BK][BN] smem.
// BM=BN=128, BK=64, 3-stage cp.async, occ 2.
// ---------------------------------------------------------------------------
#define BM 128
#define BN 128
#define HBK 64
#define HSTRIDE 72                       // A smem pad (halves)
#define BPAD 136                         // B smem pad (halves); rows 272B, 16B-aligned
#define HA_STAGE (BM * HSTRIDE)          // 9216 halves
#define HB_STAGE (HBK * BPAD)            // 8704 halves
#define HSTAGE (HA_STAGE + HB_STAGE)     // 17920 halves
#define NSTAGE 3
#define GEMM_SMEM_BYTES (NSTAGE * HSTAGE * 2)   // 107520

__device__ __forceinline__ void load_a_tile(__half* S, const __half* G, int ldg,
                                            int k0, int tid) {
    // 128 rows x 8 chunks(16B); 4 per thread
#pragma unroll
    for (int v = 0; v < 4; v++) {
        int idx = v * 256 + tid;
        int r = idx >> 3, ch = idx & 7;
        cp_async16(S + r * HSTRIDE + ch * 8, G + (size_t)r * ldg + k0 + ch * 8);
    }
}
__device__ __forceinline__ void load_b_tile(__half* S, const __half* G, int N,
                                            int bcol, int k0, int tid) {
    // 64 rows x 16 chunks(16B); 4 per thread
#pragma unroll
    for (int v = 0; v < 4; v++) {
        int idx = v * 256 + tid;
        int r = idx >> 4, ch = idx & 15;
        cp_async16(S + r * BPAD + ch * 8,
                   G + (size_t)(k0 + r) * N + bcol + ch * 8);
    }
}

__global__ __launch_bounds__(256, 2)
void gemm_fp16(const __half* __restrict__ A, const __half* __restrict__ B,
               const float* __restrict__ bias, float* __restrict__ C,
               __half* __restrict__ Ch, int M, int N, int K, int do_rope) {
    extern __shared__ __half smh[];
    int tid = threadIdx.x;
    int brow = blockIdx.y * BM;
    int bcol = blockIdx.x * BN;
    int warp = tid >> 5, lane = tid & 31;
    int wm = warp >> 1, wn = warp & 1;
    int g = lane >> 2, t = lane & 3;

    float c[2][8][4];
#pragma unroll
    for (int i = 0; i < 2; i++)
#pragma unroll
        for (int j = 0; j < 8; j++)
#pragma unroll
            for (int r = 0; r < 4; r++) c[i][j][r] = 0.f;

    const int NK = K / HBK;
    const __half* Ab = A + (size_t)brow * K;

    uint32_t smh_u32 = (uint32_t)__cvta_generic_to_shared(smh);
    // A ldmatrix lane offset: rows of 16-row tile, k-half select
    int lr = (lane & 7) + ((lane >> 3) & 1) * 8;
    int lk = (lane >> 4) * 8;
    uint32_t a_off = (uint32_t)((wm * 32 + lr) * HSTRIDE + lk) * 2;
    // B ldmatrix.trans lane offset: rows = k (lane&15), col-half = (lane>>4)*8
    uint32_t b_off = (uint32_t)(HA_STAGE + (lane & 15) * BPAD + wn * 64 +
                                (lane >> 4) * 8) * 2;

#pragma unroll
    for (int s = 0; s < NSTAGE - 1; s++) {
        __half* st = smh + s * HSTAGE;
        load_a_tile(st, Ab, K, s * HBK, tid);
        load_b_tile(st + HA_STAGE, B, N, bcol, s * HBK, tid);
        cp_commit();
    }

    for (int kt = 0; kt < NK; kt++) {
        cp_wait1();
        __syncthreads();

        if (kt + NSTAGE - 1 < NK) {
            __half* st = smh + ((kt + NSTAGE - 1) % NSTAGE) * HSTAGE;
            load_a_tile(st, Ab, K, (kt + NSTAGE - 1) * HBK, tid);
            load_b_tile(st + HA_STAGE, B, N, bcol, (kt + NSTAGE - 1) * HBK, tid);
        }
        cp_commit();

        uint32_t stage_base = smh_u32 + (uint32_t)((kt % NSTAGE) * HSTAGE * 2);

#pragma unroll
        for (int j = 0; j < 4; j++) {       // k16 steps
            uint32_t a[2][4], b[8][2];
            uint32_t ja = stage_base + a_off + (uint32_t)(j * 32);
#pragma unroll
            for (int mt = 0; mt < 2; mt++)
                ldmatrix_x4(a[mt][0], a[mt][1], a[mt][2], a[mt][3],
                            ja + (uint32_t)(mt * 16 * HSTRIDE * 2));
            uint32_t jb = stage_base + b_off + (uint32_t)(j * 16 * BPAD * 2);
#pragma unroll
            for (int p = 0; p < 4; p++) {
                uint32_t r0, r1, r2, r3;
                ldmatrix_x4_trans(r0, r1, r2, r3, jb + (uint32_t)(p * 32));
                b[2 * p][0] = r0; b[2 * p][1] = r1;
                b[2 * p + 1][0] = r2; b[2 * p + 1][1] = r3;
            }
#pragma unroll
            for (int mt = 0; mt < 2; mt++)
#pragma unroll
                for (int nt = 0; nt < 8; nt++)
                    mma_f16(c[mt][nt], a[mt], b[nt]);
        }
    }

    int rope_here = do_rope && (bcol < 2 * DIM);
#pragma unroll
    for (int mt = 0; mt < 2; mt++) {
        int r0 = brow + wm * 32 + mt * 16 + g;
        int pos0 = r0 & (SEQ - 1);
        int pos1 = (r0 + 8) & (SEQ - 1);
#pragma unroll
        for (int nt = 0; nt < 8; nt++) {
            int col = bcol + wn * 64 + nt * 8 + 2 * t;
            float b0 = bias[col], b1 = bias[col + 1];
            float v00 = c[mt][nt][0] + b0, v01 = c[mt][nt][1] + b1;
            float v10 = c[mt][nt][2] + b0, v11 = c[mt][nt][3] + b1;
            if (rope_here) {
                int i = (col & (HD - 1)) >> 1;
                float c0 = g_cos[pos0 * (HD / 2) + i];
                float s0 = g_sin[pos0 * (HD / 2) + i];
                float c1 = g_cos[pos1 * (HD / 2) + i];
                float s1 = g_sin[pos1 * (HD / 2) + i];
                float n00 = v00 * c0 - v01 * s0;
                float n01 = v01 * c0 + v00 * s0;
                float n10 = v10 * c1 - v11 * s1;
                float n11 = v11 * c1 + v10 * s1;
                v00 = n00; v01 = n01; v10 = n10; v11 = n11;
            }
            if (Ch) {
                *(__half2*)(Ch + (size_t)r0 * N + col) = __floats2half2_rn(v00, v01);
                *(__half2*)(Ch + (size_t)(r0 + 8) * N + col) = __floats2half2_rn(v10, v11);
            } else {
                *(float2*)(C + (size_t)r0 * N + col) = make_float2(v00, v01);
                *(float2*)(C + (size_t)(r0 + 8) * N + col) = make_float2(v10, v11);
            }
        }
    }
}

// ---------------------------------------------------------------------------
// FP16 flash attention — occupancy 2: FQT=64, 128 threads (4 warps),
// Q register-resident, 3-stage KV ring (104.4 KB smem), register P,
// exp2 softmax, shfl broadcasts.
// ---------------------------------------------------------------------------
#define FQT 64
#define FKT 64
#define KPADh 136
#define V_OFF (FKT * KPADh)
#define SKV (2 * FKT * KPADh)        // 17408 halves per KV stage
#define FA_NSTG 3
#define FA_SMEM_BYTES (FA_NSTG * SKV * 2)   // 104448

__device__ __forceinline__ void fa_load_kv_async(__half* dst, const __half* ksrc,
                                                 int tid) {
    // K: 64 rows x 16 chunks; 8 per thread (128 threads)
#pragma unroll
    for (int v = 0; v < 8; v++) {
        int idx = v * 128 + tid;
        int row = idx >> 4, ch = idx & 15;
        cp_async16(dst + row * KPADh + ch * 8, ksrc + (size_t)row * QKVC + ch * 8);
    }
    const __half* vsrc = ksrc + DIM;
#pragma unroll
    for (int v = 0; v < 8; v++) {
        int idx = v * 128 + tid;
        int row = idx >> 4, ch = idx & 15;
        cp_async16(dst + V_OFF + row * KPADh + ch * 8,
                   vsrc + (size_t)row * QKVC + ch * 8);
    }
}

__global__ __launch_bounds__(128, 2)
void flash_attn_f16(const __half* __restrict__ qkv, __half* __restrict__ ctx) {
    int qtile = (int)gridDim.x - 1 - (int)blockIdx.x;   // heavy tiles first
    int head = blockIdx.y, batch = blockIdx.z;
    int q0 = qtile * FQT;
    int tid = threadIdx.x, warp = tid >> 5, lane = tid & 31;
    int g = lane >> 2, t = lane & 3;

    extern __shared__ __half smh[];
    __half* KV0 = smh;

    const float scale2 = 0.08838834764831845f * 1.4426950408889634f;
    const __half* qbase = qkv + (size_t)(batch * SEQ + q0) * QKVC + head * HD;
    const __half* kvbase = qkv + (size_t)(batch * SEQ) * QKVC + DIM + head * HD;

    int ntiles = qtile + 1;

    // Prologue: KV[0], KV[1]
    fa_load_kv_async(KV0, kvbase, tid);
    cp_commit();
    if (ntiles > 1)
        fa_load_kv_async(KV0 + SKV, kvbase + (size_t)FKT * QKVC, tid);
    cp_commit();

    // Q -> registers, directly in A-fragment layout (one-time 32 LDG.32)
    uint32_t qa[8][4];
    {
        const __half* q0p = qbase + (size_t)(warp * 16 + g) * QKVC + 2 * t;
        const __half* q1p = q0p + (size_t)8 * QKVC;
#pragma unroll
        for (int j = 0; j < 8; j++) {
            qa[j][0] = *(const uint32_t*)(q0p + 16 * j);
            qa[j][1] = *(const uint32_t*)(q1p + 16 * j);
            qa[j][2] = *(const uint32_t*)(q0p + 16 * j + 8);
            qa[j][3] = *(const uint32_t*)(q1p + 16 * j + 8);
        }
    }

    uint32_t kv0_u32 = (uint32_t)__cvta_generic_to_shared(KV0);
    uint32_t v_lm_lane = (((lane & 15) * KPADh) + ((lane >> 4) * 8)) * 2;

    float o[8][2][4];
#pragma unroll
    for (int mt = 0; mt < 8; mt++)
#pragma unroll
        for (int nt = 0; nt < 2; nt++)
#pragma unroll
            for (int r = 0; r < 4; r++) o[mt][nt][r] = 0.f;

    float m_a = -INFINITY, m_b = -INFINITY, l_a = 0.f, l_b = 0.f;
    int rowa = q0 + warp * 16 + g;
    int rowb = rowa + 8;

    for (int kt = 0; kt < ntiles; kt++) {
        cp_wait1();        // KV[kt] resident (KV[kt+1] may be in flight)
        __syncthreads();   // all warps done reading buf (kt-1)%3

        if (kt + 2 < ntiles)
            fa_load_kv_async(KV0 + ((kt + 2) % FA_NSTG) * SKV,
                             kvbase + (size_t)(kt + 2) * FKT * QKVC, tid);
        cp_commit();

        int buf = kt % FA_NSTG;
        const __half* Ks = KV0 + buf * SKV;
        uint32_t v_lm = kv0_u32 + (buf * SKV + V_OFF) * 2 + v_lm_lane;

        // ---- S = Q @ K^T ----
        float sc[8][4];
#pragma unroll
        for (int nt = 0; nt < 8; nt++)
#pragma unroll
            for (int r = 0; r < 4; r++) sc[nt][r] = 0.f;

#pragma unroll
        for (int j = 0; j < 8; j++) {
            int k0 = j * 16;
#pragma unroll
            for (int nt = 0; nt < 8; nt++) {
                uint32_t b[2];
                const __half* kp = Ks + (nt * 8 + g) * KPADh + k0 + 2 * t;
                b[0] = *(const uint32_t*)kp;
                b[1] = *(const uint32_t*)(kp + 8);
                mma_f16(sc[nt], qa[j], b);
            }
        }

#pragma unroll
        for (int nt = 0; nt < 8; nt++)
#pragma unroll
            for (int r = 0; r < 4; r++) sc[nt][r] *= scale2;

        if (kt == qtile) {        // diagonal tile
            int k0g = kt * FKT;
#pragma unroll
            for (int nt = 0; nt < 8; nt++) {
                int col = k0g + nt * 8 + 2 * t;
                if (col > rowa) sc[nt][0] = -INFINITY;
                if (col + 1 > rowa) sc[nt][1] = -INFINITY;
                if (col > rowb) sc[nt][2] = -INFINITY;
                if (col + 1 > rowb) sc[nt][3] = -INFINITY;
            }
        }

        // ---- online softmax (exp2 domain, tree reductions) ----
        float ma0 = -INFINITY, ma1 = -INFINITY, mb0 = -INFINITY, mb1 = -INFINITY;
#pragma unroll
        for (int nt = 0; nt < 8; nt += 2) {
            ma0 = fmaxf(ma0, fmaxf(sc[nt][0], sc[nt][1]));
            ma1 = fmaxf(ma1, fmaxf(sc[nt + 1][0], sc[nt + 1][1]));
            mb0 = fmaxf(mb0, fmaxf(sc[nt][2], sc[nt][3]));
            mb1 = fmaxf(mb1, fmaxf(sc[nt + 1][2], sc[nt + 1][3]));
        }
        float tma = fmaxf(ma0, ma1), tmb = fmaxf(mb0, mb1);
        tma = fmaxf(tma, __shfl_xor_sync(0xffffffff, tma, 1));
        tma = fmaxf(tma, __shfl_xor_sync(0xffffffff, tma, 2));
        tmb = fmaxf(tmb, __shfl_xor_sync(0xffffffff, tmb, 1));
        tmb = fmaxf(tmb, __shfl_xor_sync(0xffffffff, tmb, 2));

        float nma = fmaxf(m_a, tma), nmb = fmaxf(m_b, tmb);
        float ca = exp2f(m_a - nma), cb = exp2f(m_b - nmb);
        m_a = nma; m_b = nmb;

        uint32_t pb[8][2];
        float sA0 = 0.f, sA1 = 0.f, sB0 = 0.f, sB1 = 0.f;
#pragma unroll
        for (int nt = 0; nt < 8; nt += 2) {
            float p0 = exp2f(sc[nt][0] - nma);
            float p1 = exp2f(sc[nt][1] - nma);
            float p2 = exp2f(sc[nt][2] - nmb);
            float p3 = exp2f(sc[nt][3] - nmb);
            pb[nt][0] = pack_half2(p0, p1);
            pb[nt][1] = pack_half2(p2, p3);
            sA0 += p0 + p1;
            sB0 += p2 + p3;
            float q0f = exp2f(sc[nt + 1][0] - nma);
            float q1f = exp2f(sc[nt + 1][1] - nma);
            float q2f = exp2f(sc[nt + 1][2] - nmb);
            float q3f = exp2f(sc[nt + 1][3] - nmb);
            pb[nt + 1][0] = pack_half2(q0f, q1f);
            pb[nt + 1][1] = pack_half2(q2f, q3f);
            sA1 += q0f + q1f;
            sB1 += q2f + q3f;
        }
        float sa = sA0 + sA1, sb = sB0 + sB1;
        sa += __shfl_xor_sync(0xffffffff, sa, 1);
        sa += __shfl_xor_sync(0xffffffff, sa, 2);
        sb += __shfl_xor_sync(0xffffffff, sb, 1);
        sb += __shfl_xor_sync(0xffffffff, sb, 2);
        l_a = l_a * ca + sa;
        l_b = l_b * cb + sb;

        // ---- rescale O^T (corr via quad-uniform shfl broadcast) ----
        float c0a = __shfl_sync(0xffffffff, ca, 8 * t);
        float c1a = __shfl_sync(0xffffffff, ca, 8 * t + 4);
        float c0b = __shfl_sync(0xffffffff, cb, 8 * t);
        float c1b = __shfl_sync(0xffffffff, cb, 8 * t + 4);
#pragma unroll
        for (int mt = 0; mt < 8; mt++) {
            o[mt][0][0] *= c0a; o[mt][0][1] *= c1a;
            o[mt][0][2] *= c0a; o[mt][0][3] *= c1a;
            o[mt][1][0] *= c0b; o[mt][1][1] *= c1b;
            o[mt][1][2] *= c0b; o[mt][1][3] *= c1b;
        }

        // ---- O^T += V^T @ P^T ----
#pragma unroll
        for (int j = 0; j < 4; j++) {
            uint32_t b0[2] = {pb[2 * j][0], pb[2 * j + 1][0]};
            uint32_t b1[2] = {pb[2 * j][1], pb[2 * j + 1][1]};
#pragma unroll
            for (int mt = 0; mt < 8; mt++) {
                uint32_t r0, r1, r2, r3;
                ldmatrix_x4_trans(r0, r1, r2, r3,
                                  v_lm + (uint32_t)(16 * j * KPADh + mt * 16) * 2);
                uint32_t a[4] = {r0, r2, r1, r3};
                mma_f16(o[mt][0], a, b0);
                mma_f16(o[mt][1], a, b1);
            }
        }
    }

    // ---- epilogue: O = O^T / l (l via shfl), fp16 out ----
    float l0a = __shfl_sync(0xffffffff, l_a, 8 * t);
    float l1a = __shfl_sync(0xffffffff, l_a, 8 * t + 4);
    float l0b = __shfl_sync(0xffffffff, l_b, 8 * t);
    float l1b = __shfl_sync(0xffffffff, l_b, 8 * t + 4);

#pragma unroll
    for (int nt = 0; nt < 2; nt++) {
        float il0 = 1.0f / (nt ? l0b : l0a);
        float il1 = 1.0f / (nt ? l1b : l1a);
        int q_loc = warp * 16 + nt * 8 + 2 * t;
        size_t r0 = (size_t)(batch * SEQ + q0 + q_loc) * DIM + head * HD;
        size_t r1 = r0 + DIM;
#pragma unroll
        for (int mt = 0; mt < 8; mt++) {
            int d = mt * 16 + g;
            ctx[r0 + d] = __float2half_rn(o[mt][nt][0] * il0);
            ctx[r1 + d] = __float2half_rn(o[mt][nt][1] * il1);
            ctx[r0 + d + 8] = __float2half_rn(o[mt][nt][2] * il0);
            ctx[r1 + d + 8] = __float2half_rn(o[mt][nt][3] * il1);
        }
    }
}

// ---------------------------------------------------------------------------
// Launch
// ---------------------------------------------------------------------------
extern "C" void kernel_launch(void* const* d_in, const int* in_sizes, int n_in,
                              void* d_out, int out_size) {
    const float* x      = (const float*)d_in[0];
    const float* Wqkv_w = (const float*)d_in[2];
    const float* Wqkv_b = (const float*)d_in[3];
    const float* Wout_w = (const float*)d_in[4];
    const float* Wout_b = (const float*)d_in[5];
    float* out = (float*)d_out;

    void *qkv_p, *ctx_p, *xh_p, *w1_p, *w2_p;
    cudaGetSymbolAddress(&qkv_p, g_qkvh);
    cudaGetSymbolAddress(&ctx_p, g_ctxh);
    cudaGetSymbolAddress(&xh_p, g_xh);
    cudaGetSymbolAddress(&w1_p, g_w1h);
    cudaGetSymbolAddress(&w2_p, g_w2h);
    __half* qkv = (__half*)qkv_p;
    __half* ctx = (__half*)ctx_p;
    __half* xh  = (__half*)xh_p;
    __half* w1h = (__half*)w1_p;
    __half* w2h = (__half*)w2_p;

    cudaFuncSetAttribute(gemm_fp16, cudaFuncAttributeMaxDynamicSharedMemorySize,
                         GEMM_SMEM_BYTES);
    cudaFuncSetAttribute(flash_attn_f16,
                         cudaFuncAttributeMaxDynamicSharedMemorySize, FA_SMEM_BYTES);

    // 0) Prep: fp32 -> fp16 (no transposes)
    conv_half<<<(NTOK * DIM / 4 + 255) / 256, 256>>>(x, xh, NTOK * DIM / 4);
    conv_half<<<(DIM * QKVC / 4 + 255) / 256, 256>>>(Wqkv_w, w1h, DIM * QKVC / 4);
    conv_half<<<(DIM * DIM / 4 + 255) / 256, 256>>>(Wout_w, w2h, DIM * DIM / 4);

    // 1) RoPE tables
    build_rope_tables<<<(SEQ * (HD / 2) + 255) / 256, 256>>>();

    // 2) QKV projection (fp16 MMA) with fused RoPE, fp16 output
    gemm_fp16<<<dim3(QKVC / BN, NTOK / BM), 256, GEMM_SMEM_BYTES>>>(
        xh, w1h, Wqkv_b, nullptr, qkv, NTOK, QKVC, DIM, 1);

    // 3) Flash attention (fp16 MMA, occ 2; fp16 ctx)
    flash_attn_f16<<<dim3(SEQ / FQT, NH, BB), 128, FA_SMEM_BYTES>>>(qkv, ctx);

    // 4) Output projection (fp16 MMA, fp32 output)
    gemm_fp16<<<dim3(DIM / BN, NTOK / BM), 256, GEMM_SMEM_BYTES>>>(
        ctx, w2h, Wout_b, out, nullptr, NTOK, DIM, DIM, 0);
}

// round 14
// speedup vs baseline: 2.2205x; 1.0032x over previous
#include <cuda_runtime.h>
#include <cuda_fp16.h>
#include <math.h>
#include <stdint.h>

// Problem constants
#define BB 4
#define SEQ 2048
#define DIM 2048
#define NH 16
#define HD 128
#define NTOK (BB * SEQ)        // 8192
#define QKVC (3 * DIM)         // 6144

// Scratch (device globals: allocation-free)
__device__ __half g_qkvh[(size_t)NTOK * QKVC];  // 96 MB fp16 qkv (post-RoPE)
__device__ __half g_ctxh[(size_t)NTOK * DIM];   // 32 MB fp16 ctx
__device__ __half g_xh[(size_t)NTOK * DIM];     // 32 MB fp16 x
__device__ __half g_w1h[(size_t)DIM * QKVC];    // 25 MB Wqkv fp16 [K][N]
__device__ __half g_w2h[(size_t)DIM * DIM];     // 8 MB  Wout fp16 [K][N]
__device__ float g_cos[SEQ * (HD / 2)];
__device__ float g_sin[SEQ * (HD / 2)];

// ---------------------------------------------------------------------------
// PTX helpers
// ---------------------------------------------------------------------------
__device__ __forceinline__ void cp_async16(const void* smem, const void* gmem) {
    uint32_t s = (uint32_t)__cvta_generic_to_shared(smem);
    asm volatile("cp.async.cg.shared.global [%0], [%1], 16;\n" :: "r"(s), "l"(gmem));
}
__device__ __forceinline__ void cp_commit() {
    asm volatile("cp.async.commit_group;\n");
}
__device__ __forceinline__ void cp_wait0() {
    asm volatile("cp.async.wait_group 0;\n");
}
__device__ __forceinline__ void cp_wait1() {
    asm volatile("cp.async.wait_group 1;\n");
}
__device__ __forceinline__ void mma_f16(float* c, const uint32_t* a, const uint32_t* b) {
    asm volatile(
        "mma.sync.aligned.m16n8k16.row.col.f32.f16.f16.f32 "
        "{%0,%1,%2,%3}, {%4,%5,%6,%7}, {%8,%9}, {%0,%1,%2,%3};\n"
        : "+f"(c[0]), "+f"(c[1]), "+f"(c[2]), "+f"(c[3])
        : "r"(a[0]), "r"(a[1]), "r"(a[2]), "r"(a[3]), "r"(b[0]), "r"(b[1]));
}
__device__ __forceinline__ void ldmatrix_x4(uint32_t& r0, uint32_t& r1,
                                            uint32_t& r2, uint32_t& r3,
                                            uint32_t addr) {
    asm volatile(
        "ldmatrix.sync.aligned.m8n8.x4.shared.b16 {%0,%1,%2,%3}, [%4];"
        : "=r"(r0), "=r"(r1), "=r"(r2), "=r"(r3) : "r"(addr));
}
__device__ __forceinline__ void ldmatrix_x4_trans(uint32_t& r0, uint32_t& r1,
                                                  uint32_t& r2, uint32_t& r3,
                                                  uint32_t addr) {
    asm volatile(
        "ldmatrix.sync.aligned.m8n8.x4.trans.shared.b16 {%0,%1,%2,%3}, [%4];"
        : "=r"(r0), "=r"(r1), "=r"(r2), "=r"(r3) : "r"(addr));
}
__device__ __forceinline__ uint32_t pack_half2(float a, float b) {
    __half2 h = __floats2half2_rn(a, b);
    return *(uint32_t*)&h;
}

// ---------------------------------------------------------------------------
// Prep kernels
// ---------------------------------------------------------------------------
__global__ void conv_half(const float* __restrict__ src, __half* __restrict__ dst,
                          int n4) {
    int i = blockIdx.x * blockDim.x + threadIdx.x;
    if (i >= n4) return;
    float4 v = ((const float4*)src)[i];
    ((__half2*)dst)[2 * i] = __floats2half2_rn(v.x, v.y);
    ((__half2*)dst)[2 * i + 1] = __floats2half2_rn(v.z, v.w);
}

// fp32 tables: float sincos error (~2 ulp) is invisible vs fp16 noise floor.
__global__ void build_rope_tables() {
    int idx = blockIdx.x * blockDim.x + threadIdx.x;
    if (idx >= SEQ * (HD / 2)) return;
    int pos = idx / (HD / 2);
    int i = idx % (HD / 2);
    float inv = (float)exp(-((double)(2 * i) / (double)HD) * log(10000.0));
    float ang = (float)pos * inv;
    float s, c;
    sincosf(ang, &s, &c);
    g_cos[idx] = c;
    g_sin[idx] = s;
}

// ---------------------------------------------------------------------------
// FP16 mma.sync GEMM (unchanged from R13).
// ---------------------------------------------------------------------------
#define BM 128
#define BN 128
#define HBK 64
#define HSTRIDE 72
#define BPAD 136
#define HA_STAGE (BM * HSTRIDE)
#define HB_STAGE (HBK * BPAD)
#define HSTAGE (HA_STAGE + HB_STAGE)
#define NSTAGE 3
#define GEMM_SMEM_BYTES (NSTAGE * HSTAGE * 2)   // 107520

__device__ __forceinline__ void load_a_tile(__half* S, const __half* G, int ldg,
                                            int k0, int tid) {
#pragma unroll
    for (int v = 0; v < 4; v++) {
        int idx = v * 256 + tid;
        int r = idx >> 3, ch = idx & 7;
        cp_async16(S + r * HSTRIDE + ch * 8, G + (size_t)r * ldg + k0 + ch * 8);
    }
}
__device__ __forceinline__ void load_b_tile(__half* S, const __half* G, int N,
                                            int bcol, int k0, int tid) {
#pragma unroll
    for (int v = 0; v < 4; v++) {
        int idx = v * 256 + tid;
        int r = idx >> 4, ch = idx & 15;
        cp_async16(S + r * BPAD + ch * 8,
                   G + (size_t)(k0 + r) * N + bcol + ch * 8);
    }
}

__global__ __launch_bounds__(256, 2)
void gemm_fp16(const __half* __restrict__ A, const __half* __restrict__ B,
               const float* __restrict__ bias, float* __restrict__ C,
               __half* __restrict__ Ch, int M, int N, int K, int do_rope) {
    extern __shared__ __half smh[];
    int tid = threadIdx.x;
    int brow = blockIdx.y * BM;
    int bcol = blockIdx.x * BN;
    int warp = tid >> 5, lane = tid & 31;
    int wm = warp >> 1, wn = warp & 1;
    int g = lane >> 2, t = lane & 3;

    float c[2][8][4];
#pragma unroll
    for (int i = 0; i < 2; i++)
#pragma unroll
        for (int j = 0; j < 8; j++)
#pragma unroll
            for (int r = 0; r < 4; r++) c[i][j][r] = 0.f;

    const int NK = K / HBK;
    const __half* Ab = A + (size_t)brow * K;

    uint32_t smh_u32 = (uint32_t)__cvta_generic_to_shared(smh);
    int lr = (lane & 7) + ((lane >> 3) & 1) * 8;
    int lk = (lane >> 4) * 8;
    uint32_t a_off = (uint32_t)((wm * 32 + lr) * HSTRIDE + lk) * 2;
    uint32_t b_off = (uint32_t)(HA_STAGE + (lane & 15) * BPAD + wn * 64 +
                                (lane >> 4) * 8) * 2;

#pragma unroll
    for (int s = 0; s < NSTAGE - 1; s++) {
        __half* st = smh + s * HSTAGE;
        load_a_tile(st, Ab, K, s * HBK, tid);
        load_b_tile(st + HA_STAGE, B, N, bcol, s * HBK, tid);
        cp_commit();
    }

    for (int kt = 0; kt < NK; kt++) {
        cp_wait1();
        __syncthreads();

        if (kt + NSTAGE - 1 < NK) {
            __half* st = smh + ((kt + NSTAGE - 1) % NSTAGE) * HSTAGE;
            load_a_tile(st, Ab, K, (kt + NSTAGE - 1) * HBK, tid);
            load_b_tile(st + HA_STAGE, B, N, bcol, (kt + NSTAGE - 1) * HBK, tid);
        }
        cp_commit();

        uint32_t stage_base = smh_u32 + (uint32_t)((kt % NSTAGE) * HSTAGE * 2);

#pragma unroll
        for (int j = 0; j < 4; j++) {
            uint32_t a[2][4], b[8][2];
            uint32_t ja = stage_base + a_off + (uint32_t)(j * 32);
#pragma unroll
            for (int mt = 0; mt < 2; mt++)
                ldmatrix_x4(a[mt][0], a[mt][1], a[mt][2], a[mt][3],
                            ja + (uint32_t)(mt * 16 * HSTRIDE * 2));
            uint32_t jb = stage_base + b_off + (uint32_t)(j * 16 * BPAD * 2);
#pragma unroll
            for (int p = 0; p < 4; p++) {
                uint32_t r0, r1, r2, r3;
                ldmatrix_x4_trans(r0, r1, r2, r3, jb + (uint32_t)(p * 32));
                b[2 * p][0] = r0; b[2 * p][1] = r1;
                b[2 * p + 1][0] = r2; b[2 * p + 1][1] = r3;
            }
#pragma unroll
            for (int mt = 0; mt < 2; mt++)
#pragma unroll
                for (int nt = 0; nt < 8; nt++)
                    mma_f16(c[mt][nt], a[mt], b[nt]);
        }
    }

    int rope_here = do_rope && (bcol < 2 * DIM);
#pragma unroll
    for (int mt = 0; mt < 2; mt++) {
        int r0 = brow + wm * 32 + mt * 16 + g;
        int pos0 = r0 & (SEQ - 1);
        int pos1 = (r0 + 8) & (SEQ - 1);
#pragma unroll
        for (int nt = 0; nt < 8; nt++) {
            int col = bcol + wn * 64 + nt * 8 + 2 * t;
            float b0 = bias[col], b1 = bias[col + 1];
            float v00 = c[mt][nt][0] + b0, v01 = c[mt][nt][1] + b1;
            float v10 = c[mt][nt][2] + b0, v11 = c[mt][nt][3] + b1;
            if (rope_here) {
                int i = (col & (HD - 1)) >> 1;
                float c0 = g_cos[pos0 * (HD / 2) + i];
                float s0 = g_sin[pos0 * (HD / 2) + i];
                float c1 = g_cos[pos1 * (HD / 2) + i];
                float s1 = g_sin[pos1 * (HD / 2) + i];
                float n00 = v00 * c0 - v01 * s0;
                float n01 = v01 * c0 + v00 * s0;
                float n10 = v10 * c1 - v11 * s1;
                float n11 = v11 * c1 + v10 * s1;
                v00 = n00; v01 = n01; v10 = n10; v11 = n11;
            }
            if (Ch) {
                *(__half2*)(Ch + (size_t)r0 * N + col) = __floats2half2_rn(v00, v01);
                *(__half2*)(Ch + (size_t)(r0 + 8) * N + col) = __floats2half2_rn(v10, v11);
            } else {
                *(float2*)(C + (size_t)r0 * N + col) = make_float2(v00, v01);
                *(float2*)(C + (size_t)(r0 + 8) * N + col) = make_float2(v10, v11);
            }
        }
    }
}

// ---------------------------------------------------------------------------
// FP16 flash attention — occupancy 3: FQT=64, 128 threads, Q in registers,
// 2-stage KV ring (69.6 KB smem -> 3 CTAs/SM), register P, exp2 softmax.
// ---------------------------------------------------------------------------
#define FQT 64
#define FKT 64
#define KPADh 136
#define V_OFF (FKT * KPADh)
#define SKV (2 * FKT * KPADh)        // 17408 halves per KV stage
#define FA_NSTG 2
#define FA_SMEM_BYTES (FA_NSTG * SKV * 2)   // 69632

__device__ __forceinline__ void fa_load_kv_async(__half* dst, const __half* ksrc,
                                                 int tid) {
#pragma unroll
    for (int v = 0; v < 8; v++) {
        int idx = v * 128 + tid;
        int row = idx >> 4, ch = idx & 15;
        cp_async16(dst + row * KPADh + ch * 8, ksrc + (size_t)row * QKVC + ch * 8);
    }
    const __half* vsrc = ksrc + DIM;
#pragma unroll
    for (int v = 0; v < 8; v++) {
        int idx = v * 128 + tid;
        int row = idx >> 4, ch = idx & 15;
        cp_async16(dst + V_OFF + row * KPADh + ch * 8,
                   vsrc + (size_t)row * QKVC + ch * 8);
    }
}

__global__ __launch_bounds__(128, 3)
void flash_attn_f16(const __half* __restrict__ qkv, __half* __restrict__ ctx) {
    int qtile = (int)gridDim.x - 1 - (int)blockIdx.x;   // heavy tiles first
    int head = blockIdx.y, batch = blockIdx.z;
    int q0 = qtile * FQT;
    int tid = threadIdx.x, warp = tid >> 5, lane = tid & 31;
    int g = lane >> 2, t = lane & 3;

    extern __shared__ __half smh[];
    __half* KV0 = smh;

    const float scale2 = 0.08838834764831845f * 1.4426950408889634f;
    const __half* qbase = qkv + (size_t)(batch * SEQ + q0) * QKVC + head * HD;
    const __half* kvbase = qkv + (size_t)(batch * SEQ) * QKVC + DIM + head * HD;

    int ntiles = qtile + 1;

    // Prologue: KV[0]
    fa_load_kv_async(KV0, kvbase, tid);
    cp_commit();

    // Q -> registers, directly in A-fragment layout
    uint32_t qa[8][4];
    {
        const __half* q0p = qbase + (size_t)(warp * 16 + g) * QKVC + 2 * t;
        const __half* q1p = q0p + (size_t)8 * QKVC;
#pragma unroll
        for (int j = 0; j < 8; j++) {
            qa[j][0] = *(const uint32_t*)(q0p + 16 * j);
            qa[j][1] = *(const uint32_t*)(q1p + 16 * j);
            qa[j][2] = *(const uint32_t*)(q0p + 16 * j + 8);
            qa[j][3] = *(const uint32_t*)(q1p + 16 * j + 8);
        }
    }

    uint32_t kv0_u32 = (uint32_t)__cvta_generic_to_shared(KV0);
    uint32_t v_lm_lane = (((lane & 15) * KPADh) + ((lane >> 4) * 8)) * 2;

    float o[8][2][4];
#pragma unroll
    for (int mt = 0; mt < 8; mt++)
#pragma unroll
        for (int nt = 0; nt < 2; nt++)
#pragma unroll
            for (int r = 0; r < 4; r++) o[mt][nt][r] = 0.f;

    float m_a = -INFINITY, m_b = -INFINITY, l_a = 0.f, l_b = 0.f;
    int rowa = q0 + warp * 16 + g;
    int rowb = rowa + 8;

    int buf = 0;
    for (int kt = 0; kt < ntiles; kt++) {
        cp_wait0();        // KV[kt] resident
        __syncthreads();   // all warps done reading buf^1

        if (kt + 1 < ntiles) {
            fa_load_kv_async(KV0 + (buf ^ 1) * SKV,
                             kvbase + (size_t)(kt + 1) * FKT * QKVC, tid);
            cp_commit();
        }
        const __half* Ks = KV0 + buf * SKV;
        uint32_t v_lm = kv0_u32 + (buf * SKV + V_OFF) * 2 + v_lm_lane;

        // ---- S = Q @ K^T ----
        float sc[8][4];
#pragma unroll
        for (int nt = 0; nt < 8; nt++)
#pragma unroll
            for (int r = 0; r < 4; r++) sc[nt][r] = 0.f;

#pragma unroll
        for (int j = 0; j < 8; j++) {
            int k0 = j * 16;
#pragma unroll
            for (int nt = 0; nt < 8; nt++) {
                uint32_t b[2];
                const __half* kp = Ks + (nt * 8 + g) * KPADh + k0 + 2 * t;
                b[0] = *(const uint32_t*)kp;
                b[1] = *(const uint32_t*)(kp + 8);
                mma_f16(sc[nt], qa[j], b);
            }
        }

#pragma unroll
        for (int nt = 0; nt < 8; nt++)
#pragma unroll
            for (int r = 0; r < 4; r++) sc[nt][r] *= scale2;

        if (kt == qtile) {        // diagonal tile
            int k0g = kt * FKT;
#pragma unroll
            for (int nt = 0; nt < 8; nt++) {
                int col = k0g + nt * 8 + 2 * t;
                if (col > rowa) sc[nt][0] = -INFINITY;
                if (col + 1 > rowa) sc[nt][1] = -INFINITY;
                if (col > rowb) sc[nt][2] = -INFINITY;
                if (col + 1 > rowb) sc[nt][3] = -INFINITY;
            }
        }

        // ---- online softmax (exp2 domain, tree reductions) ----
        float ma0 = -INFINITY, ma1 = -INFINITY, mb0 = -INFINITY, mb1 = -INFINITY;
#pragma unroll
        for (int nt = 0; nt < 8; nt += 2) {
            ma0 = fmaxf(ma0, fmaxf(sc[nt][0], sc[nt][1]));
            ma1 = fmaxf(ma1, fmaxf(sc[nt + 1][0], sc[nt + 1][1]));
            mb0 = fmaxf(mb0, fmaxf(sc[nt][2], sc[nt][3]));
            mb1 = fmaxf(mb1, fmaxf(sc[nt + 1][2], sc[nt + 1][3]));
        }
        float tma = fmaxf(ma0, ma1), tmb = fmaxf(mb0, mb1);
        tma = fmaxf(tma, __shfl_xor_sync(0xffffffff, tma, 1));
        tma = fmaxf(tma, __shfl_xor_sync(0xffffffff, tma, 2));
        tmb = fmaxf(tmb, __shfl_xor_sync(0xffffffff, tmb, 1));
        tmb = fmaxf(tmb, __shfl_xor_sync(0xffffffff, tmb, 2));

        float nma = fmaxf(m_a, tma), nmb = fmaxf(m_b, tmb);
        float ca = exp2f(m_a - nma), cb = exp2f(m_b - nmb);
        m_a = nma; m_b = nmb;

        uint32_t pb[8][2];
        float sA0 = 0.f, sA1 = 0.f, sB0 = 0.f, sB1 = 0.f;
#pragma unroll
        for (int nt = 0; nt < 8; nt += 2) {
            float p0 = exp2f(sc[nt][0] - nma);
            float p1 = exp2f(sc[nt][1] - nma);
            float p2 = exp2f(sc[nt][2] - nmb);
            float p3 = exp2f(sc[nt][3] - nmb);
            pb[nt][0] = pack_half2(p0, p1);
            pb[nt][1] = pack_half2(p2, p3);
            sA0 += p0 + p1;
            sB0 += p2 + p3;
            float q0f = exp2f(sc[nt + 1][0] - nma);
            float q1f = exp2f(sc[nt + 1][1] - nma);
            float q2f = exp2f(sc[nt + 1][2] - nmb);
            float q3f = exp2f(sc[nt + 1][3] - nmb);
            pb[nt + 1][0] = pack_half2(q0f, q1f);
            pb[nt + 1][1] = pack_half2(q2f, q3f);
            sA1 += q0f + q1f;
            sB1 += q2f + q3f;
        }
        float sa = sA0 + sA1, sb = sB0 + sB1;
        sa += __shfl_xor_sync(0xffffffff, sa, 1);
        sa += __shfl_xor_sync(0xffffffff, sa, 2);
        sb += __shfl_xor_sync(0xffffffff, sb, 1);
        sb += __shfl_xor_sync(0xffffffff, sb, 2);
        l_a = l_a * ca + sa;
        l_b = l_b * cb + sb;

        // ---- rescale O^T ----
        float c0a = __shfl_sync(0xffffffff, ca, 8 * t);
        float c1a = __shfl_sync(0xffffffff, ca, 8 * t + 4);
        float c0b = __shfl_sync(0xffffffff, cb, 8 * t);
        float c1b = __shfl_sync(0xffffffff, cb, 8 * t + 4);
#pragma unroll
        for (int mt = 0; mt < 8; mt++) {
            o[mt][0][0] *= c0a; o[mt][0][1] *= c1a;
            o[mt][0][2] *= c0a; o[mt][0][3] *= c1a;
            o[mt][1][0] *= c0b; o[mt][1][1] *= c1b;
            o[mt][1][2] *= c0b; o[mt][1][3] *= c1b;
        }

        // ---- O^T += V^T @ P^T ----
#pragma unroll
        for (int j = 0; j < 4; j++) {
            uint32_t b0[2] = {pb[2 * j][0], pb[2 * j + 1][0]};
            uint32_t b1[2] = {pb[2 * j][1], pb[2 * j + 1][1]};
#pragma unroll
            for (int mt = 0; mt < 8; mt++) {
                uint32_t r0, r1, r2, r3;
                ldmatrix_x4_trans(r0, r1, r2, r3,
                                  v_lm + (uint32_t)(16 * j * KPADh + mt * 16) * 2);
                uint32_t a[4] = {r0, r2, r1, r3};
                mma_f16(o[mt][0], a, b0);
                mma_f16(o[mt][1], a, b1);
            }
        }

        buf ^= 1;
    }

    // ---- epilogue: O = O^T / l (l via shfl), fp16 out ----
    float l0a = __shfl_sync(0xffffffff, l_a, 8 * t);
    float l1a = __shfl_sync(0xffffffff, l_a, 8 * t + 4);
    float l0b = __shfl_sync(0xffffffff, l_b, 8 * t);
    float l1b = __shfl_sync(0xffffffff, l_b, 8 * t + 4);

#pragma unroll
    for (int nt = 0; nt < 2; nt++) {
        float il0 = 1.0f / (nt ? l0b : l0a);
        float il1 = 1.0f / (nt ? l1b : l1a);
        int q_loc = warp * 16 + nt * 8 + 2 * t;
        size_t r0 = (size_t)(batch * SEQ + q0 + q_loc) * DIM + head * HD;
        size_t r1 = r0 + DIM;
#pragma unroll
        for (int mt = 0; mt < 8; mt++) {
            int d = mt * 16 + g;
            ctx[r0 + d] = __float2half_rn(o[mt][nt][0] * il0);
            ctx[r1 + d] = __float2half_rn(o[mt][nt][1] * il1);
            ctx[r0 + d + 8] = __float2half_rn(o[mt][nt][2] * il0);
            ctx[r1 + d + 8] = __float2half_rn(o[mt][nt][3] * il1);
        }
    }
}

// ---------------------------------------------------------------------------
// Launch
// ---------------------------------------------------------------------------
extern "C" void kernel_launch(void* const* d_in, const int* in_sizes, int n_in,
                              void* d_out, int out_size) {
    const float* x      = (const float*)d_in[0];
    const float* Wqkv_w = (const float*)d_in[2];
    const float* Wqkv_b = (const float*)d_in[3];
    const float* Wout_w = (const float*)d_in[4];
    const float* Wout_b = (const float*)d_in[5];
    float* out = (float*)d_out;

    void *qkv_p, *ctx_p, *xh_p, *w1_p, *w2_p;
    cudaGetSymbolAddress(&qkv_p, g_qkvh);
    cudaGetSymbolAddress(&ctx_p, g_ctxh);
    cudaGetSymbolAddress(&xh_p, g_xh);
    cudaGetSymbolAddress(&w1_p, g_w1h);
    cudaGetSymbolAddress(&w2_p, g_w2h);
    __half* qkv = (__half*)qkv_p;
    __half* ctx = (__half*)ctx_p;
    __half* xh  = (__half*)xh_p;
    __half* w1h = (__half*)w1_p;
    __half* w2h = (__half*)w2_p;

    cudaFuncSetAttribute(gemm_fp16, cudaFuncAttributeMaxDynamicSharedMemorySize,
                         GEMM_SMEM_BYTES);
    cudaFuncSetAttribute(flash_attn_f16,
                         cudaFuncAttributeMaxDynamicSharedMemorySize, FA_SMEM_BYTES);

    // 0) Prep: fp32 -> fp16
    conv_half<<<(NTOK * DIM / 4 + 255) / 256, 256>>>(x, xh, NTOK * DIM / 4);
    conv_half<<<(DIM * QKVC / 4 + 255) / 256, 256>>>(Wqkv_w, w1h, DIM * QKVC / 4);
    conv_half<<<(DIM * DIM / 4 + 255) / 256, 256>>>(Wout_w, w2h, DIM * DIM / 4);

    // 1) RoPE tables (fp32 sincos)
    build_rope_tables<<<(SEQ * (HD / 2) + 255) / 256, 256>>>();

    // 2) QKV projection (fp16 MMA) with fused RoPE, fp16 output
    gemm_fp16<<<dim3(QKVC / BN, NTOK / BM), 256, GEMM_SMEM_BYTES>>>(
        xh, w1h, Wqkv_b, nullptr, qkv, NTOK, QKVC, DIM, 1);

    // 3) Flash attention (fp16 MMA, occ 3; fp16 ctx)
    flash_attn_f16<<<dim3(SEQ / FQT, NH, BB), 128, FA_SMEM_BYTES>>>(qkv, ctx);

    // 4) Output projection (fp16 MMA, fp32 output)
    gemm_fp16<<<dim3(DIM / BN, NTOK / BM), 256, GEMM_SMEM_BYTES>>>(
        ctx, w2h, Wout_b, out, nullptr, NTOK, DIM, DIM, 0);
}